// round 6
// baseline (speedup 1.0000x reference)
#include <cuda_runtime.h>
#include <math.h>

#define NEV   128
#define NPAIR 64
#define NSAMP 131072
#define NFFT  262144
#define NFR   128
#define WINL  1024
#define CPD   16
#define NCP   512
#define NVO   8
#define NVB   16
#define HID   128
#define KSP   128
#define LSTR  576

__device__ float2 g_twtab[1024];                     // [0:512) W512^k ; [512:1024) W_N^k
__device__ float2 g_spec[(size_t)NPAIR * NFFT];      // 128 MB packed spectra
__device__ float2 g_vspec[(size_t)NVB * NFFT];       // 32 MB verb spectra
__device__ float  g_sig[(size_t)NEV * NSAMP];
__device__ float  g_hs[(size_t)NEV * NFR * HID];
__device__ float  g_ctrl[NEV * NFR * CPD];
__device__ float  g_M[NVO * HID * CPD];
__device__ int    g_vidx[NEV], g_ridx[NEV], g_shift[NEV];
__device__ float  g_m0[NEV], g_m1[NEV], g_amp[NEV];
__device__ int    g_pairA[257], g_pairB[257];

__device__ __forceinline__ int skew(int i){ return i + (i >> 3); }
__device__ __forceinline__ float2 cadd(float2 a, float2 b){ return make_float2(a.x+b.x, a.y+b.y); }
__device__ __forceinline__ float2 csub(float2 a, float2 b){ return make_float2(a.x-b.x, a.y-b.y); }
__device__ __forceinline__ float2 cmul(float2 a, float2 b){ return make_float2(a.x*b.x - a.y*b.y, a.x*b.y + a.y*b.x); }
__device__ __forceinline__ float2 cmulc(float2 a, float2 b){ return make_float2(a.x*b.x + a.y*b.y, a.y*b.x - a.x*b.y); }
__device__ __forceinline__ int rev9(int p){ return ((p & 7) << 6) | (p & 56) | (p >> 6); }

__device__ __forceinline__ float2 twN(int idx){
    int k = idx & (NFFT - 1);
    return cmul(g_twtab[k >> 9], g_twtab[512 + (k & 511)]);
}

template<bool INV>
__device__ __forceinline__ float2 mulmi(float2 a){
    return INV ? make_float2(-a.y, a.x) : make_float2(a.y, -a.x);
}

template<bool INV>
__device__ __forceinline__ void dft8(float2* v){
    float2 t0 = cadd(v[0], v[4]), t1 = csub(v[0], v[4]);
    float2 t2 = cadd(v[2], v[6]), t3 = mulmi<INV>(csub(v[2], v[6]));
    float2 t4 = cadd(v[1], v[5]), t5 = csub(v[1], v[5]);
    float2 t6 = cadd(v[3], v[7]), t7 = mulmi<INV>(csub(v[3], v[7]));
    float2 a0 = cadd(t0, t2), a2 = csub(t0, t2);
    float2 a1 = cadd(t1, t3), a3 = csub(t1, t3);
    float2 b0 = cadd(t4, t6), b2 = csub(t4, t6);
    float2 b1 = cadd(t5, t7), b3 = csub(t5, t7);
    const float r = 0.70710678118654752440f;
    float2 w1 = INV ? make_float2(r,  r) : make_float2(r, -r);
    float2 w3 = INV ? make_float2(-r, r) : make_float2(-r, -r);
    b1 = cmul(b1, w1); b2 = mulmi<INV>(b2); b3 = cmul(b3, w3);
    v[0] = cadd(a0, b0); v[4] = csub(a0, b0);
    v[1] = cadd(a1, b1); v[5] = csub(a1, b1);
    v[2] = cadd(a2, b2); v[6] = csub(a2, b2);
    v[3] = cadd(a3, b3); v[7] = csub(a3, b3);
}

// DIF 512 = radix-8^3, natural in -> octal-digit-reversed out.
__device__ __forceinline__ void dif512(float2* L, int t){
    float2 v[8];
    #pragma unroll
    for(int m = 0; m < 8; m++) v[m] = L[skew(t + 64*m)];
    dft8<false>(v);
    #pragma unroll
    for(int m = 1; m < 8; m++) v[m] = cmul(v[m], g_twtab[(t*m) & 511]);
    #pragma unroll
    for(int m = 0; m < 8; m++) L[skew(t + 64*m)] = v[m];
    __syncthreads();
    int base = (t >> 3) << 6, j = t & 7;
    #pragma unroll
    for(int m = 0; m < 8; m++) v[m] = L[skew(base + j + 8*m)];
    dft8<false>(v);
    #pragma unroll
    for(int m = 1; m < 8; m++) v[m] = cmul(v[m], g_twtab[((j*m) << 3) & 511]);
    #pragma unroll
    for(int m = 0; m < 8; m++) L[skew(base + j + 8*m)] = v[m];
    __syncthreads();
    base = t << 3;
    #pragma unroll
    for(int m = 0; m < 8; m++) v[m] = L[skew(base + m)];
    dft8<false>(v);
    #pragma unroll
    for(int m = 0; m < 8; m++) L[skew(base + m)] = v[m];
}

// DIT 512: digit-reversed in -> natural out, conjugate twiddles (unscaled inverse).
__device__ __forceinline__ void dit512(float2* L, int t){
    float2 v[8];
    int base = t << 3;
    #pragma unroll
    for(int m = 0; m < 8; m++) v[m] = L[skew(base + m)];
    dft8<true>(v);
    #pragma unroll
    for(int m = 0; m < 8; m++) L[skew(base + m)] = v[m];
    __syncthreads();
    base = (t >> 3) << 6; int j = t & 7;
    #pragma unroll
    for(int m = 0; m < 8; m++) v[m] = L[skew(base + j + 8*m)];
    #pragma unroll
    for(int m = 1; m < 8; m++) v[m] = cmulc(v[m], g_twtab[((j*m) << 3) & 511]);
    dft8<true>(v);
    #pragma unroll
    for(int m = 0; m < 8; m++) L[skew(base + j + 8*m)] = v[m];
    __syncthreads();
    #pragma unroll
    for(int m = 0; m < 8; m++) v[m] = L[skew(t + 64*m)];
    #pragma unroll
    for(int m = 1; m < 8; m++) v[m] = cmulc(v[m], g_twtab[(t*m) & 511]);
    dft8<true>(v);
    #pragma unroll
    for(int m = 0; m < 8; m++) L[skew(t + 64*m)] = v[m];
}

__global__ void k_twtab(){
    int k = blockIdx.x * blockDim.x + threadIdx.x;
    if(k < 1024){
        double a;
        if(k < 512) a = -6.283185307179586476925286766559 * (double)k / 512.0;
        else        a = -6.283185307179586476925286766559 * (double)(k - 512) / (double)NFFT;
        double s, c; sincos(a, &s, &c);
        g_twtab[k] = make_float2((float)c, (float)s);
    }
    if(k == 0){
        int cnt = 0;
        for(int p = 0; p < 512; p++){
            int k1 = rev9(p);
            int pp = rev9((512 - k1) & 511);
            if(p <= pp){ g_pairA[cnt] = p; g_pairB[cnt] = pp; cnt++; }
        }
    }
}

__global__ __launch_bounds__(256) void k_prep(
    const float* __restrict__ voice, const float* __restrict__ cpc,
    const float* __restrict__ amp,   const float* __restrict__ room,
    const float* __restrict__ mix,   const float* __restrict__ times,
    const float* __restrict__ cp_table)
{
    int n = blockIdx.x, tid = threadIdx.x;
    __shared__ float sv[256];
    __shared__ int   si[256];
    __shared__ int   s_cidx, s_cnt;

    float best = -1e30f; int bi = 0;
    for(int j = tid; j < NCP; j += 256){
        float v = cpc[n*NCP + j];
        if(v > best){ best = v; bi = j; }
    }
    sv[tid] = best; si[tid] = bi; __syncthreads();
    for(int s = 128; s > 0; s >>= 1){
        if(tid < s){
            if(sv[tid+s] > sv[tid] || (sv[tid+s] == sv[tid] && si[tid+s] < si[tid])){
                sv[tid] = sv[tid+s]; si[tid] = si[tid+s];
            }
        }
        __syncthreads();
    }
    if(tid == 0){
        s_cidx = si[0];
        float b = -1e30f; int ii = 0;
        for(int j = 0; j < NFR; j++){ float v = times[n*NFR + j]; if(v > b){ b = v; ii = j; } }
        g_shift[n] = ii * (NSAMP / NFR);
        b = -1e30f; ii = 0;
        for(int j = 0; j < NVO; j++){ float v = voice[n*NVO + j]; if(v > b){ b = v; ii = j; } }
        g_vidx[n] = ii;
        b = -1e30f; ii = 0;
        for(int j = 0; j < NVB; j++){ float v = room[n*NVB + j]; if(v > b){ b = v; ii = j; } }
        g_ridx[n] = ii;
        float x0 = mix[n*2], x1 = mix[n*2 + 1];
        float mm = fmaxf(x0, x1);
        float e0 = expf(x0 - mm), e1 = expf(x1 - mm);
        g_m0[n] = e0 / (e0 + e1);
        g_m1[n] = e1 / (e0 + e1);
        g_amp[n] = fabsf(amp[n]);
    }
    __syncthreads();

    const float* row = cp_table + (size_t)s_cidx * (NFR*CPD);
    float rv[8];
    #pragma unroll
    for(int j = 0; j < 8; j++) rv[j] = row[tid + 256*j];
    unsigned lo = 0u, hi = 0x7F800000u;
    while(hi - lo > 1u){
        unsigned mid = lo + ((hi - lo) >> 1);
        int c = 0;
        #pragma unroll
        for(int j = 0; j < 8; j++) c += (__float_as_uint(rv[j]) >= mid) ? 1 : 0;
        si[tid] = c; __syncthreads();
        for(int s = 128; s > 0; s >>= 1){
            if(tid < s) si[tid] += si[tid+s];
            __syncthreads();
        }
        if(tid == 0) s_cnt = si[0];
        __syncthreads();
        if(s_cnt >= KSP) lo = mid; else hi = mid;
    }
    for(int idx = tid; idx < NFR*CPD; idx += 256){
        int f = idx >> 4, c = idx & 15;
        float v = row[c*NFR + f];
        float keep = (__float_as_uint(v) >= lo) ? v : 0.f;
        g_ctrl[n*NFR*CPD + idx] = fmaxf(keep, 0.f);
    }
}

// M[v] = W_ih[v] @ W_in[v] — parallel Kahan-fp32 split-K
__global__ __launch_bounds__(128) void k_collapse(
    const float* __restrict__ w_ih, const float* __restrict__ w_in)
{
    int blk = blockIdx.x;
    int v = blk >> 7, i = blk & 127;
    int t = threadIdx.x;
    const float* wr = w_ih + ((size_t)v*HID + i) * WINL;
    const float* wc = w_in + (size_t)v*WINL*CPD;
    float s[CPD], comp[CPD];
    #pragma unroll
    for(int c = 0; c < CPD; c++){ s[c] = 0.f; comp[c] = 0.f; }
    for(int k = t; k < WINL; k += 128){
        float a = wr[k];
        const float4* p = (const float4*)(wc + (size_t)k*CPD);
        float4 q[4] = {p[0], p[1], p[2], p[3]};
        const float* qs = (const float*)q;
        #pragma unroll
        for(int c = 0; c < CPD; c++){
            float y = fmaf(a, qs[c], -comp[c]);
            float tt = s[c] + y;
            comp[c] = (tt - s[c]) - y;
            s[c] = tt;
        }
    }
    __shared__ float red[128 * CPD];
    #pragma unroll
    for(int c = 0; c < CPD; c++) red[t*CPD + c] = s[c];
    __syncthreads();
    for(int st = 64; st > 0; st >>= 1){
        if(t < st){
            #pragma unroll
            for(int c = 0; c < CPD; c++) red[t*CPD + c] += red[(t+st)*CPD + c];
        }
        __syncthreads();
    }
    if(t < CPD) g_M[(v*HID + i)*CPD + t] = red[t];
}

__global__ __launch_bounds__(256) void k_rnn(const float* __restrict__ w_hh){
    int n = blockIdx.x, t = threadIdx.x;
    int i = t & 127, half = t >> 7;
    int v = g_vidx[n];
    __shared__ float ctrl_s[NFR*CPD];
    __shared__ float h_s[HID];
    __shared__ float part_s[256];

    float W[64];
    const float* wh = w_hh + ((size_t)v*HID + i) * HID + half*64;
    #pragma unroll
    for(int k = 0; k < 64; k++) W[k] = wh[k];
    float M[CPD];
    const float* mp = g_M + (v*HID + i)*CPD;
    #pragma unroll
    for(int c = 0; c < CPD; c++) M[c] = mp[c];
    for(int idx = t; idx < NFR*CPD; idx += 256) ctrl_s[idx] = g_ctrl[n*NFR*CPD + idx];
    if(t < HID) h_s[t] = 0.f;
    __syncthreads();

    float* hsout = g_hs + (size_t)n*NFR*HID;
    for(int f = 0; f < NFR; f++){
        float p = 0.f;
        const float* hb = h_s + half*64;
        #pragma unroll
        for(int k = 0; k < 64; k++) p += W[k] * hb[k];
        part_s[t] = p;
        __syncthreads();
        if(half == 0){
            float inp = 0.f;
            #pragma unroll
            for(int c = 0; c < CPD; c++) inp += M[c] * ctrl_s[f*CPD + c];
            float h = tanhf(p + part_s[t + 128] + inp);
            h_s[i] = h;
            hsout[f*HID + i] = h;
        }
        __syncthreads();
    }
}

// ---- tf32 helpers ----
__device__ __forceinline__ unsigned f2tf(float x){
    unsigned u; asm("cvt.rna.tf32.f32 %0, %1;" : "=r"(u) : "f"(x)); return u;
}
__device__ __forceinline__ void mma8(float* c, unsigned a0, unsigned a1, unsigned a2, unsigned a3,
                                     unsigned b0, unsigned b1){
    asm volatile("mma.sync.aligned.m16n8k8.row.col.f32.tf32.tf32.f32 "
        "{%0,%1,%2,%3}, {%4,%5,%6,%7}, {%8,%9}, {%0,%1,%2,%3};"
        : "+f"(c[0]), "+f"(c[1]), "+f"(c[2]), "+f"(c[3])
        : "r"(a0), "r"(a1), "r"(a2), "r"(a3), "r"(b0), "r"(b1));
}

// sig[f,w] = sin( hs[f,:] . w_out[v,w,:] ) via 3xTF32 split MMA
__global__ __launch_bounds__(256) void k_wout(const float* __restrict__ w_out){
    int wt = blockIdx.x, n = blockIdx.y, t = threadIdx.x;
    int v = g_vidx[n];
    const float* A  = g_hs + (size_t)n*NFR*HID;
    const float* Bm = w_out + (size_t)v*WINL*HID + (size_t)wt*128*HID;
    __shared__ uint2 As2[128*17];
    __shared__ uint2 Bs2[128*17];
    int lane = t & 31, wid = t >> 5;
    int wm = wid & 1, wn = wid >> 1;        // 2 x 4 warp grid
    int g = lane >> 2, tI = lane & 3;
    float C[4][4][4];
    #pragma unroll
    for(int mt = 0; mt < 4; mt++)
        #pragma unroll
        for(int nt = 0; nt < 4; nt++)
            #pragma unroll
            for(int q = 0; q < 4; q++) C[mt][nt][q] = 0.f;

    for(int kc = 0; kc < 8; kc++){
        int k0 = kc*16;
        #pragma unroll
        for(int j = 0; j < 8; j++){
            int idx = t + 256*j;
            int r = idx >> 4, k = idx & 15;
            float a = A[r*HID + k0 + k];
            unsigned ah = f2tf(a);
            As2[r*17 + k] = make_uint2(ah, f2tf(a - __uint_as_float(ah)));
            float b = Bm[(size_t)r*HID + k0 + k];
            unsigned bh = f2tf(b);
            Bs2[r*17 + k] = make_uint2(bh, f2tf(b - __uint_as_float(bh)));
        }
        __syncthreads();
        #pragma unroll
        for(int kt = 0; kt < 2; kt++){
            int kk = kt*8;
            uint2 a0[4], a1[4], a2[4], a3[4];
            #pragma unroll
            for(int mt = 0; mt < 4; mt++){
                int r = wm*64 + mt*16 + g;
                a0[mt] = As2[r*17 + kk + tI];
                a1[mt] = As2[(r+8)*17 + kk + tI];
                a2[mt] = As2[r*17 + kk + tI + 4];
                a3[mt] = As2[(r+8)*17 + kk + tI + 4];
            }
            uint2 b0[4], b1[4];
            #pragma unroll
            for(int nt = 0; nt < 4; nt++){
                int r = wn*32 + nt*8 + g;
                b0[nt] = Bs2[r*17 + kk + tI];
                b1[nt] = Bs2[r*17 + kk + tI + 4];
            }
            #pragma unroll
            for(int mt = 0; mt < 4; mt++)
                #pragma unroll
                for(int nt = 0; nt < 4; nt++){
                    mma8(C[mt][nt], a0[mt].x, a1[mt].x, a2[mt].x, a3[mt].x, b0[nt].x, b1[nt].x);
                    mma8(C[mt][nt], a0[mt].x, a1[mt].x, a2[mt].x, a3[mt].x, b0[nt].y, b1[nt].y);
                    mma8(C[mt][nt], a0[mt].y, a1[mt].y, a2[mt].y, a3[mt].y, b0[nt].x, b1[nt].x);
                }
        }
        __syncthreads();
    }
    float* outp = g_sig + (size_t)n*NSAMP + wt*128;
    #pragma unroll
    for(int mt = 0; mt < 4; mt++){
        int r0 = wm*64 + mt*16 + g;
        #pragma unroll
        for(int nt = 0; nt < 4; nt++){
            int c0 = wn*32 + nt*8 + tI*2;
            outp[(size_t)r0*WINL + c0]       = sinf(C[mt][nt][0]);
            outp[(size_t)r0*WINL + c0 + 1]   = sinf(C[mt][nt][1]);
            outp[(size_t)(r0+8)*WINL + c0]     = sinf(C[mt][nt][2]);
            outp[(size_t)(r0+8)*WINL + c0 + 1] = sinf(C[mt][nt][3]);
        }
    }
}

// F1 column pass (forward). VERB=1: real verb -> g_vspec. VERB=0: packed pair of sigs -> g_spec.
template<int VERB>
__global__ __launch_bounds__(512) void k_col_fwd(const float* __restrict__ rin_ext){
    __shared__ float2 s[8*LSTR];
    int y = blockIdx.y, col0 = blockIdx.x*8, tid = threadIdx.x;
    const float* sa; const float* sb = nullptr; float2* dst;
    if(VERB){ sa = rin_ext + (size_t)y*NSAMP;        dst = g_vspec + (size_t)y*NFFT; }
    else    { sa = g_sig + (size_t)(2*y)*NSAMP; sb = g_sig + (size_t)(2*y+1)*NSAMP;
              dst = g_spec + (size_t)y*NFFT; }
    for(int idx = tid; idx < 4096; idx += 512){
        int r = idx >> 3, c = idx & 7;
        float re = 0.f, im = 0.f;
        if(r < 256){
            int o = r*512 + col0 + c;
            re = sa[o];
            if(!VERB) im = sb[o];
        }
        s[c*LSTR + skew(r)] = make_float2(re, im);
    }
    __syncthreads();
    dif512(&s[(tid >> 6)*LSTR], tid & 63);
    __syncthreads();
    for(int idx = tid; idx < 4096; idx += 512){
        int r = idx >> 3, c = idx & 7;
        int n2 = col0 + c;
        dst[(size_t)r*512 + n2] = cmul(s[c*LSTR + skew(r)], twN(rev9(r)*n2));
    }
}

// F2 row pass for verb spectra (store in scrambled (row,e) layout)
__global__ __launch_bounds__(512) void k_row_verb(){
    __shared__ float2 s[8*LSTR];
    int n = blockIdx.y, row0 = blockIdx.x*8, tid = threadIdx.x;
    float2* base = g_vspec + (size_t)n*NFFT + (size_t)row0*512;
    for(int idx = tid; idx < 4096; idx += 512){
        int r = idx >> 9, e = idx & 511;
        s[r*LSTR + skew(e)] = base[(size_t)r*512 + e];
    }
    __syncthreads();
    dif512(&s[(tid >> 6)*LSTR], tid & 63);
    __syncthreads();
    for(int idx = tid; idx < 4096; idx += 512){
        int r = idx >> 9, e = idx & 511;
        base[(size_t)r*512 + e] = s[r*LSTR + skew(e)];
    }
}

__device__ __forceinline__ int pzero(int e){   // partner col for the k1==0 row
    int k2 = rev9(e);
    return rev9((512 - k2) & 511);
}

// Fused: F2 + conj-unpack + spectral mul (verb+dry fold, 1/N) + repack + I1 + conj twiddle.
// 512 threads = 4 pair-slots per block (8 lines). Extra groups clamp to slot 256 (idempotent).
__global__ __launch_bounds__(512) void k_rowpair(){
    __shared__ float2 s[8*LSTR];
    int p = blockIdx.y;
    int grp = threadIdx.x >> 7;
    int lt  = threadIdx.x & 127;
    int slot = blockIdx.x*4 + grp; if(slot > 256) slot = 256;
    int rows0 = g_pairA[slot], rows1 = g_pairB[slot];
    int line = lt >> 6, t = lt & 63;
    float2* base = g_spec + (size_t)p*NFFT;
    float2* sg = s + (2*grp)*LSTR;
    for(int idx = lt; idx < 1024; idx += 128){
        int l = idx >> 9, e = idx & 511;
        int row = l ? rows1 : rows0;
        sg[l*LSTR + skew(e)] = base[(size_t)row*512 + e];
    }
    __syncthreads();
    dif512(&sg[line*LSTR], t);
    __syncthreads();

    int na = 2*p, nb = 2*p + 1;
    const float2* va = g_vspec + (size_t)g_ridx[na]*NFFT;
    const float2* vb = g_vspec + (size_t)g_ridx[nb]*NFFT;
    float m0a = g_m0[na], m1a = g_m1[na], m0b = g_m0[nb], m1b = g_m1[nb];
    const float invN = 1.f / (float)NFFT;

    float2 Z[8], Zp[8];
    #pragma unroll
    for(int q = 0; q < 8; q++){
        int idx = lt + 128*q;
        int l = idx >> 9, e = idx & 511;
        int row = l ? rows1 : rows0;
        int k1 = rev9(row);
        int ep = (k1 == 0) ? pzero(e) : (511 - e);
        Z[q]  = sg[l*LSTR + skew(e)];
        Zp[q] = sg[(1 - l)*LSTR + skew(ep)];
    }
    __syncthreads();
    #pragma unroll
    for(int q = 0; q < 8; q++){
        int idx = lt + 128*q;
        int l = idx >> 9, e = idx & 511;
        int row = l ? rows1 : rows0;
        float2 S1 = make_float2(0.5f*(Z[q].x + Zp[q].x), 0.5f*(Z[q].y - Zp[q].y));
        float2 S2 = make_float2(0.5f*(Z[q].y + Zp[q].y), -0.5f*(Z[q].x - Zp[q].x));
        float2 V1 = va[(size_t)row*512 + e];
        float2 V2 = vb[(size_t)row*512 + e];
        float2 M1 = make_float2(m0a*V1.x + m1a, m0a*V1.y);
        float2 M2 = make_float2(m0b*V2.x + m1b, m0b*V2.y);
        float2 W1 = cmul(S1, M1), W2 = cmul(S2, M2);
        sg[l*LSTR + skew(e)] = make_float2((W1.x - W2.y)*invN, (W1.y + W2.x)*invN);
    }
    __syncthreads();
    dit512(&sg[line*LSTR], t);
    __syncthreads();
    for(int idx = lt; idx < 1024; idx += 128){
        int l = idx >> 9, e = idx & 511;
        int row = l ? rows1 : rows0;
        int k1 = rev9(row);
        base[(size_t)row*512 + e] = cmulc(sg[l*LSTR + skew(e)], twN(k1*e));
    }
}

// I2 column pass (inverse, packed) + epilogue: |amp| + dirac row-shift.
__global__ __launch_bounds__(512) void k_col_inv(float* __restrict__ out){
    __shared__ float2 s[8*LSTR];
    int p = blockIdx.y, col0 = blockIdx.x*8, tid = threadIdx.x;
    const float2* src = g_spec + (size_t)p*NFFT;
    for(int idx = tid; idx < 4096; idx += 512){
        int r = idx >> 3, c = idx & 7;
        s[c*LSTR + skew(r)] = src[(size_t)r*512 + col0 + c];
    }
    __syncthreads();
    dit512(&s[(tid >> 6)*LSTR], tid & 63);
    __syncthreads();
    int na = 2*p, nb = 2*p + 1;
    float aA = g_amp[na], aB = g_amp[nb];
    int dA = g_shift[na] >> 9, dB = g_shift[nb] >> 9;
    float* oA = out + (size_t)na*NSAMP;
    float* oB = out + (size_t)nb*NSAMP;
    for(int idx = tid; idx < 2048; idx += 512){
        int rp = idx >> 3, c = idx & 7;
        int col = col0 + c;
        int ra = rp - dA;
        oA[rp*512 + col] = (ra >= 0) ? s[c*LSTR + skew(ra)].x * aA : 0.f;
        int rb = rp - dB;
        oB[rp*512 + col] = (rb >= 0) ? s[c*LSTR + skew(rb)].y * aB : 0.f;
    }
}

extern "C" void kernel_launch(void* const* d_in, const int* in_sizes, int n_in,
                              void* d_out, int out_size) {
    const float* voice = (const float*)d_in[0];
    const float* cpc   = (const float*)d_in[1];
    const float* amp   = (const float*)d_in[2];
    const float* room  = (const float*)d_in[3];
    const float* mix   = (const float*)d_in[4];
    const float* times = (const float*)d_in[5];
    const float* cp_table = (const float*)d_in[6];
    const float* verbs = (const float*)d_in[7];
    const float* w_in  = (const float*)d_in[8];
    const float* w_ih  = (const float*)d_in[9];
    const float* w_hh  = (const float*)d_in[10];
    const float* w_out = (const float*)d_in[11];
    float* out = (float*)d_out;

    k_twtab<<<2, 512>>>();
    k_prep<<<NEV, 256>>>(voice, cpc, amp, room, mix, times, cp_table);
    k_collapse<<<NVO*HID, 128>>>(w_ih, w_in);
    k_rnn<<<NEV, 256>>>(w_hh);
    k_wout<<<dim3(8, NEV), 256>>>(w_out);
    k_col_fwd<1><<<dim3(64, NVB), 512>>>(verbs);
    k_row_verb<<<dim3(64, NVB), 512>>>();
    k_col_fwd<0><<<dim3(64, NPAIR), 512>>>(nullptr);
    k_rowpair<<<dim3(65, NPAIR), 512>>>();
    k_col_inv<<<dim3(64, NPAIR), 512>>>(out);
}

// round 7
// speedup vs baseline: 1.1257x; 1.1257x over previous
#include <cuda_runtime.h>
#include <math.h>

#define NEV   128
#define NPAIR 64
#define NSAMP 131072
#define NFFT  262144
#define NFR   128
#define WINL  1024
#define CPD   16
#define NCP   512
#define NVO   8
#define NVB   16
#define HID   128
#define KSP   128
#define LSTR  576

__device__ float2 g_twtab[1024];                     // [0:512) W512^k ; [512:1024) W_N^k
__device__ float2 g_spec[(size_t)NPAIR * NFFT];      // 128 MB packed spectra
__device__ float2 g_vspec[(size_t)NVB * NFFT];       // 32 MB verb spectra
__device__ float  g_sig[(size_t)NEV * NSAMP];
__device__ float  g_hs[(size_t)NEV * NFR * HID];
__device__ float  g_ctrl[NEV * NFR * CPD];
__device__ float  g_M[NVO * HID * CPD];
__device__ int    g_vidx[NEV], g_ridx[NEV], g_shift[NEV];
__device__ float  g_m0[NEV], g_m1[NEV], g_amp[NEV];
__device__ int    g_pairA[257], g_pairB[257];

__device__ __forceinline__ int skew(int i){ return i + (i >> 3); }
__device__ __forceinline__ float2 cadd(float2 a, float2 b){ return make_float2(a.x+b.x, a.y+b.y); }
__device__ __forceinline__ float2 csub(float2 a, float2 b){ return make_float2(a.x-b.x, a.y-b.y); }
__device__ __forceinline__ float2 cmul(float2 a, float2 b){ return make_float2(a.x*b.x - a.y*b.y, a.x*b.y + a.y*b.x); }
__device__ __forceinline__ float2 cmulc(float2 a, float2 b){ return make_float2(a.x*b.x + a.y*b.y, a.y*b.x - a.x*b.y); }
__device__ __forceinline__ int rev9(int p){ return ((p & 7) << 6) | (p & 56) | (p >> 6); }

__device__ __forceinline__ float2 twN(int idx){
    int k = idx & (NFFT - 1);
    return cmul(g_twtab[k >> 9], g_twtab[512 + (k & 511)]);
}

template<bool INV>
__device__ __forceinline__ float2 mulmi(float2 a){
    return INV ? make_float2(-a.y, a.x) : make_float2(a.y, -a.x);
}

template<bool INV>
__device__ __forceinline__ void dft8(float2* v){
    float2 t0 = cadd(v[0], v[4]), t1 = csub(v[0], v[4]);
    float2 t2 = cadd(v[2], v[6]), t3 = mulmi<INV>(csub(v[2], v[6]));
    float2 t4 = cadd(v[1], v[5]), t5 = csub(v[1], v[5]);
    float2 t6 = cadd(v[3], v[7]), t7 = mulmi<INV>(csub(v[3], v[7]));
    float2 a0 = cadd(t0, t2), a2 = csub(t0, t2);
    float2 a1 = cadd(t1, t3), a3 = csub(t1, t3);
    float2 b0 = cadd(t4, t6), b2 = csub(t4, t6);
    float2 b1 = cadd(t5, t7), b3 = csub(t5, t7);
    const float r = 0.70710678118654752440f;
    float2 w1 = INV ? make_float2(r,  r) : make_float2(r, -r);
    float2 w3 = INV ? make_float2(-r, r) : make_float2(-r, -r);
    b1 = cmul(b1, w1); b2 = mulmi<INV>(b2); b3 = cmul(b3, w3);
    v[0] = cadd(a0, b0); v[4] = csub(a0, b0);
    v[1] = cadd(a1, b1); v[5] = csub(a1, b1);
    v[2] = cadd(a2, b2); v[6] = csub(a2, b2);
    v[3] = cadd(a3, b3); v[7] = csub(a3, b3);
}

// DIF 512 = radix-8^3, natural in -> octal-digit-reversed out.
__device__ __forceinline__ void dif512(float2* L, int t){
    float2 v[8];
    #pragma unroll
    for(int m = 0; m < 8; m++) v[m] = L[skew(t + 64*m)];
    dft8<false>(v);
    #pragma unroll
    for(int m = 1; m < 8; m++) v[m] = cmul(v[m], g_twtab[(t*m) & 511]);
    #pragma unroll
    for(int m = 0; m < 8; m++) L[skew(t + 64*m)] = v[m];
    __syncthreads();
    int base = (t >> 3) << 6, j = t & 7;
    #pragma unroll
    for(int m = 0; m < 8; m++) v[m] = L[skew(base + j + 8*m)];
    dft8<false>(v);
    #pragma unroll
    for(int m = 1; m < 8; m++) v[m] = cmul(v[m], g_twtab[((j*m) << 3) & 511]);
    #pragma unroll
    for(int m = 0; m < 8; m++) L[skew(base + j + 8*m)] = v[m];
    __syncthreads();
    base = t << 3;
    #pragma unroll
    for(int m = 0; m < 8; m++) v[m] = L[skew(base + m)];
    dft8<false>(v);
    #pragma unroll
    for(int m = 0; m < 8; m++) L[skew(base + m)] = v[m];
}

// DIT 512: digit-reversed in -> natural out, conjugate twiddles (unscaled inverse).
__device__ __forceinline__ void dit512(float2* L, int t){
    float2 v[8];
    int base = t << 3;
    #pragma unroll
    for(int m = 0; m < 8; m++) v[m] = L[skew(base + m)];
    dft8<true>(v);
    #pragma unroll
    for(int m = 0; m < 8; m++) L[skew(base + m)] = v[m];
    __syncthreads();
    base = (t >> 3) << 6; int j = t & 7;
    #pragma unroll
    for(int m = 0; m < 8; m++) v[m] = L[skew(base + j + 8*m)];
    #pragma unroll
    for(int m = 1; m < 8; m++) v[m] = cmulc(v[m], g_twtab[((j*m) << 3) & 511]);
    dft8<true>(v);
    #pragma unroll
    for(int m = 0; m < 8; m++) L[skew(base + j + 8*m)] = v[m];
    __syncthreads();
    #pragma unroll
    for(int m = 0; m < 8; m++) v[m] = L[skew(t + 64*m)];
    #pragma unroll
    for(int m = 1; m < 8; m++) v[m] = cmulc(v[m], g_twtab[(t*m) & 511]);
    dft8<true>(v);
    #pragma unroll
    for(int m = 0; m < 8; m++) L[skew(t + 64*m)] = v[m];
}

__global__ void k_twtab(){
    int k = blockIdx.x * blockDim.x + threadIdx.x;
    if(k < 1024){
        double a;
        if(k < 512) a = -6.283185307179586476925286766559 * (double)k / 512.0;
        else        a = -6.283185307179586476925286766559 * (double)(k - 512) / (double)NFFT;
        double s, c; sincos(a, &s, &c);
        g_twtab[k] = make_float2((float)c, (float)s);
    }
    if(k == 0){
        int cnt = 0;
        for(int p = 0; p < 512; p++){
            int k1 = rev9(p);
            int pp = rev9((512 - k1) & 511);
            if(p <= pp){ g_pairA[cnt] = p; g_pairB[cnt] = pp; cnt++; }
        }
    }
}

__global__ __launch_bounds__(256) void k_prep(
    const float* __restrict__ voice, const float* __restrict__ cpc,
    const float* __restrict__ amp,   const float* __restrict__ room,
    const float* __restrict__ mix,   const float* __restrict__ times,
    const float* __restrict__ cp_table)
{
    int n = blockIdx.x, tid = threadIdx.x;
    __shared__ float sv[256];
    __shared__ int   si[256];
    __shared__ int   s_cidx, s_cnt;

    float best = -1e30f; int bi = 0;
    for(int j = tid; j < NCP; j += 256){
        float v = cpc[n*NCP + j];
        if(v > best){ best = v; bi = j; }
    }
    sv[tid] = best; si[tid] = bi; __syncthreads();
    for(int s = 128; s > 0; s >>= 1){
        if(tid < s){
            if(sv[tid+s] > sv[tid] || (sv[tid+s] == sv[tid] && si[tid+s] < si[tid])){
                sv[tid] = sv[tid+s]; si[tid] = si[tid+s];
            }
        }
        __syncthreads();
    }
    if(tid == 0){
        s_cidx = si[0];
        float b = -1e30f; int ii = 0;
        for(int j = 0; j < NFR; j++){ float v = times[n*NFR + j]; if(v > b){ b = v; ii = j; } }
        g_shift[n] = ii * (NSAMP / NFR);
        b = -1e30f; ii = 0;
        for(int j = 0; j < NVO; j++){ float v = voice[n*NVO + j]; if(v > b){ b = v; ii = j; } }
        g_vidx[n] = ii;
        b = -1e30f; ii = 0;
        for(int j = 0; j < NVB; j++){ float v = room[n*NVB + j]; if(v > b){ b = v; ii = j; } }
        g_ridx[n] = ii;
        float x0 = mix[n*2], x1 = mix[n*2 + 1];
        float mm = fmaxf(x0, x1);
        float e0 = expf(x0 - mm), e1 = expf(x1 - mm);
        g_m0[n] = e0 / (e0 + e1);
        g_m1[n] = e1 / (e0 + e1);
        g_amp[n] = fabsf(amp[n]);
    }
    __syncthreads();

    const float* row = cp_table + (size_t)s_cidx * (NFR*CPD);
    float rv[8];
    #pragma unroll
    for(int j = 0; j < 8; j++) rv[j] = row[tid + 256*j];
    unsigned lo = 0u, hi = 0x7F800000u;
    while(hi - lo > 1u){
        unsigned mid = lo + ((hi - lo) >> 1);
        int c = 0;
        #pragma unroll
        for(int j = 0; j < 8; j++) c += (__float_as_uint(rv[j]) >= mid) ? 1 : 0;
        si[tid] = c; __syncthreads();
        for(int s = 128; s > 0; s >>= 1){
            if(tid < s) si[tid] += si[tid+s];
            __syncthreads();
        }
        if(tid == 0) s_cnt = si[0];
        __syncthreads();
        if(s_cnt >= KSP) lo = mid; else hi = mid;
    }
    for(int idx = tid; idx < NFR*CPD; idx += 256){
        int f = idx >> 4, c = idx & 15;
        float v = row[c*NFR + f];
        float keep = (__float_as_uint(v) >= lo) ? v : 0.f;
        g_ctrl[n*NFR*CPD + idx] = fmaxf(keep, 0.f);
    }
}

// M[v] = W_ih[v] @ W_in[v] — parallel Kahan-fp32 split-K
__global__ __launch_bounds__(128) void k_collapse(
    const float* __restrict__ w_ih, const float* __restrict__ w_in)
{
    int blk = blockIdx.x;
    int v = blk >> 7, i = blk & 127;
    int t = threadIdx.x;
    const float* wr = w_ih + ((size_t)v*HID + i) * WINL;
    const float* wc = w_in + (size_t)v*WINL*CPD;
    float s[CPD], comp[CPD];
    #pragma unroll
    for(int c = 0; c < CPD; c++){ s[c] = 0.f; comp[c] = 0.f; }
    for(int k = t; k < WINL; k += 128){
        float a = wr[k];
        const float4* p = (const float4*)(wc + (size_t)k*CPD);
        float4 q[4] = {p[0], p[1], p[2], p[3]};
        const float* qs = (const float*)q;
        #pragma unroll
        for(int c = 0; c < CPD; c++){
            float y = fmaf(a, qs[c], -comp[c]);
            float tt = s[c] + y;
            comp[c] = (tt - s[c]) - y;
            s[c] = tt;
        }
    }
    __shared__ float red[128 * CPD];
    #pragma unroll
    for(int c = 0; c < CPD; c++) red[t*CPD + c] = s[c];
    __syncthreads();
    for(int st = 64; st > 0; st >>= 1){
        if(t < st){
            #pragma unroll
            for(int c = 0; c < CPD; c++) red[t*CPD + c] += red[(t+st)*CPD + c];
        }
        __syncthreads();
    }
    if(t < CPD) g_M[(v*HID + i)*CPD + t] = red[t];
}

// persistent RNN: one block per event; 4-way split accumulators + hoisted input projection
__global__ __launch_bounds__(256) void k_rnn(const float* __restrict__ w_hh){
    int n = blockIdx.x, t = threadIdx.x;
    int i = t & 127, half = t >> 7;
    int v = g_vidx[n];
    __shared__ float ctrl_s[NFR*CPD];
    __shared__ float h_s[HID];
    __shared__ float part_s[256];

    float W[64];
    const float* wh = w_hh + ((size_t)v*HID + i) * HID + half*64;
    #pragma unroll
    for(int k = 0; k < 64; k++) W[k] = wh[k];
    float M[CPD];
    const float* mp = g_M + (v*HID + i)*CPD;
    #pragma unroll
    for(int c = 0; c < CPD; c++) M[c] = mp[c];
    for(int idx = t; idx < NFR*CPD; idx += 256) ctrl_s[idx] = g_ctrl[n*NFR*CPD + idx];
    if(t < HID) h_s[t] = 0.f;
    __syncthreads();

    float* hsout = g_hs + (size_t)n*NFR*HID;
    for(int f = 0; f < NFR; f++){
        const float* hb = h_s + half*64;
        float p0 = 0.f, p1 = 0.f, p2 = 0.f, p3 = 0.f;
        #pragma unroll
        for(int k = 0; k < 64; k += 4){
            p0 = fmaf(W[k],   hb[k],   p0);
            p1 = fmaf(W[k+1], hb[k+1], p1);
            p2 = fmaf(W[k+2], hb[k+2], p2);
            p3 = fmaf(W[k+3], hb[k+3], p3);
        }
        // input projection hoisted into the pre-barrier phase (ILP-overlapped, half 0 only)
        float inp = 0.f;
        if(half == 0){
            const float* cf = ctrl_s + f*CPD;
            float i0 = 0.f, i1 = 0.f;
            #pragma unroll
            for(int c = 0; c < CPD; c += 2){
                i0 = fmaf(M[c],   cf[c],   i0);
                i1 = fmaf(M[c+1], cf[c+1], i1);
            }
            inp = i0 + i1;
        }
        part_s[t] = (p0 + p1) + (p2 + p3);
        __syncthreads();
        if(half == 0){
            float h = tanhf(part_s[t] + part_s[t + 128] + inp);
            h_s[i] = h;
            hsout[f*HID + i] = h;
        }
        __syncthreads();
    }
}

// sig[f,w] = sin( hs[f,:] . w_out[v,w,:] ) — fp32 register-tiled GEMM (R5 version)
__global__ __launch_bounds__(256) void k_wout(const float* __restrict__ w_out){
    int wt = blockIdx.x, n = blockIdx.y, t = threadIdx.x;
    int v = g_vidx[n];
    const float* A  = g_hs + (size_t)n*NFR*HID;
    const float* Bm = w_out + (size_t)v*WINL*HID + (size_t)wt*128*HID;
    __shared__ float As[32*132];
    __shared__ float Bs[32*132];
    int tx = t & 15, ty = t >> 4;
    int f0 = ty*8, w0 = tx*8;
    float acc[8][8];
    #pragma unroll
    for(int i = 0; i < 8; i++)
        #pragma unroll
        for(int j = 0; j < 8; j++) acc[i][j] = 0.f;

    for(int ks = 0; ks < 4; ks++){
        int k0 = ks*32;
        #pragma unroll
        for(int r = 0; r < 4; r++){
            int idx4 = t + 256*r;
            int rr = idx4 >> 3, kk4 = idx4 & 7;
            float4 va = *(const float4*)(A  + (size_t)rr*HID + k0 + kk4*4);
            float4 vb = *(const float4*)(Bm + (size_t)rr*HID + k0 + kk4*4);
            As[(kk4*4+0)*132 + rr] = va.x; As[(kk4*4+1)*132 + rr] = va.y;
            As[(kk4*4+2)*132 + rr] = va.z; As[(kk4*4+3)*132 + rr] = va.w;
            Bs[(kk4*4+0)*132 + rr] = vb.x; Bs[(kk4*4+1)*132 + rr] = vb.y;
            Bs[(kk4*4+2)*132 + rr] = vb.z; Bs[(kk4*4+3)*132 + rr] = vb.w;
        }
        __syncthreads();
        #pragma unroll
        for(int k = 0; k < 32; k++){
            float4 a0 = *(const float4*)&As[k*132 + f0];
            float4 a1 = *(const float4*)&As[k*132 + f0 + 4];
            float4 b0 = *(const float4*)&Bs[k*132 + w0];
            float4 b1 = *(const float4*)&Bs[k*132 + w0 + 4];
            float a[8] = {a0.x,a0.y,a0.z,a0.w,a1.x,a1.y,a1.z,a1.w};
            float b[8] = {b0.x,b0.y,b0.z,b0.w,b1.x,b1.y,b1.z,b1.w};
            #pragma unroll
            for(int i = 0; i < 8; i++)
                #pragma unroll
                for(int j = 0; j < 8; j++) acc[i][j] += a[i]*b[j];
        }
        __syncthreads();
    }
    float* out = g_sig + (size_t)n*NSAMP + wt*128;
    #pragma unroll
    for(int i = 0; i < 8; i++)
        #pragma unroll
        for(int j = 0; j < 8; j++)
            out[(size_t)(f0+i)*WINL + w0 + j] = sinf(acc[i][j]);
}

// F1 column pass (forward). VERB=1: real verb -> g_vspec. VERB=0: packed pair of sigs -> g_spec.
template<int VERB>
__global__ __launch_bounds__(512) void k_col_fwd(const float* __restrict__ rin_ext){
    __shared__ float2 s[8*LSTR];
    int y = blockIdx.y, col0 = blockIdx.x*8, tid = threadIdx.x;
    const float* sa; const float* sb = nullptr; float2* dst;
    if(VERB){ sa = rin_ext + (size_t)y*NSAMP;        dst = g_vspec + (size_t)y*NFFT; }
    else    { sa = g_sig + (size_t)(2*y)*NSAMP; sb = g_sig + (size_t)(2*y+1)*NSAMP;
              dst = g_spec + (size_t)y*NFFT; }
    for(int idx = tid; idx < 4096; idx += 512){
        int r = idx >> 3, c = idx & 7;
        float re = 0.f, im = 0.f;
        if(r < 256){
            int o = r*512 + col0 + c;
            re = sa[o];
            if(!VERB) im = sb[o];
        }
        s[c*LSTR + skew(r)] = make_float2(re, im);
    }
    __syncthreads();
    dif512(&s[(tid >> 6)*LSTR], tid & 63);
    __syncthreads();
    for(int idx = tid; idx < 4096; idx += 512){
        int r = idx >> 3, c = idx & 7;
        int n2 = col0 + c;
        dst[(size_t)r*512 + n2] = cmul(s[c*LSTR + skew(r)], twN(rev9(r)*n2));
    }
}

// F2 row pass for verb spectra (store in scrambled (row,e) layout)
__global__ __launch_bounds__(512) void k_row_verb(){
    __shared__ float2 s[8*LSTR];
    int n = blockIdx.y, row0 = blockIdx.x*8, tid = threadIdx.x;
    float2* base = g_vspec + (size_t)n*NFFT + (size_t)row0*512;
    for(int idx = tid; idx < 4096; idx += 512){
        int r = idx >> 9, e = idx & 511;
        s[r*LSTR + skew(e)] = base[(size_t)r*512 + e];
    }
    __syncthreads();
    dif512(&s[(tid >> 6)*LSTR], tid & 63);
    __syncthreads();
    for(int idx = tid; idx < 4096; idx += 512){
        int r = idx >> 9, e = idx & 511;
        base[(size_t)r*512 + e] = s[r*LSTR + skew(e)];
    }
}

__device__ __forceinline__ int pzero(int e){   // partner col for the k1==0 row
    int k2 = rev9(e);
    return rev9((512 - k2) & 511);
}

// Fused: F2 + conj-unpack + spectral mul (verb+dry fold, 1/N) + repack + I1 + conj twiddle (R5 version)
__global__ __launch_bounds__(128) void k_rowpair(){
    __shared__ float2 s[2*LSTR];
    int slot = blockIdx.x, p = blockIdx.y;
    int rows0 = g_pairA[slot], rows1 = g_pairB[slot];
    int line = threadIdx.x >> 6, t = threadIdx.x & 63;
    float2* base = g_spec + (size_t)p*NFFT;
    for(int idx = threadIdx.x; idx < 1024; idx += 128){
        int l = idx >> 9, e = idx & 511;
        int row = l ? rows1 : rows0;
        s[l*LSTR + skew(e)] = base[(size_t)row*512 + e];
    }
    __syncthreads();
    dif512(&s[line*LSTR], t);
    __syncthreads();

    int na = 2*p, nb = 2*p + 1;
    const float2* va = g_vspec + (size_t)g_ridx[na]*NFFT;
    const float2* vb = g_vspec + (size_t)g_ridx[nb]*NFFT;
    float m0a = g_m0[na], m1a = g_m1[na], m0b = g_m0[nb], m1b = g_m1[nb];
    const float invN = 1.f / (float)NFFT;

    float2 Z[8], Zp[8];
    #pragma unroll
    for(int q = 0; q < 8; q++){
        int idx = threadIdx.x + 128*q;
        int l = idx >> 9, e = idx & 511;
        int row = l ? rows1 : rows0;
        int k1 = rev9(row);
        int ep = (k1 == 0) ? pzero(e) : (511 - e);
        Z[q]  = s[l*LSTR + skew(e)];
        Zp[q] = s[(1 - l)*LSTR + skew(ep)];
    }
    __syncthreads();
    #pragma unroll
    for(int q = 0; q < 8; q++){
        int idx = threadIdx.x + 128*q;
        int l = idx >> 9, e = idx & 511;
        int row = l ? rows1 : rows0;
        float2 S1 = make_float2(0.5f*(Z[q].x + Zp[q].x), 0.5f*(Z[q].y - Zp[q].y));
        float2 S2 = make_float2(0.5f*(Z[q].y + Zp[q].y), -0.5f*(Z[q].x - Zp[q].x));
        float2 V1 = va[(size_t)row*512 + e];
        float2 V2 = vb[(size_t)row*512 + e];
        float2 M1 = make_float2(m0a*V1.x + m1a, m0a*V1.y);
        float2 M2 = make_float2(m0b*V2.x + m1b, m0b*V2.y);
        float2 W1 = cmul(S1, M1), W2 = cmul(S2, M2);
        s[l*LSTR + skew(e)] = make_float2((W1.x - W2.y)*invN, (W1.y + W2.x)*invN);
    }
    __syncthreads();
    dit512(&s[line*LSTR], t);
    __syncthreads();
    for(int idx = threadIdx.x; idx < 1024; idx += 128){
        int l = idx >> 9, e = idx & 511;
        int row = l ? rows1 : rows0;
        int k1 = rev9(row);
        base[(size_t)row*512 + e] = cmulc(s[l*LSTR + skew(e)], twN(k1*e));
    }
}

// I2 column pass (inverse, packed) + epilogue: |amp| + dirac row-shift.
__global__ __launch_bounds__(512) void k_col_inv(float* __restrict__ out){
    __shared__ float2 s[8*LSTR];
    int p = blockIdx.y, col0 = blockIdx.x*8, tid = threadIdx.x;
    const float2* src = g_spec + (size_t)p*NFFT;
    for(int idx = tid; idx < 4096; idx += 512){
        int r = idx >> 3, c = idx & 7;
        s[c*LSTR + skew(r)] = src[(size_t)r*512 + col0 + c];
    }
    __syncthreads();
    dit512(&s[(tid >> 6)*LSTR], tid & 63);
    __syncthreads();
    int na = 2*p, nb = 2*p + 1;
    float aA = g_amp[na], aB = g_amp[nb];
    int dA = g_shift[na] >> 9, dB = g_shift[nb] >> 9;
    float* oA = out + (size_t)na*NSAMP;
    float* oB = out + (size_t)nb*NSAMP;
    for(int idx = tid; idx < 2048; idx += 512){
        int rp = idx >> 3, c = idx & 7;
        int col = col0 + c;
        int ra = rp - dA;
        oA[rp*512 + col] = (ra >= 0) ? s[c*LSTR + skew(ra)].x * aA : 0.f;
        int rb = rp - dB;
        oB[rp*512 + col] = (rb >= 0) ? s[c*LSTR + skew(rb)].y * aB : 0.f;
    }
}

extern "C" void kernel_launch(void* const* d_in, const int* in_sizes, int n_in,
                              void* d_out, int out_size) {
    const float* voice = (const float*)d_in[0];
    const float* cpc   = (const float*)d_in[1];
    const float* amp   = (const float*)d_in[2];
    const float* room  = (const float*)d_in[3];
    const float* mix   = (const float*)d_in[4];
    const float* times = (const float*)d_in[5];
    const float* cp_table = (const float*)d_in[6];
    const float* verbs = (const float*)d_in[7];
    const float* w_in  = (const float*)d_in[8];
    const float* w_ih  = (const float*)d_in[9];
    const float* w_hh  = (const float*)d_in[10];
    const float* w_out = (const float*)d_in[11];
    float* out = (float*)d_out;

    k_twtab<<<2, 512>>>();
    k_prep<<<NEV, 256>>>(voice, cpc, amp, room, mix, times, cp_table);
    k_collapse<<<NVO*HID, 128>>>(w_ih, w_in);
    k_rnn<<<NEV, 256>>>(w_hh);
    k_wout<<<dim3(8, NEV), 256>>>(w_out);
    k_col_fwd<1><<<dim3(64, NVB), 512>>>(verbs);
    k_row_verb<<<dim3(64, NVB), 512>>>();
    k_col_fwd<0><<<dim3(64, NPAIR), 512>>>(nullptr);
    k_rowpair<<<dim3(257, NPAIR), 128>>>();
    k_col_inv<<<dim3(64, NPAIR), 512>>>(out);
}

// round 8
// speedup vs baseline: 1.2328x; 1.0951x over previous
#include <cuda_runtime.h>
#include <math.h>

#define NEV   128
#define NPAIR 64
#define NSAMP 131072
#define NFFT  262144
#define NFR   128
#define WINL  1024
#define CPD   16
#define NCP   512
#define NVO   8
#define NVB   16
#define HID   128
#define KSP   128
#define LSTR  578

__device__ float2 g_twtab[1024];                     // [0:512) W512^k ; [512:1024) W_N^k
__device__ float2 g_spec[(size_t)NPAIR * NFFT];      // 128 MB packed spectra
__device__ float2 g_vspec[(size_t)NVB * NFFT];       // 32 MB verb spectra
__device__ float  g_sig[(size_t)NEV * NSAMP];
__device__ float  g_hs[(size_t)NEV * NFR * HID];
__device__ float  g_ctrl[NEV * NFR * CPD];
__device__ float  g_M[NVO * HID * CPD];
__device__ int    g_vidx[NEV], g_ridx[NEV], g_shift[NEV];
__device__ float  g_m0[NEV], g_m1[NEV], g_amp[NEV];
__device__ int    g_pairA[257], g_pairB[257];

__device__ __forceinline__ int skew(int i){ return i + (i >> 3); }
__device__ __forceinline__ float2 cadd(float2 a, float2 b){ return make_float2(a.x+b.x, a.y+b.y); }
__device__ __forceinline__ float2 csub(float2 a, float2 b){ return make_float2(a.x-b.x, a.y-b.y); }
__device__ __forceinline__ float2 cmul(float2 a, float2 b){ return make_float2(a.x*b.x - a.y*b.y, a.x*b.y + a.y*b.x); }
__device__ __forceinline__ float2 cmulc(float2 a, float2 b){ return make_float2(a.x*b.x + a.y*b.y, a.y*b.x - a.x*b.y); }
__device__ __forceinline__ int rev9(int p){ return ((p & 7) << 6) | (p & 56) | (p >> 6); }

__device__ __forceinline__ float2 twN(int idx){
    int k = idx & (NFFT - 1);
    return cmul(g_twtab[k >> 9], g_twtab[512 + (k & 511)]);
}

template<bool INV>
__device__ __forceinline__ float2 mulmi(float2 a){
    return INV ? make_float2(-a.y, a.x) : make_float2(a.y, -a.x);
}

template<bool INV>
__device__ __forceinline__ void dft8(float2* v){
    float2 t0 = cadd(v[0], v[4]), t1 = csub(v[0], v[4]);
    float2 t2 = cadd(v[2], v[6]), t3 = mulmi<INV>(csub(v[2], v[6]));
    float2 t4 = cadd(v[1], v[5]), t5 = csub(v[1], v[5]);
    float2 t6 = cadd(v[3], v[7]), t7 = mulmi<INV>(csub(v[3], v[7]));
    float2 a0 = cadd(t0, t2), a2 = csub(t0, t2);
    float2 a1 = cadd(t1, t3), a3 = csub(t1, t3);
    float2 b0 = cadd(t4, t6), b2 = csub(t4, t6);
    float2 b1 = cadd(t5, t7), b3 = csub(t5, t7);
    const float r = 0.70710678118654752440f;
    float2 w1 = INV ? make_float2(r,  r) : make_float2(r, -r);
    float2 w3 = INV ? make_float2(-r, r) : make_float2(-r, -r);
    b1 = cmul(b1, w1); b2 = mulmi<INV>(b2); b3 = cmul(b3, w3);
    v[0] = cadd(a0, b0); v[4] = csub(a0, b0);
    v[1] = cadd(a1, b1); v[5] = csub(a1, b1);
    v[2] = cadd(a2, b2); v[6] = csub(a2, b2);
    v[3] = cadd(a3, b3); v[7] = csub(a3, b3);
}

// DIF 512 = radix-8^3, natural in -> octal-digit-reversed out.
__device__ __forceinline__ void dif512(float2* L, int t){
    float2 v[8];
    #pragma unroll
    for(int m = 0; m < 8; m++) v[m] = L[skew(t + 64*m)];
    dft8<false>(v);
    #pragma unroll
    for(int m = 1; m < 8; m++) v[m] = cmul(v[m], g_twtab[(t*m) & 511]);
    #pragma unroll
    for(int m = 0; m < 8; m++) L[skew(t + 64*m)] = v[m];
    __syncthreads();
    int base = (t >> 3) << 6, j = t & 7;
    #pragma unroll
    for(int m = 0; m < 8; m++) v[m] = L[skew(base + j + 8*m)];
    dft8<false>(v);
    #pragma unroll
    for(int m = 1; m < 8; m++) v[m] = cmul(v[m], g_twtab[((j*m) << 3) & 511]);
    #pragma unroll
    for(int m = 0; m < 8; m++) L[skew(base + j + 8*m)] = v[m];
    __syncthreads();
    base = t << 3;
    #pragma unroll
    for(int m = 0; m < 8; m++) v[m] = L[skew(base + m)];
    dft8<false>(v);
    #pragma unroll
    for(int m = 0; m < 8; m++) L[skew(base + m)] = v[m];
}

// DIT 512: digit-reversed in -> natural out, conjugate twiddles (unscaled inverse).
__device__ __forceinline__ void dit512(float2* L, int t){
    float2 v[8];
    int base = t << 3;
    #pragma unroll
    for(int m = 0; m < 8; m++) v[m] = L[skew(base + m)];
    dft8<true>(v);
    #pragma unroll
    for(int m = 0; m < 8; m++) L[skew(base + m)] = v[m];
    __syncthreads();
    base = (t >> 3) << 6; int j = t & 7;
    #pragma unroll
    for(int m = 0; m < 8; m++) v[m] = L[skew(base + j + 8*m)];
    #pragma unroll
    for(int m = 1; m < 8; m++) v[m] = cmulc(v[m], g_twtab[((j*m) << 3) & 511]);
    dft8<true>(v);
    #pragma unroll
    for(int m = 0; m < 8; m++) L[skew(base + j + 8*m)] = v[m];
    __syncthreads();
    #pragma unroll
    for(int m = 0; m < 8; m++) v[m] = L[skew(t + 64*m)];
    #pragma unroll
    for(int m = 1; m < 8; m++) v[m] = cmulc(v[m], g_twtab[(t*m) & 511]);
    dft8<true>(v);
    #pragma unroll
    for(int m = 0; m < 8; m++) L[skew(t + 64*m)] = v[m];
}

__global__ void k_twtab(){
    int k = blockIdx.x * blockDim.x + threadIdx.x;
    if(k < 1024){
        double a;
        if(k < 512) a = -6.283185307179586476925286766559 * (double)k / 512.0;
        else        a = -6.283185307179586476925286766559 * (double)(k - 512) / (double)NFFT;
        double s, c; sincos(a, &s, &c);
        g_twtab[k] = make_float2((float)c, (float)s);
    }
    if(k == 0){
        int cnt = 0;
        for(int p = 0; p < 512; p++){
            int k1 = rev9(p);
            int pp = rev9((512 - k1) & 511);
            if(p <= pp){ g_pairA[cnt] = p; g_pairB[cnt] = pp; cnt++; }
        }
    }
}

__global__ __launch_bounds__(256) void k_prep(
    const float* __restrict__ voice, const float* __restrict__ cpc,
    const float* __restrict__ amp,   const float* __restrict__ room,
    const float* __restrict__ mix,   const float* __restrict__ times,
    const float* __restrict__ cp_table)
{
    int n = blockIdx.x, tid = threadIdx.x;
    __shared__ float sv[256];
    __shared__ int   si[256];
    __shared__ int   s_cidx, s_cnt;

    float best = -1e30f; int bi = 0;
    for(int j = tid; j < NCP; j += 256){
        float v = cpc[n*NCP + j];
        if(v > best){ best = v; bi = j; }
    }
    sv[tid] = best; si[tid] = bi; __syncthreads();
    for(int s = 128; s > 0; s >>= 1){
        if(tid < s){
            if(sv[tid+s] > sv[tid] || (sv[tid+s] == sv[tid] && si[tid+s] < si[tid])){
                sv[tid] = sv[tid+s]; si[tid] = si[tid+s];
            }
        }
        __syncthreads();
    }
    if(tid == 0){
        s_cidx = si[0];
        float b = -1e30f; int ii = 0;
        for(int j = 0; j < NFR; j++){ float v = times[n*NFR + j]; if(v > b){ b = v; ii = j; } }
        g_shift[n] = ii * (NSAMP / NFR);
        b = -1e30f; ii = 0;
        for(int j = 0; j < NVO; j++){ float v = voice[n*NVO + j]; if(v > b){ b = v; ii = j; } }
        g_vidx[n] = ii;
        b = -1e30f; ii = 0;
        for(int j = 0; j < NVB; j++){ float v = room[n*NVB + j]; if(v > b){ b = v; ii = j; } }
        g_ridx[n] = ii;
        float x0 = mix[n*2], x1 = mix[n*2 + 1];
        float mm = fmaxf(x0, x1);
        float e0 = expf(x0 - mm), e1 = expf(x1 - mm);
        g_m0[n] = e0 / (e0 + e1);
        g_m1[n] = e1 / (e0 + e1);
        g_amp[n] = fabsf(amp[n]);
    }
    __syncthreads();

    const float* row = cp_table + (size_t)s_cidx * (NFR*CPD);
    float rv[8];
    #pragma unroll
    for(int j = 0; j < 8; j++) rv[j] = row[tid + 256*j];
    unsigned lo = 0u, hi = 0x7F800000u;
    while(hi - lo > 1u){
        unsigned mid = lo + ((hi - lo) >> 1);
        int c = 0;
        #pragma unroll
        for(int j = 0; j < 8; j++) c += (__float_as_uint(rv[j]) >= mid) ? 1 : 0;
        si[tid] = c; __syncthreads();
        for(int s = 128; s > 0; s >>= 1){
            if(tid < s) si[tid] += si[tid+s];
            __syncthreads();
        }
        if(tid == 0) s_cnt = si[0];
        __syncthreads();
        if(s_cnt >= KSP) lo = mid; else hi = mid;
    }
    for(int idx = tid; idx < NFR*CPD; idx += 256){
        int f = idx >> 4, c = idx & 15;
        float v = row[c*NFR + f];
        float keep = (__float_as_uint(v) >= lo) ? v : 0.f;
        g_ctrl[n*NFR*CPD + idx] = fmaxf(keep, 0.f);
    }
}

// M[v] = W_ih[v] @ W_in[v] — parallel Kahan-fp32 split-K
__global__ __launch_bounds__(128) void k_collapse(
    const float* __restrict__ w_ih, const float* __restrict__ w_in)
{
    int blk = blockIdx.x;
    int v = blk >> 7, i = blk & 127;
    int t = threadIdx.x;
    const float* wr = w_ih + ((size_t)v*HID + i) * WINL;
    const float* wc = w_in + (size_t)v*WINL*CPD;
    float s[CPD], comp[CPD];
    #pragma unroll
    for(int c = 0; c < CPD; c++){ s[c] = 0.f; comp[c] = 0.f; }
    for(int k = t; k < WINL; k += 128){
        float a = wr[k];
        const float4* p = (const float4*)(wc + (size_t)k*CPD);
        float4 q[4] = {p[0], p[1], p[2], p[3]};
        const float* qs = (const float*)q;
        #pragma unroll
        for(int c = 0; c < CPD; c++){
            float y = fmaf(a, qs[c], -comp[c]);
            float tt = s[c] + y;
            comp[c] = (tt - s[c]) - y;
            s[c] = tt;
        }
    }
    __shared__ float red[128 * CPD];
    #pragma unroll
    for(int c = 0; c < CPD; c++) red[t*CPD + c] = s[c];
    __syncthreads();
    for(int st = 64; st > 0; st >>= 1){
        if(t < st){
            #pragma unroll
            for(int c = 0; c < CPD; c++) red[t*CPD + c] += red[(t+st)*CPD + c];
        }
        __syncthreads();
    }
    if(t < CPD) g_M[(v*HID + i)*CPD + t] = red[t];
}

// persistent RNN: one block per event
__global__ __launch_bounds__(256) void k_rnn(const float* __restrict__ w_hh){
    int n = blockIdx.x, t = threadIdx.x;
    int i = t & 127, half = t >> 7;
    int v = g_vidx[n];
    __shared__ float ctrl_s[NFR*CPD];
    __shared__ float h_s[HID];
    __shared__ float part_s[256];

    float W[64];
    const float* wh = w_hh + ((size_t)v*HID + i) * HID + half*64;
    #pragma unroll
    for(int k = 0; k < 64; k++) W[k] = wh[k];
    float M[CPD];
    const float* mp = g_M + (v*HID + i)*CPD;
    #pragma unroll
    for(int c = 0; c < CPD; c++) M[c] = mp[c];
    for(int idx = t; idx < NFR*CPD; idx += 256) ctrl_s[idx] = g_ctrl[n*NFR*CPD + idx];
    if(t < HID) h_s[t] = 0.f;
    __syncthreads();

    float* hsout = g_hs + (size_t)n*NFR*HID;
    for(int f = 0; f < NFR; f++){
        const float* hb = h_s + half*64;
        float p0 = 0.f, p1 = 0.f, p2 = 0.f, p3 = 0.f;
        #pragma unroll
        for(int k = 0; k < 64; k += 4){
            p0 = fmaf(W[k],   hb[k],   p0);
            p1 = fmaf(W[k+1], hb[k+1], p1);
            p2 = fmaf(W[k+2], hb[k+2], p2);
            p3 = fmaf(W[k+3], hb[k+3], p3);
        }
        float inp = 0.f;
        if(half == 0){
            const float* cf = ctrl_s + f*CPD;
            float i0 = 0.f, i1 = 0.f;
            #pragma unroll
            for(int c = 0; c < CPD; c += 2){
                i0 = fmaf(M[c],   cf[c],   i0);
                i1 = fmaf(M[c+1], cf[c+1], i1);
            }
            inp = i0 + i1;
        }
        part_s[t] = (p0 + p1) + (p2 + p3);
        __syncthreads();
        if(half == 0){
            float h = tanhf(part_s[t] + part_s[t + 128] + inp);
            h_s[i] = h;
            hsout[f*HID + i] = h;
        }
        __syncthreads();
    }
}

// sig[f,w] = sin( hs[f,:] . w_out[v,w,:] ) — fp32 register-tiled GEMM
__global__ __launch_bounds__(256) void k_wout(const float* __restrict__ w_out){
    int wt = blockIdx.x, n = blockIdx.y, t = threadIdx.x;
    int v = g_vidx[n];
    const float* A  = g_hs + (size_t)n*NFR*HID;
    const float* Bm = w_out + (size_t)v*WINL*HID + (size_t)wt*128*HID;
    __shared__ float As[32*132];
    __shared__ float Bs[32*132];
    int tx = t & 15, ty = t >> 4;
    int f0 = ty*8, w0 = tx*8;
    float acc[8][8];
    #pragma unroll
    for(int i = 0; i < 8; i++)
        #pragma unroll
        for(int j = 0; j < 8; j++) acc[i][j] = 0.f;

    for(int ks = 0; ks < 4; ks++){
        int k0 = ks*32;
        #pragma unroll
        for(int r = 0; r < 4; r++){
            int idx4 = t + 256*r;
            int rr = idx4 >> 3, kk4 = idx4 & 7;
            float4 va = *(const float4*)(A  + (size_t)rr*HID + k0 + kk4*4);
            float4 vb = *(const float4*)(Bm + (size_t)rr*HID + k0 + kk4*4);
            As[(kk4*4+0)*132 + rr] = va.x; As[(kk4*4+1)*132 + rr] = va.y;
            As[(kk4*4+2)*132 + rr] = va.z; As[(kk4*4+3)*132 + rr] = va.w;
            Bs[(kk4*4+0)*132 + rr] = vb.x; Bs[(kk4*4+1)*132 + rr] = vb.y;
            Bs[(kk4*4+2)*132 + rr] = vb.z; Bs[(kk4*4+3)*132 + rr] = vb.w;
        }
        __syncthreads();
        #pragma unroll
        for(int k = 0; k < 32; k++){
            float4 a0 = *(const float4*)&As[k*132 + f0];
            float4 a1 = *(const float4*)&As[k*132 + f0 + 4];
            float4 b0 = *(const float4*)&Bs[k*132 + w0];
            float4 b1 = *(const float4*)&Bs[k*132 + w0 + 4];
            float a[8] = {a0.x,a0.y,a0.z,a0.w,a1.x,a1.y,a1.z,a1.w};
            float b[8] = {b0.x,b0.y,b0.z,b0.w,b1.x,b1.y,b1.z,b1.w};
            #pragma unroll
            for(int i = 0; i < 8; i++)
                #pragma unroll
                for(int j = 0; j < 8; j++) acc[i][j] += a[i]*b[j];
        }
        __syncthreads();
    }
    float* out = g_sig + (size_t)n*NSAMP + wt*128;
    #pragma unroll
    for(int i = 0; i < 8; i++)
        #pragma unroll
        for(int j = 0; j < 8; j++)
            out[(size_t)(f0+i)*WINL + w0 + j] = sinf(acc[i][j]);
}

// F1 column pass (forward). VERB=1: real verb -> g_vspec. VERB=0: packed pair of sigs -> g_spec.
template<int VERB>
__global__ __launch_bounds__(512) void k_col_fwd(const float* __restrict__ rin_ext){
    __shared__ float2 s[8*LSTR];
    int y = blockIdx.y, col0 = blockIdx.x*8, tid = threadIdx.x;
    const float* sa; const float* sb = nullptr; float2* dst;
    if(VERB){ sa = rin_ext + (size_t)y*NSAMP;        dst = g_vspec + (size_t)y*NFFT; }
    else    { sa = g_sig + (size_t)(2*y)*NSAMP; sb = g_sig + (size_t)(2*y+1)*NSAMP;
              dst = g_spec + (size_t)y*NFFT; }
    for(int idx = tid; idx < 4096; idx += 512){
        int r = idx >> 3, c = idx & 7;
        float re = 0.f, im = 0.f;
        if(r < 256){
            int o = r*512 + col0 + c;
            re = sa[o];
            if(!VERB) im = sb[o];
        }
        s[c*LSTR + skew(r)] = make_float2(re, im);
    }
    __syncthreads();
    dif512(&s[(tid >> 6)*LSTR], tid & 63);
    __syncthreads();
    for(int idx = tid; idx < 4096; idx += 512){
        int r = idx >> 3, c = idx & 7;
        int n2 = col0 + c;
        dst[(size_t)r*512 + n2] = cmul(s[c*LSTR + skew(r)], twN(rev9(r)*n2));
    }
}

// F2 row pass for verb spectra (store in scrambled (row,e) layout)
__global__ __launch_bounds__(512) void k_row_verb(){
    __shared__ float2 s[8*LSTR];
    int n = blockIdx.y, row0 = blockIdx.x*8, tid = threadIdx.x;
    float2* base = g_vspec + (size_t)n*NFFT + (size_t)row0*512;
    for(int idx = tid; idx < 4096; idx += 512){
        int r = idx >> 9, e = idx & 511;
        s[r*LSTR + skew(e)] = base[(size_t)r*512 + e];
    }
    __syncthreads();
    dif512(&s[(tid >> 6)*LSTR], tid & 63);
    __syncthreads();
    for(int idx = tid; idx < 4096; idx += 512){
        int r = idx >> 9, e = idx & 511;
        base[(size_t)r*512 + e] = s[r*LSTR + skew(e)];
    }
}

__device__ __forceinline__ int pzero(int e){   // partner col for the k1==0 row
    int k2 = rev9(e);
    return rev9((512 - k2) & 511);
}

// Fused: F2 + conj-unpack + spectral mul (verb+dry fold, 1/N) + repack + I1 + conj twiddle
__global__ __launch_bounds__(128) void k_rowpair(){
    __shared__ float2 s[2*LSTR];
    int slot = blockIdx.x, p = blockIdx.y;
    int rows0 = g_pairA[slot], rows1 = g_pairB[slot];
    int line = threadIdx.x >> 6, t = threadIdx.x & 63;
    float2* base = g_spec + (size_t)p*NFFT;
    for(int idx = threadIdx.x; idx < 1024; idx += 128){
        int l = idx >> 9, e = idx & 511;
        int row = l ? rows1 : rows0;
        s[l*LSTR + skew(e)] = base[(size_t)row*512 + e];
    }
    __syncthreads();
    dif512(&s[line*LSTR], t);
    __syncthreads();

    int na = 2*p, nb = 2*p + 1;
    const float2* va = g_vspec + (size_t)g_ridx[na]*NFFT;
    const float2* vb = g_vspec + (size_t)g_ridx[nb]*NFFT;
    float m0a = g_m0[na], m1a = g_m1[na], m0b = g_m0[nb], m1b = g_m1[nb];
    const float invN = 1.f / (float)NFFT;

    float2 Z[8], Zp[8];
    #pragma unroll
    for(int q = 0; q < 8; q++){
        int idx = threadIdx.x + 128*q;
        int l = idx >> 9, e = idx & 511;
        int row = l ? rows1 : rows0;
        int k1 = rev9(row);
        int ep = (k1 == 0) ? pzero(e) : (511 - e);
        Z[q]  = s[l*LSTR + skew(e)];
        Zp[q] = s[(1 - l)*LSTR + skew(ep)];
    }
    __syncthreads();
    #pragma unroll
    for(int q = 0; q < 8; q++){
        int idx = threadIdx.x + 128*q;
        int l = idx >> 9, e = idx & 511;
        int row = l ? rows1 : rows0;
        float2 S1 = make_float2(0.5f*(Z[q].x + Zp[q].x), 0.5f*(Z[q].y - Zp[q].y));
        float2 S2 = make_float2(0.5f*(Z[q].y + Zp[q].y), -0.5f*(Z[q].x - Zp[q].x));
        float2 V1 = va[(size_t)row*512 + e];
        float2 V2 = vb[(size_t)row*512 + e];
        float2 M1 = make_float2(m0a*V1.x + m1a, m0a*V1.y);
        float2 M2 = make_float2(m0b*V2.x + m1b, m0b*V2.y);
        float2 W1 = cmul(S1, M1), W2 = cmul(S2, M2);
        s[l*LSTR + skew(e)] = make_float2((W1.x - W2.y)*invN, (W1.y + W2.x)*invN);
    }
    __syncthreads();
    dit512(&s[line*LSTR], t);
    __syncthreads();
    for(int idx = threadIdx.x; idx < 1024; idx += 128){
        int l = idx >> 9, e = idx & 511;
        int row = l ? rows1 : rows0;
        int k1 = rev9(row);
        base[(size_t)row*512 + e] = cmulc(s[l*LSTR + skew(e)], twN(k1*e));
    }
}

// I2 column pass (inverse, packed) + epilogue: |amp| + dirac row-shift.
__global__ __launch_bounds__(512) void k_col_inv(float* __restrict__ out){
    __shared__ float2 s[8*LSTR];
    int p = blockIdx.y, col0 = blockIdx.x*8, tid = threadIdx.x;
    const float2* src = g_spec + (size_t)p*NFFT;
    for(int idx = tid; idx < 4096; idx += 512){
        int r = idx >> 3, c = idx & 7;
        s[c*LSTR + skew(r)] = src[(size_t)r*512 + col0 + c];
    }
    __syncthreads();
    dit512(&s[(tid >> 6)*LSTR], tid & 63);
    __syncthreads();
    int na = 2*p, nb = 2*p + 1;
    float aA = g_amp[na], aB = g_amp[nb];
    int dA = g_shift[na] >> 9, dB = g_shift[nb] >> 9;
    float* oA = out + (size_t)na*NSAMP;
    float* oB = out + (size_t)nb*NSAMP;
    for(int idx = tid; idx < 2048; idx += 512){
        int rp = idx >> 3, c = idx & 7;
        int col = col0 + c;
        int ra = rp - dA;
        oA[rp*512 + col] = (ra >= 0) ? s[c*LSTR + skew(ra)].x * aA : 0.f;
        int rb = rp - dB;
        oB[rp*512 + col] = (rb >= 0) ? s[c*LSTR + skew(rb)].y * aB : 0.f;
    }
}

extern "C" void kernel_launch(void* const* d_in, const int* in_sizes, int n_in,
                              void* d_out, int out_size) {
    const float* voice = (const float*)d_in[0];
    const float* cpc   = (const float*)d_in[1];
    const float* amp   = (const float*)d_in[2];
    const float* room  = (const float*)d_in[3];
    const float* mix   = (const float*)d_in[4];
    const float* times = (const float*)d_in[5];
    const float* cp_table = (const float*)d_in[6];
    const float* verbs = (const float*)d_in[7];
    const float* w_in  = (const float*)d_in[8];
    const float* w_ih  = (const float*)d_in[9];
    const float* w_hh  = (const float*)d_in[10];
    const float* w_out = (const float*)d_in[11];
    float* out = (float*)d_out;

    k_twtab<<<2, 512>>>();
    k_prep<<<NEV, 256>>>(voice, cpc, amp, room, mix, times, cp_table);
    k_collapse<<<NVO*HID, 128>>>(w_ih, w_in);
    k_rnn<<<NEV, 256>>>(w_hh);
    k_wout<<<dim3(8, NEV), 256>>>(w_out);
    k_col_fwd<1><<<dim3(64, NVB), 512>>>(verbs);
    k_row_verb<<<dim3(64, NVB), 512>>>();
    k_col_fwd<0><<<dim3(64, NPAIR), 512>>>(nullptr);
    k_rowpair<<<dim3(257, NPAIR), 128>>>();
    k_col_inv<<<dim3(64, NPAIR), 512>>>(out);
}

// round 9
// speedup vs baseline: 1.2742x; 1.0335x over previous
#include <cuda_runtime.h>
#include <math.h>

#define NEV   128
#define NPAIR 64
#define NSAMP 131072
#define NFFT  262144
#define NFR   128
#define WINL  1024
#define CPD   16
#define NCP   512
#define NVO   8
#define NVB   16
#define HID   128
#define KSP   128
#define LSTR  578

__device__ float2 g_twtab[1024];                     // [0:512) W512^k ; [512:1024) W_N^k
__device__ float2 g_spec[(size_t)NPAIR * NFFT];      // 128 MB packed spectra
__device__ float2 g_vspec[(size_t)NVB * NFFT];       // 32 MB verb spectra
__device__ float  g_sig[(size_t)NEV * NSAMP];
__device__ float  g_hs[(size_t)NEV * NFR * HID];
__device__ float  g_ctrl[NEV * NFR * CPD];
__device__ float  g_M[NVO * HID * CPD];
__device__ int    g_vidx[NEV], g_ridx[NEV], g_shift[NEV];
__device__ float  g_m0[NEV], g_m1[NEV], g_amp[NEV];
__device__ int    g_pairA[257], g_pairB[257];

__device__ __forceinline__ int skew(int i){ return i + (i >> 3); }
__device__ __forceinline__ float2 cadd(float2 a, float2 b){ return make_float2(a.x+b.x, a.y+b.y); }
__device__ __forceinline__ float2 csub(float2 a, float2 b){ return make_float2(a.x-b.x, a.y-b.y); }
__device__ __forceinline__ float2 cmul(float2 a, float2 b){ return make_float2(a.x*b.x - a.y*b.y, a.x*b.y + a.y*b.x); }
__device__ __forceinline__ float2 cmulc(float2 a, float2 b){ return make_float2(a.x*b.x + a.y*b.y, a.y*b.x - a.x*b.y); }
__device__ __forceinline__ int rev9(int p){ return ((p & 7) << 6) | (p & 56) | (p >> 6); }

__device__ __forceinline__ float2 twN(int idx){
    int k = idx & (NFFT - 1);
    return cmul(g_twtab[k >> 9], g_twtab[512 + (k & 511)]);
}

template<bool INV>
__device__ __forceinline__ float2 mulmi(float2 a){
    return INV ? make_float2(-a.y, a.x) : make_float2(a.y, -a.x);
}

template<bool INV>
__device__ __forceinline__ void dft8(float2* v){
    float2 t0 = cadd(v[0], v[4]), t1 = csub(v[0], v[4]);
    float2 t2 = cadd(v[2], v[6]), t3 = mulmi<INV>(csub(v[2], v[6]));
    float2 t4 = cadd(v[1], v[5]), t5 = csub(v[1], v[5]);
    float2 t6 = cadd(v[3], v[7]), t7 = mulmi<INV>(csub(v[3], v[7]));
    float2 a0 = cadd(t0, t2), a2 = csub(t0, t2);
    float2 a1 = cadd(t1, t3), a3 = csub(t1, t3);
    float2 b0 = cadd(t4, t6), b2 = csub(t4, t6);
    float2 b1 = cadd(t5, t7), b3 = csub(t5, t7);
    const float r = 0.70710678118654752440f;
    float2 w1 = INV ? make_float2(r,  r) : make_float2(r, -r);
    float2 w3 = INV ? make_float2(-r, r) : make_float2(-r, -r);
    b1 = cmul(b1, w1); b2 = mulmi<INV>(b2); b3 = cmul(b3, w3);
    v[0] = cadd(a0, b0); v[4] = csub(a0, b0);
    v[1] = cadd(a1, b1); v[5] = csub(a1, b1);
    v[2] = cadd(a2, b2); v[6] = csub(a2, b2);
    v[3] = cadd(a3, b3); v[7] = csub(a3, b3);
}

// DIF 512 = radix-8^3, natural in -> octal-digit-reversed out.
// ZTOP: input rows [256,512) are structural zeros (not staged in smem).
template<bool ZTOP>
__device__ __forceinline__ void dif512t(float2* L, int t){
    float2 v[8];
    if(ZTOP){
        #pragma unroll
        for(int m = 0; m < 4; m++) v[m] = L[skew(t + 64*m)];
        #pragma unroll
        for(int m = 4; m < 8; m++) v[m] = make_float2(0.f, 0.f);
    } else {
        #pragma unroll
        for(int m = 0; m < 8; m++) v[m] = L[skew(t + 64*m)];
    }
    dft8<false>(v);
    #pragma unroll
    for(int m = 1; m < 8; m++) v[m] = cmul(v[m], g_twtab[(t*m) & 511]);
    #pragma unroll
    for(int m = 0; m < 8; m++) L[skew(t + 64*m)] = v[m];
    __syncthreads();
    int base = (t >> 3) << 6, j = t & 7;
    #pragma unroll
    for(int m = 0; m < 8; m++) v[m] = L[skew(base + j + 8*m)];
    dft8<false>(v);
    #pragma unroll
    for(int m = 1; m < 8; m++) v[m] = cmul(v[m], g_twtab[((j*m) << 3) & 511]);
    #pragma unroll
    for(int m = 0; m < 8; m++) L[skew(base + j + 8*m)] = v[m];
    __syncthreads();
    base = t << 3;
    #pragma unroll
    for(int m = 0; m < 8; m++) v[m] = L[skew(base + m)];
    dft8<false>(v);
    #pragma unroll
    for(int m = 0; m < 8; m++) L[skew(base + m)] = v[m];
}

// DIT 512: digit-reversed in -> natural out, conjugate twiddles (unscaled inverse).
__device__ __forceinline__ void dit512(float2* L, int t){
    float2 v[8];
    int base = t << 3;
    #pragma unroll
    for(int m = 0; m < 8; m++) v[m] = L[skew(base + m)];
    dft8<true>(v);
    #pragma unroll
    for(int m = 0; m < 8; m++) L[skew(base + m)] = v[m];
    __syncthreads();
    base = (t >> 3) << 6; int j = t & 7;
    #pragma unroll
    for(int m = 0; m < 8; m++) v[m] = L[skew(base + j + 8*m)];
    #pragma unroll
    for(int m = 1; m < 8; m++) v[m] = cmulc(v[m], g_twtab[((j*m) << 3) & 511]);
    dft8<true>(v);
    #pragma unroll
    for(int m = 0; m < 8; m++) L[skew(base + j + 8*m)] = v[m];
    __syncthreads();
    #pragma unroll
    for(int m = 0; m < 8; m++) v[m] = L[skew(t + 64*m)];
    #pragma unroll
    for(int m = 1; m < 8; m++) v[m] = cmulc(v[m], g_twtab[(t*m) & 511]);
    dft8<true>(v);
    #pragma unroll
    for(int m = 0; m < 8; m++) L[skew(t + 64*m)] = v[m];
}

__global__ void k_twtab(){
    int k = blockIdx.x * blockDim.x + threadIdx.x;
    if(k < 1024){
        double a;
        if(k < 512) a = -6.283185307179586476925286766559 * (double)k / 512.0;
        else        a = -6.283185307179586476925286766559 * (double)(k - 512) / (double)NFFT;
        double s, c; sincos(a, &s, &c);
        g_twtab[k] = make_float2((float)c, (float)s);
    }
    if(k == 0){
        int cnt = 0;
        for(int p = 0; p < 512; p++){
            int k1 = rev9(p);
            int pp = rev9((512 - k1) & 511);
            if(p <= pp){ g_pairA[cnt] = p; g_pairB[cnt] = pp; cnt++; }
        }
    }
}

__global__ __launch_bounds__(256) void k_prep(
    const float* __restrict__ voice, const float* __restrict__ cpc,
    const float* __restrict__ amp,   const float* __restrict__ room,
    const float* __restrict__ mix,   const float* __restrict__ times,
    const float* __restrict__ cp_table)
{
    int n = blockIdx.x, tid = threadIdx.x;
    __shared__ float sv[256];
    __shared__ int   si[256];
    __shared__ int   s_cidx, s_cnt;

    float best = -1e30f; int bi = 0;
    for(int j = tid; j < NCP; j += 256){
        float v = cpc[n*NCP + j];
        if(v > best){ best = v; bi = j; }
    }
    sv[tid] = best; si[tid] = bi; __syncthreads();
    for(int s = 128; s > 0; s >>= 1){
        if(tid < s){
            if(sv[tid+s] > sv[tid] || (sv[tid+s] == sv[tid] && si[tid+s] < si[tid])){
                sv[tid] = sv[tid+s]; si[tid] = si[tid+s];
            }
        }
        __syncthreads();
    }
    if(tid == 0){
        s_cidx = si[0];
        float b = -1e30f; int ii = 0;
        for(int j = 0; j < NFR; j++){ float v = times[n*NFR + j]; if(v > b){ b = v; ii = j; } }
        g_shift[n] = ii * (NSAMP / NFR);
        b = -1e30f; ii = 0;
        for(int j = 0; j < NVO; j++){ float v = voice[n*NVO + j]; if(v > b){ b = v; ii = j; } }
        g_vidx[n] = ii;
        b = -1e30f; ii = 0;
        for(int j = 0; j < NVB; j++){ float v = room[n*NVB + j]; if(v > b){ b = v; ii = j; } }
        g_ridx[n] = ii;
        float x0 = mix[n*2], x1 = mix[n*2 + 1];
        float mm = fmaxf(x0, x1);
        float e0 = expf(x0 - mm), e1 = expf(x1 - mm);
        g_m0[n] = e0 / (e0 + e1);
        g_m1[n] = e1 / (e0 + e1);
        g_amp[n] = fabsf(amp[n]);
    }
    __syncthreads();

    const float* row = cp_table + (size_t)s_cidx * (NFR*CPD);
    float rv[8];
    #pragma unroll
    for(int j = 0; j < 8; j++) rv[j] = row[tid + 256*j];
    unsigned lo = 0u, hi = 0x7F800000u;
    while(hi - lo > 1u){
        unsigned mid = lo + ((hi - lo) >> 1);
        int c = 0;
        #pragma unroll
        for(int j = 0; j < 8; j++) c += (__float_as_uint(rv[j]) >= mid) ? 1 : 0;
        si[tid] = c; __syncthreads();
        for(int s = 128; s > 0; s >>= 1){
            if(tid < s) si[tid] += si[tid+s];
            __syncthreads();
        }
        if(tid == 0) s_cnt = si[0];
        __syncthreads();
        if(s_cnt >= KSP) lo = mid; else hi = mid;
    }
    for(int idx = tid; idx < NFR*CPD; idx += 256){
        int f = idx >> 4, c = idx & 15;
        float v = row[c*NFR + f];
        float keep = (__float_as_uint(v) >= lo) ? v : 0.f;
        g_ctrl[n*NFR*CPD + idx] = fmaxf(keep, 0.f);
    }
}

// M[v] = W_ih[v] @ W_in[v] — parallel Kahan-fp32 split-K
__global__ __launch_bounds__(128) void k_collapse(
    const float* __restrict__ w_ih, const float* __restrict__ w_in)
{
    int blk = blockIdx.x;
    int v = blk >> 7, i = blk & 127;
    int t = threadIdx.x;
    const float* wr = w_ih + ((size_t)v*HID + i) * WINL;
    const float* wc = w_in + (size_t)v*WINL*CPD;
    float s[CPD], comp[CPD];
    #pragma unroll
    for(int c = 0; c < CPD; c++){ s[c] = 0.f; comp[c] = 0.f; }
    for(int k = t; k < WINL; k += 128){
        float a = wr[k];
        const float4* p = (const float4*)(wc + (size_t)k*CPD);
        float4 q[4] = {p[0], p[1], p[2], p[3]};
        const float* qs = (const float*)q;
        #pragma unroll
        for(int c = 0; c < CPD; c++){
            float y = fmaf(a, qs[c], -comp[c]);
            float tt = s[c] + y;
            comp[c] = (tt - s[c]) - y;
            s[c] = tt;
        }
    }
    __shared__ float red[128 * CPD];
    #pragma unroll
    for(int c = 0; c < CPD; c++) red[t*CPD + c] = s[c];
    __syncthreads();
    for(int st = 64; st > 0; st >>= 1){
        if(t < st){
            #pragma unroll
            for(int c = 0; c < CPD; c++) red[t*CPD + c] += red[(t+st)*CPD + c];
        }
        __syncthreads();
    }
    if(t < CPD) g_M[(v*HID + i)*CPD + t] = red[t];
}

// persistent RNN: one block per event
__global__ __launch_bounds__(256) void k_rnn(const float* __restrict__ w_hh){
    int n = blockIdx.x, t = threadIdx.x;
    int i = t & 127, half = t >> 7;
    int v = g_vidx[n];
    __shared__ float ctrl_s[NFR*CPD];
    __shared__ float h_s[HID];
    __shared__ float part_s[256];

    float W[64];
    const float* wh = w_hh + ((size_t)v*HID + i) * HID + half*64;
    #pragma unroll
    for(int k = 0; k < 64; k++) W[k] = wh[k];
    float M[CPD];
    const float* mp = g_M + (v*HID + i)*CPD;
    #pragma unroll
    for(int c = 0; c < CPD; c++) M[c] = mp[c];
    for(int idx = t; idx < NFR*CPD; idx += 256) ctrl_s[idx] = g_ctrl[n*NFR*CPD + idx];
    if(t < HID) h_s[t] = 0.f;
    __syncthreads();

    float* hsout = g_hs + (size_t)n*NFR*HID;
    for(int f = 0; f < NFR; f++){
        const float* hb = h_s + half*64;
        float p0 = 0.f, p1 = 0.f, p2 = 0.f, p3 = 0.f;
        #pragma unroll
        for(int k = 0; k < 64; k += 4){
            p0 = fmaf(W[k],   hb[k],   p0);
            p1 = fmaf(W[k+1], hb[k+1], p1);
            p2 = fmaf(W[k+2], hb[k+2], p2);
            p3 = fmaf(W[k+3], hb[k+3], p3);
        }
        float inp = 0.f;
        if(half == 0){
            const float* cf = ctrl_s + f*CPD;
            float i0 = 0.f, i1 = 0.f;
            #pragma unroll
            for(int c = 0; c < CPD; c += 2){
                i0 = fmaf(M[c],   cf[c],   i0);
                i1 = fmaf(M[c+1], cf[c+1], i1);
            }
            inp = i0 + i1;
        }
        part_s[t] = (p0 + p1) + (p2 + p3);
        __syncthreads();
        if(half == 0){
            float h = tanhf(part_s[t] + part_s[t + 128] + inp);
            h_s[i] = h;
            hsout[f*HID + i] = h;
        }
        __syncthreads();
    }
}

// sig[f,w] = sin( hs[f,:] . w_out[v,w,:] ) — fp32 register-tiled GEMM, fast-sin epilogue
__global__ __launch_bounds__(256) void k_wout(const float* __restrict__ w_out){
    int wt = blockIdx.x, n = blockIdx.y, t = threadIdx.x;
    int v = g_vidx[n];
    const float* A  = g_hs + (size_t)n*NFR*HID;
    const float* Bm = w_out + (size_t)v*WINL*HID + (size_t)wt*128*HID;
    __shared__ float As[32*132];
    __shared__ float Bs[32*132];
    int tx = t & 15, ty = t >> 4;
    int f0 = ty*8, w0 = tx*8;
    float acc[8][8];
    #pragma unroll
    for(int i = 0; i < 8; i++)
        #pragma unroll
        for(int j = 0; j < 8; j++) acc[i][j] = 0.f;

    for(int ks = 0; ks < 4; ks++){
        int k0 = ks*32;
        #pragma unroll
        for(int r = 0; r < 4; r++){
            int idx4 = t + 256*r;
            int rr = idx4 >> 3, kk4 = idx4 & 7;
            float4 va = *(const float4*)(A  + (size_t)rr*HID + k0 + kk4*4);
            float4 vb = *(const float4*)(Bm + (size_t)rr*HID + k0 + kk4*4);
            As[(kk4*4+0)*132 + rr] = va.x; As[(kk4*4+1)*132 + rr] = va.y;
            As[(kk4*4+2)*132 + rr] = va.z; As[(kk4*4+3)*132 + rr] = va.w;
            Bs[(kk4*4+0)*132 + rr] = vb.x; Bs[(kk4*4+1)*132 + rr] = vb.y;
            Bs[(kk4*4+2)*132 + rr] = vb.z; Bs[(kk4*4+3)*132 + rr] = vb.w;
        }
        __syncthreads();
        #pragma unroll
        for(int k = 0; k < 32; k++){
            float4 a0 = *(const float4*)&As[k*132 + f0];
            float4 a1 = *(const float4*)&As[k*132 + f0 + 4];
            float4 b0 = *(const float4*)&Bs[k*132 + w0];
            float4 b1 = *(const float4*)&Bs[k*132 + w0 + 4];
            float a[8] = {a0.x,a0.y,a0.z,a0.w,a1.x,a1.y,a1.z,a1.w};
            float b[8] = {b0.x,b0.y,b0.z,b0.w,b1.x,b1.y,b1.z,b1.w};
            #pragma unroll
            for(int i = 0; i < 8; i++)
                #pragma unroll
                for(int j = 0; j < 8; j++) acc[i][j] += a[i]*b[j];
        }
        __syncthreads();
    }
    float* out = g_sig + (size_t)n*NSAMP + wt*128;
    #pragma unroll
    for(int i = 0; i < 8; i++)
        #pragma unroll
        for(int j = 0; j < 8; j++)
            out[(size_t)(f0+i)*WINL + w0 + j] = __sinf(acc[i][j]);
}

// F1 column pass (forward). VERB=1: real verb -> g_vspec. VERB=0: packed pair of sigs -> g_spec.
// Upper 256 rows are structural zeros: not staged, pruned in dif512t<true>.
template<int VERB>
__global__ __launch_bounds__(512) void k_col_fwd(const float* __restrict__ rin_ext){
    __shared__ float2 s[8*LSTR];
    int y = blockIdx.y, col0 = blockIdx.x*8, tid = threadIdx.x;
    const float* sa; const float* sb = nullptr; float2* dst;
    if(VERB){ sa = rin_ext + (size_t)y*NSAMP;        dst = g_vspec + (size_t)y*NFFT; }
    else    { sa = g_sig + (size_t)(2*y)*NSAMP; sb = g_sig + (size_t)(2*y+1)*NSAMP;
              dst = g_spec + (size_t)y*NFFT; }
    for(int idx = tid; idx < 2048; idx += 512){
        int r = idx >> 3, c = idx & 7;
        int o = r*512 + col0 + c;
        float re = sa[o];
        float im = VERB ? 0.f : sb[o];
        s[c*LSTR + skew(r)] = make_float2(re, im);
    }
    __syncthreads();
    dif512t<true>(&s[(tid >> 6)*LSTR], tid & 63);
    __syncthreads();
    for(int idx = tid; idx < 4096; idx += 512){
        int r = idx >> 3, c = idx & 7;
        int n2 = col0 + c;
        dst[(size_t)r*512 + n2] = cmul(s[c*LSTR + skew(r)], twN(rev9(r)*n2));
    }
}

// F2 row pass for verb spectra (store in scrambled (row,e) layout)
__global__ __launch_bounds__(512) void k_row_verb(){
    __shared__ float2 s[8*LSTR];
    int n = blockIdx.y, row0 = blockIdx.x*8, tid = threadIdx.x;
    float2* base = g_vspec + (size_t)n*NFFT + (size_t)row0*512;
    for(int idx = tid; idx < 4096; idx += 512){
        int r = idx >> 9, e = idx & 511;
        s[r*LSTR + skew(e)] = base[(size_t)r*512 + e];
    }
    __syncthreads();
    dif512t<false>(&s[(tid >> 6)*LSTR], tid & 63);
    __syncthreads();
    for(int idx = tid; idx < 4096; idx += 512){
        int r = idx >> 9, e = idx & 511;
        base[(size_t)r*512 + e] = s[r*LSTR + skew(e)];
    }
}

__device__ __forceinline__ int pzero(int e){   // partner col for the k1==0 row
    int k2 = rev9(e);
    return rev9((512 - k2) & 511);
}

// Fused: F2 + conj-unpack + spectral mul (verb+dry fold, 1/N) + repack + I1 + conj twiddle.
// 256 threads = 2 pair-slots per block. Slot >256 clamps to 256 (idempotent duplicate).
__global__ __launch_bounds__(256) void k_rowpair(){
    __shared__ float2 s[4*LSTR];
    int p = blockIdx.y;
    int grp = threadIdx.x >> 7;
    int lt  = threadIdx.x & 127;
    int slot = blockIdx.x*2 + grp; if(slot > 256) slot = 256;
    int rows0 = g_pairA[slot], rows1 = g_pairB[slot];
    int line = lt >> 6, t = lt & 63;
    float2* base = g_spec + (size_t)p*NFFT;
    float2* sg = s + (2*grp)*LSTR;
    for(int idx = lt; idx < 1024; idx += 128){
        int l = idx >> 9, e = idx & 511;
        int row = l ? rows1 : rows0;
        sg[l*LSTR + skew(e)] = base[(size_t)row*512 + e];
    }
    __syncthreads();
    dif512t<false>(&sg[line*LSTR], t);
    __syncthreads();

    int na = 2*p, nb = 2*p + 1;
    const float2* va = g_vspec + (size_t)g_ridx[na]*NFFT;
    const float2* vb = g_vspec + (size_t)g_ridx[nb]*NFFT;
    float m0a = g_m0[na], m1a = g_m1[na], m0b = g_m0[nb], m1b = g_m1[nb];
    const float invN = 1.f / (float)NFFT;

    float2 Z[8], Zp[8];
    #pragma unroll
    for(int q = 0; q < 8; q++){
        int idx = lt + 128*q;
        int l = idx >> 9, e = idx & 511;
        int row = l ? rows1 : rows0;
        int k1 = rev9(row);
        int ep = (k1 == 0) ? pzero(e) : (511 - e);
        Z[q]  = sg[l*LSTR + skew(e)];
        Zp[q] = sg[(1 - l)*LSTR + skew(ep)];
    }
    __syncthreads();
    #pragma unroll
    for(int q = 0; q < 8; q++){
        int idx = lt + 128*q;
        int l = idx >> 9, e = idx & 511;
        int row = l ? rows1 : rows0;
        float2 S1 = make_float2(0.5f*(Z[q].x + Zp[q].x), 0.5f*(Z[q].y - Zp[q].y));
        float2 S2 = make_float2(0.5f*(Z[q].y + Zp[q].y), -0.5f*(Z[q].x - Zp[q].x));
        float2 V1 = va[(size_t)row*512 + e];
        float2 V2 = vb[(size_t)row*512 + e];
        float2 M1 = make_float2(m0a*V1.x + m1a, m0a*V1.y);
        float2 M2 = make_float2(m0b*V2.x + m1b, m0b*V2.y);
        float2 W1 = cmul(S1, M1), W2 = cmul(S2, M2);
        sg[l*LSTR + skew(e)] = make_float2((W1.x - W2.y)*invN, (W1.y + W2.x)*invN);
    }
    __syncthreads();
    dit512(&sg[line*LSTR], t);
    __syncthreads();
    for(int idx = lt; idx < 1024; idx += 128){
        int l = idx >> 9, e = idx & 511;
        int row = l ? rows1 : rows0;
        int k1 = rev9(row);
        base[(size_t)row*512 + e] = cmulc(sg[l*LSTR + skew(e)], twN(k1*e));
    }
}

// I2 column pass (inverse, packed) + epilogue: |amp| + dirac row-shift.
__global__ __launch_bounds__(512) void k_col_inv(float* __restrict__ out){
    __shared__ float2 s[8*LSTR];
    int p = blockIdx.y, col0 = blockIdx.x*8, tid = threadIdx.x;
    const float2* src = g_spec + (size_t)p*NFFT;
    for(int idx = tid; idx < 4096; idx += 512){
        int r = idx >> 3, c = idx & 7;
        s[c*LSTR + skew(r)] = src[(size_t)r*512 + col0 + c];
    }
    __syncthreads();
    dit512(&s[(tid >> 6)*LSTR], tid & 63);
    __syncthreads();
    int na = 2*p, nb = 2*p + 1;
    float aA = g_amp[na], aB = g_amp[nb];
    int dA = g_shift[na] >> 9, dB = g_shift[nb] >> 9;
    float* oA = out + (size_t)na*NSAMP;
    float* oB = out + (size_t)nb*NSAMP;
    for(int idx = tid; idx < 2048; idx += 512){
        int rp = idx >> 3, c = idx & 7;
        int col = col0 + c;
        int ra = rp - dA;
        oA[rp*512 + col] = (ra >= 0) ? s[c*LSTR + skew(ra)].x * aA : 0.f;
        int rb = rp - dB;
        oB[rp*512 + col] = (rb >= 0) ? s[c*LSTR + skew(rb)].y * aB : 0.f;
    }
}

extern "C" void kernel_launch(void* const* d_in, const int* in_sizes, int n_in,
                              void* d_out, int out_size) {
    const float* voice = (const float*)d_in[0];
    const float* cpc   = (const float*)d_in[1];
    const float* amp   = (const float*)d_in[2];
    const float* room  = (const float*)d_in[3];
    const float* mix   = (const float*)d_in[4];
    const float* times = (const float*)d_in[5];
    const float* cp_table = (const float*)d_in[6];
    const float* verbs = (const float*)d_in[7];
    const float* w_in  = (const float*)d_in[8];
    const float* w_ih  = (const float*)d_in[9];
    const float* w_hh  = (const float*)d_in[10];
    const float* w_out = (const float*)d_in[11];
    float* out = (float*)d_out;

    k_twtab<<<2, 512>>>();
    k_prep<<<NEV, 256>>>(voice, cpc, amp, room, mix, times, cp_table);
    k_collapse<<<NVO*HID, 128>>>(w_ih, w_in);
    k_rnn<<<NEV, 256>>>(w_hh);
    k_wout<<<dim3(8, NEV), 256>>>(w_out);
    k_col_fwd<1><<<dim3(64, NVB), 512>>>(verbs);
    k_row_verb<<<dim3(64, NVB), 512>>>();
    k_col_fwd<0><<<dim3(64, NPAIR), 512>>>(nullptr);
    k_rowpair<<<dim3(129, NPAIR), 256>>>();
    k_col_inv<<<dim3(64, NPAIR), 512>>>(out);
}

// round 10
// speedup vs baseline: 1.3283x; 1.0425x over previous
#include <cuda_runtime.h>
#include <math.h>

#define NEV   128
#define NPAIR 64
#define NSAMP 131072
#define NFFT  262144
#define NFR   128
#define WINL  1024
#define CPD   16
#define NCP   512
#define NVO   8
#define NVB   16
#define HID   128
#define KSP   128
#define LSTR  578

__device__ float2 g_twtab[1024];                     // [0:512) W512^k ; [512:1024) W_N^k
__device__ float2 g_spec[(size_t)NPAIR * NFFT];      // 128 MB packed spectra
__device__ float2 g_vspec[(size_t)NVB * NFFT];       // 32 MB verb spectra
__device__ float  g_sig[(size_t)NEV * NSAMP];
__device__ float  g_hs[(size_t)NEV * NFR * HID];
__device__ float  g_ctrl[NEV * NFR * CPD];
__device__ float  g_M[NVO * HID * CPD];
__device__ int    g_vidx[NEV], g_ridx[NEV], g_shift[NEV];
__device__ float  g_m0[NEV], g_m1[NEV], g_amp[NEV];
__device__ int    g_pairA[257], g_pairB[257];

__device__ __forceinline__ int skew(int i){ return i + (i >> 3); }
__device__ __forceinline__ float2 cadd(float2 a, float2 b){ return make_float2(a.x+b.x, a.y+b.y); }
__device__ __forceinline__ float2 csub(float2 a, float2 b){ return make_float2(a.x-b.x, a.y-b.y); }
__device__ __forceinline__ float2 cmul(float2 a, float2 b){ return make_float2(a.x*b.x - a.y*b.y, a.x*b.y + a.y*b.x); }
__device__ __forceinline__ float2 cmulc(float2 a, float2 b){ return make_float2(a.x*b.x + a.y*b.y, a.y*b.x - a.x*b.y); }
__device__ __forceinline__ int rev9(int p){ return ((p & 7) << 6) | (p & 56) | (p >> 6); }

__device__ __forceinline__ float2 twN(int idx){
    int k = idx & (NFFT - 1);
    return cmul(g_twtab[k >> 9], g_twtab[512 + (k & 511)]);
}

template<bool INV>
__device__ __forceinline__ float2 mulmi(float2 a){
    return INV ? make_float2(-a.y, a.x) : make_float2(a.y, -a.x);
}

template<bool INV>
__device__ __forceinline__ void dft8(float2* v){
    float2 t0 = cadd(v[0], v[4]), t1 = csub(v[0], v[4]);
    float2 t2 = cadd(v[2], v[6]), t3 = mulmi<INV>(csub(v[2], v[6]));
    float2 t4 = cadd(v[1], v[5]), t5 = csub(v[1], v[5]);
    float2 t6 = cadd(v[3], v[7]), t7 = mulmi<INV>(csub(v[3], v[7]));
    float2 a0 = cadd(t0, t2), a2 = csub(t0, t2);
    float2 a1 = cadd(t1, t3), a3 = csub(t1, t3);
    float2 b0 = cadd(t4, t6), b2 = csub(t4, t6);
    float2 b1 = cadd(t5, t7), b3 = csub(t5, t7);
    const float r = 0.70710678118654752440f;
    float2 w1 = INV ? make_float2(r,  r) : make_float2(r, -r);
    float2 w3 = INV ? make_float2(-r, r) : make_float2(-r, -r);
    b1 = cmul(b1, w1); b2 = mulmi<INV>(b2); b3 = cmul(b3, w3);
    v[0] = cadd(a0, b0); v[4] = csub(a0, b0);
    v[1] = cadd(a1, b1); v[5] = csub(a1, b1);
    v[2] = cadd(a2, b2); v[6] = csub(a2, b2);
    v[3] = cadd(a3, b3); v[7] = csub(a3, b3);
}

// DIF 512 = radix-8^3, natural in -> octal-digit-reversed out.
// ZTOP: input rows [256,512) are structural zeros (not staged in smem).
template<bool ZTOP>
__device__ __forceinline__ void dif512t(float2* L, int t){
    float2 v[8];
    if(ZTOP){
        #pragma unroll
        for(int m = 0; m < 4; m++) v[m] = L[skew(t + 64*m)];
        #pragma unroll
        for(int m = 4; m < 8; m++) v[m] = make_float2(0.f, 0.f);
    } else {
        #pragma unroll
        for(int m = 0; m < 8; m++) v[m] = L[skew(t + 64*m)];
    }
    dft8<false>(v);
    #pragma unroll
    for(int m = 1; m < 8; m++) v[m] = cmul(v[m], g_twtab[(t*m) & 511]);
    #pragma unroll
    for(int m = 0; m < 8; m++) L[skew(t + 64*m)] = v[m];
    __syncthreads();
    int base = (t >> 3) << 6, j = t & 7;
    #pragma unroll
    for(int m = 0; m < 8; m++) v[m] = L[skew(base + j + 8*m)];
    dft8<false>(v);
    #pragma unroll
    for(int m = 1; m < 8; m++) v[m] = cmul(v[m], g_twtab[((j*m) << 3) & 511]);
    #pragma unroll
    for(int m = 0; m < 8; m++) L[skew(base + j + 8*m)] = v[m];
    __syncthreads();
    base = t << 3;
    #pragma unroll
    for(int m = 0; m < 8; m++) v[m] = L[skew(base + m)];
    dft8<false>(v);
    #pragma unroll
    for(int m = 0; m < 8; m++) L[skew(base + m)] = v[m];
}

// DIT 512: digit-reversed in -> natural out, conjugate twiddles (unscaled inverse).
__device__ __forceinline__ void dit512(float2* L, int t){
    float2 v[8];
    int base = t << 3;
    #pragma unroll
    for(int m = 0; m < 8; m++) v[m] = L[skew(base + m)];
    dft8<true>(v);
    #pragma unroll
    for(int m = 0; m < 8; m++) L[skew(base + m)] = v[m];
    __syncthreads();
    base = (t >> 3) << 6; int j = t & 7;
    #pragma unroll
    for(int m = 0; m < 8; m++) v[m] = L[skew(base + j + 8*m)];
    #pragma unroll
    for(int m = 1; m < 8; m++) v[m] = cmulc(v[m], g_twtab[((j*m) << 3) & 511]);
    dft8<true>(v);
    #pragma unroll
    for(int m = 0; m < 8; m++) L[skew(base + j + 8*m)] = v[m];
    __syncthreads();
    #pragma unroll
    for(int m = 0; m < 8; m++) v[m] = L[skew(t + 64*m)];
    #pragma unroll
    for(int m = 1; m < 8; m++) v[m] = cmulc(v[m], g_twtab[(t*m) & 511]);
    dft8<true>(v);
    #pragma unroll
    for(int m = 0; m < 8; m++) L[skew(t + 64*m)] = v[m];
}

__global__ void k_twtab(){
    int k = blockIdx.x * blockDim.x + threadIdx.x;
    if(k < 1024){
        double a;
        if(k < 512) a = -6.283185307179586476925286766559 * (double)k / 512.0;
        else        a = -6.283185307179586476925286766559 * (double)(k - 512) / (double)NFFT;
        double s, c; sincos(a, &s, &c);
        g_twtab[k] = make_float2((float)c, (float)s);
    }
    if(k == 0){
        int cnt = 0;
        for(int p = 0; p < 512; p++){
            int k1 = rev9(p);
            int pp = rev9((512 - k1) & 511);
            if(p <= pp){ g_pairA[cnt] = p; g_pairB[cnt] = pp; cnt++; }
        }
    }
}

__global__ __launch_bounds__(256) void k_prep(
    const float* __restrict__ voice, const float* __restrict__ cpc,
    const float* __restrict__ amp,   const float* __restrict__ room,
    const float* __restrict__ mix,   const float* __restrict__ times,
    const float* __restrict__ cp_table)
{
    int n = blockIdx.x, tid = threadIdx.x;
    __shared__ float sv[256];
    __shared__ int   si[256];
    __shared__ int   s_cidx, s_cnt;

    float best = -1e30f; int bi = 0;
    for(int j = tid; j < NCP; j += 256){
        float v = cpc[n*NCP + j];
        if(v > best){ best = v; bi = j; }
    }
    sv[tid] = best; si[tid] = bi; __syncthreads();
    for(int s = 128; s > 0; s >>= 1){
        if(tid < s){
            if(sv[tid+s] > sv[tid] || (sv[tid+s] == sv[tid] && si[tid+s] < si[tid])){
                sv[tid] = sv[tid+s]; si[tid] = si[tid+s];
            }
        }
        __syncthreads();
    }
    if(tid == 0){
        s_cidx = si[0];
        float b = -1e30f; int ii = 0;
        for(int j = 0; j < NFR; j++){ float v = times[n*NFR + j]; if(v > b){ b = v; ii = j; } }
        g_shift[n] = ii * (NSAMP / NFR);
        b = -1e30f; ii = 0;
        for(int j = 0; j < NVO; j++){ float v = voice[n*NVO + j]; if(v > b){ b = v; ii = j; } }
        g_vidx[n] = ii;
        b = -1e30f; ii = 0;
        for(int j = 0; j < NVB; j++){ float v = room[n*NVB + j]; if(v > b){ b = v; ii = j; } }
        g_ridx[n] = ii;
        float x0 = mix[n*2], x1 = mix[n*2 + 1];
        float mm = fmaxf(x0, x1);
        float e0 = expf(x0 - mm), e1 = expf(x1 - mm);
        g_m0[n] = e0 / (e0 + e1);
        g_m1[n] = e1 / (e0 + e1);
        g_amp[n] = fabsf(amp[n]);
    }
    __syncthreads();

    const float* row = cp_table + (size_t)s_cidx * (NFR*CPD);
    float rv[8];
    #pragma unroll
    for(int j = 0; j < 8; j++) rv[j] = row[tid + 256*j];
    unsigned lo = 0u, hi = 0x7F800000u;
    while(hi - lo > 1u){
        unsigned mid = lo + ((hi - lo) >> 1);
        int c = 0;
        #pragma unroll
        for(int j = 0; j < 8; j++) c += (__float_as_uint(rv[j]) >= mid) ? 1 : 0;
        si[tid] = c; __syncthreads();
        for(int s = 128; s > 0; s >>= 1){
            if(tid < s) si[tid] += si[tid+s];
            __syncthreads();
        }
        if(tid == 0) s_cnt = si[0];
        __syncthreads();
        if(s_cnt >= KSP) lo = mid; else hi = mid;
    }
    for(int idx = tid; idx < NFR*CPD; idx += 256){
        int f = idx >> 4, c = idx & 15;
        float v = row[c*NFR + f];
        float keep = (__float_as_uint(v) >= lo) ? v : 0.f;
        g_ctrl[n*NFR*CPD + idx] = fmaxf(keep, 0.f);
    }
}

// M[v] = W_ih[v] @ W_in[v] — parallel Kahan-fp32 split-K
__global__ __launch_bounds__(128) void k_collapse(
    const float* __restrict__ w_ih, const float* __restrict__ w_in)
{
    int blk = blockIdx.x;
    int v = blk >> 7, i = blk & 127;
    int t = threadIdx.x;
    const float* wr = w_ih + ((size_t)v*HID + i) * WINL;
    const float* wc = w_in + (size_t)v*WINL*CPD;
    float s[CPD], comp[CPD];
    #pragma unroll
    for(int c = 0; c < CPD; c++){ s[c] = 0.f; comp[c] = 0.f; }
    for(int k = t; k < WINL; k += 128){
        float a = wr[k];
        const float4* p = (const float4*)(wc + (size_t)k*CPD);
        float4 q[4] = {p[0], p[1], p[2], p[3]};
        const float* qs = (const float*)q;
        #pragma unroll
        for(int c = 0; c < CPD; c++){
            float y = fmaf(a, qs[c], -comp[c]);
            float tt = s[c] + y;
            comp[c] = (tt - s[c]) - y;
            s[c] = tt;
        }
    }
    __shared__ float red[128 * CPD];
    #pragma unroll
    for(int c = 0; c < CPD; c++) red[t*CPD + c] = s[c];
    __syncthreads();
    for(int st = 64; st > 0; st >>= 1){
        if(t < st){
            #pragma unroll
            for(int c = 0; c < CPD; c++) red[t*CPD + c] += red[(t+st)*CPD + c];
        }
        __syncthreads();
    }
    if(t < CPD) g_M[(v*HID + i)*CPD + t] = red[t];
}

// persistent RNN: one block per event
__global__ __launch_bounds__(256) void k_rnn(const float* __restrict__ w_hh){
    int n = blockIdx.x, t = threadIdx.x;
    int i = t & 127, half = t >> 7;
    int v = g_vidx[n];
    __shared__ float ctrl_s[NFR*CPD];
    __shared__ float h_s[HID];
    __shared__ float part_s[256];

    float W[64];
    const float* wh = w_hh + ((size_t)v*HID + i) * HID + half*64;
    #pragma unroll
    for(int k = 0; k < 64; k++) W[k] = wh[k];
    float M[CPD];
    const float* mp = g_M + (v*HID + i)*CPD;
    #pragma unroll
    for(int c = 0; c < CPD; c++) M[c] = mp[c];
    for(int idx = t; idx < NFR*CPD; idx += 256) ctrl_s[idx] = g_ctrl[n*NFR*CPD + idx];
    if(t < HID) h_s[t] = 0.f;
    __syncthreads();

    float* hsout = g_hs + (size_t)n*NFR*HID;
    for(int f = 0; f < NFR; f++){
        const float* hb = h_s + half*64;
        float p0 = 0.f, p1 = 0.f, p2 = 0.f, p3 = 0.f;
        #pragma unroll
        for(int k = 0; k < 64; k += 4){
            p0 = fmaf(W[k],   hb[k],   p0);
            p1 = fmaf(W[k+1], hb[k+1], p1);
            p2 = fmaf(W[k+2], hb[k+2], p2);
            p3 = fmaf(W[k+3], hb[k+3], p3);
        }
        float inp = 0.f;
        if(half == 0){
            const float* cf = ctrl_s + f*CPD;
            float i0 = 0.f, i1 = 0.f;
            #pragma unroll
            for(int c = 0; c < CPD; c += 2){
                i0 = fmaf(M[c],   cf[c],   i0);
                i1 = fmaf(M[c+1], cf[c+1], i1);
            }
            inp = i0 + i1;
        }
        part_s[t] = (p0 + p1) + (p2 + p3);
        __syncthreads();
        if(half == 0){
            float h = tanhf(part_s[t] + part_s[t + 128] + inp);
            h_s[i] = h;
            hsout[f*HID + i] = h;
        }
        __syncthreads();
    }
}

// sig[f,w] = sin( hs[f,:] . w_out[v,w,:] ) — fp32 register-tiled GEMM, fast-sin epilogue
__global__ __launch_bounds__(256) void k_wout(const float* __restrict__ w_out){
    int wt = blockIdx.x, n = blockIdx.y, t = threadIdx.x;
    int v = g_vidx[n];
    const float* A  = g_hs + (size_t)n*NFR*HID;
    const float* Bm = w_out + (size_t)v*WINL*HID + (size_t)wt*128*HID;
    __shared__ float As[32*132];
    __shared__ float Bs[32*132];
    int tx = t & 15, ty = t >> 4;
    int f0 = ty*8, w0 = tx*8;
    float acc[8][8];
    #pragma unroll
    for(int i = 0; i < 8; i++)
        #pragma unroll
        for(int j = 0; j < 8; j++) acc[i][j] = 0.f;

    for(int ks = 0; ks < 4; ks++){
        int k0 = ks*32;
        #pragma unroll
        for(int r = 0; r < 4; r++){
            int idx4 = t + 256*r;
            int rr = idx4 >> 3, kk4 = idx4 & 7;
            float4 va = *(const float4*)(A  + (size_t)rr*HID + k0 + kk4*4);
            float4 vb = *(const float4*)(Bm + (size_t)rr*HID + k0 + kk4*4);
            As[(kk4*4+0)*132 + rr] = va.x; As[(kk4*4+1)*132 + rr] = va.y;
            As[(kk4*4+2)*132 + rr] = va.z; As[(kk4*4+3)*132 + rr] = va.w;
            Bs[(kk4*4+0)*132 + rr] = vb.x; Bs[(kk4*4+1)*132 + rr] = vb.y;
            Bs[(kk4*4+2)*132 + rr] = vb.z; Bs[(kk4*4+3)*132 + rr] = vb.w;
        }
        __syncthreads();
        #pragma unroll
        for(int k = 0; k < 32; k++){
            float4 a0 = *(const float4*)&As[k*132 + f0];
            float4 a1 = *(const float4*)&As[k*132 + f0 + 4];
            float4 b0 = *(const float4*)&Bs[k*132 + w0];
            float4 b1 = *(const float4*)&Bs[k*132 + w0 + 4];
            float a[8] = {a0.x,a0.y,a0.z,a0.w,a1.x,a1.y,a1.z,a1.w};
            float b[8] = {b0.x,b0.y,b0.z,b0.w,b1.x,b1.y,b1.z,b1.w};
            #pragma unroll
            for(int i = 0; i < 8; i++)
                #pragma unroll
                for(int j = 0; j < 8; j++) acc[i][j] += a[i]*b[j];
        }
        __syncthreads();
    }
    float* out = g_sig + (size_t)n*NSAMP + wt*128;
    #pragma unroll
    for(int i = 0; i < 8; i++)
        #pragma unroll
        for(int j = 0; j < 8; j++)
            out[(size_t)(f0+i)*WINL + w0 + j] = __sinf(acc[i][j]);
}

// F1 column pass (forward). VERB=1: real verb -> g_vspec. VERB=0: packed pair of sigs -> g_spec.
// Upper 256 rows are structural zeros: not staged, pruned in dif512t<true>.
template<int VERB>
__global__ __launch_bounds__(512) void k_col_fwd(const float* __restrict__ rin_ext){
    __shared__ float2 s[8*LSTR];
    int y = blockIdx.y, col0 = blockIdx.x*8, tid = threadIdx.x;
    const float* sa; const float* sb = nullptr; float2* dst;
    if(VERB){ sa = rin_ext + (size_t)y*NSAMP;        dst = g_vspec + (size_t)y*NFFT; }
    else    { sa = g_sig + (size_t)(2*y)*NSAMP; sb = g_sig + (size_t)(2*y+1)*NSAMP;
              dst = g_spec + (size_t)y*NFFT; }
    for(int idx = tid; idx < 2048; idx += 512){
        int r = idx >> 3, c = idx & 7;
        int o = r*512 + col0 + c;
        float re = sa[o];
        float im = VERB ? 0.f : sb[o];
        s[c*LSTR + skew(r)] = make_float2(re, im);
    }
    __syncthreads();
    dif512t<true>(&s[(tid >> 6)*LSTR], tid & 63);
    __syncthreads();
    for(int idx = tid; idx < 4096; idx += 512){
        int r = idx >> 3, c = idx & 7;
        int n2 = col0 + c;
        dst[(size_t)r*512 + n2] = cmul(s[c*LSTR + skew(r)], twN(rev9(r)*n2));
    }
}

// F2 row pass for verb spectra (store in scrambled (row,e) layout)
__global__ __launch_bounds__(512) void k_row_verb(){
    __shared__ float2 s[8*LSTR];
    int n = blockIdx.y, row0 = blockIdx.x*8, tid = threadIdx.x;
    float2* base = g_vspec + (size_t)n*NFFT + (size_t)row0*512;
    for(int idx = tid; idx < 4096; idx += 512){
        int r = idx >> 9, e = idx & 511;
        s[r*LSTR + skew(e)] = base[(size_t)r*512 + e];
    }
    __syncthreads();
    dif512t<false>(&s[(tid >> 6)*LSTR], tid & 63);
    __syncthreads();
    for(int idx = tid; idx < 4096; idx += 512){
        int r = idx >> 9, e = idx & 511;
        base[(size_t)r*512 + e] = s[r*LSTR + skew(e)];
    }
}

__device__ __forceinline__ int pzero(int e){   // partner col for the k1==0 row
    int k2 = rev9(e);
    return rev9((512 - k2) & 511);
}

// Fused: F2 + conj-unpack + spectral mul (verb+dry fold, 1/N) + repack + I1 + conj twiddle.
// 256 threads = 2 pair-slots per block. Slot >256 clamps to 256 (idempotent duplicate).
__global__ __launch_bounds__(256) void k_rowpair(){
    __shared__ float2 s[4*LSTR];
    int p = blockIdx.y;
    int grp = threadIdx.x >> 7;
    int lt  = threadIdx.x & 127;
    int slot = blockIdx.x*2 + grp; if(slot > 256) slot = 256;
    int rows0 = g_pairA[slot], rows1 = g_pairB[slot];
    int line = lt >> 6, t = lt & 63;
    float2* base = g_spec + (size_t)p*NFFT;
    float2* sg = s + (2*grp)*LSTR;
    for(int idx = lt; idx < 1024; idx += 128){
        int l = idx >> 9, e = idx & 511;
        int row = l ? rows1 : rows0;
        sg[l*LSTR + skew(e)] = base[(size_t)row*512 + e];
    }
    __syncthreads();
    dif512t<false>(&sg[line*LSTR], t);
    __syncthreads();

    int na = 2*p, nb = 2*p + 1;
    const float2* va = g_vspec + (size_t)g_ridx[na]*NFFT;
    const float2* vb = g_vspec + (size_t)g_ridx[nb]*NFFT;
    float m0a = g_m0[na], m1a = g_m1[na], m0b = g_m0[nb], m1b = g_m1[nb];
    const float invN = 1.f / (float)NFFT;

    float2 Z[8], Zp[8];
    #pragma unroll
    for(int q = 0; q < 8; q++){
        int idx = lt + 128*q;
        int l = idx >> 9, e = idx & 511;
        int row = l ? rows1 : rows0;
        int k1 = rev9(row);
        int ep = (k1 == 0) ? pzero(e) : (511 - e);
        Z[q]  = sg[l*LSTR + skew(e)];
        Zp[q] = sg[(1 - l)*LSTR + skew(ep)];
    }
    __syncthreads();
    #pragma unroll
    for(int q = 0; q < 8; q++){
        int idx = lt + 128*q;
        int l = idx >> 9, e = idx & 511;
        int row = l ? rows1 : rows0;
        float2 S1 = make_float2(0.5f*(Z[q].x + Zp[q].x), 0.5f*(Z[q].y - Zp[q].y));
        float2 S2 = make_float2(0.5f*(Z[q].y + Zp[q].y), -0.5f*(Z[q].x - Zp[q].x));
        float2 V1 = va[(size_t)row*512 + e];
        float2 V2 = vb[(size_t)row*512 + e];
        float2 M1 = make_float2(m0a*V1.x + m1a, m0a*V1.y);
        float2 M2 = make_float2(m0b*V2.x + m1b, m0b*V2.y);
        float2 W1 = cmul(S1, M1), W2 = cmul(S2, M2);
        sg[l*LSTR + skew(e)] = make_float2((W1.x - W2.y)*invN, (W1.y + W2.x)*invN);
    }
    __syncthreads();
    dit512(&sg[line*LSTR], t);
    __syncthreads();
    for(int idx = lt; idx < 1024; idx += 128){
        int l = idx >> 9, e = idx & 511;
        int row = l ? rows1 : rows0;
        int k1 = rev9(row);
        base[(size_t)row*512 + e] = cmulc(sg[l*LSTR + skew(e)], twN(k1*e));
    }
}

// I2 column pass (inverse, packed) + epilogue: |amp| + dirac row-shift.
__global__ __launch_bounds__(512) void k_col_inv(float* __restrict__ out){
    __shared__ float2 s[8*LSTR];
    int p = blockIdx.y, col0 = blockIdx.x*8, tid = threadIdx.x;
    const float2* src = g_spec + (size_t)p*NFFT;
    for(int idx = tid; idx < 4096; idx += 512){
        int r = idx >> 3, c = idx & 7;
        s[c*LSTR + skew(r)] = src[(size_t)r*512 + col0 + c];
    }
    __syncthreads();
    dit512(&s[(tid >> 6)*LSTR], tid & 63);
    __syncthreads();
    int na = 2*p, nb = 2*p + 1;
    float aA = g_amp[na], aB = g_amp[nb];
    int dA = g_shift[na] >> 9, dB = g_shift[nb] >> 9;
    float* oA = out + (size_t)na*NSAMP;
    float* oB = out + (size_t)nb*NSAMP;
    for(int idx = tid; idx < 2048; idx += 512){
        int rp = idx >> 3, c = idx & 7;
        int col = col0 + c;
        int ra = rp - dA;
        oA[rp*512 + col] = (ra >= 0) ? s[c*LSTR + skew(ra)].x * aA : 0.f;
        int rb = rp - dB;
        oB[rp*512 + col] = (rb >= 0) ? s[c*LSTR + skew(rb)].y * aB : 0.f;
    }
}

extern "C" void kernel_launch(void* const* d_in, const int* in_sizes, int n_in,
                              void* d_out, int out_size) {
    const float* voice = (const float*)d_in[0];
    const float* cpc   = (const float*)d_in[1];
    const float* amp   = (const float*)d_in[2];
    const float* room  = (const float*)d_in[3];
    const float* mix   = (const float*)d_in[4];
    const float* times = (const float*)d_in[5];
    const float* cp_table = (const float*)d_in[6];
    const float* verbs = (const float*)d_in[7];
    const float* w_in  = (const float*)d_in[8];
    const float* w_ih  = (const float*)d_in[9];
    const float* w_hh  = (const float*)d_in[10];
    const float* w_out = (const float*)d_in[11];
    float* out = (float*)d_out;

    // One-time side stream + events (created on the correctness call, OUTSIDE capture;
    // replayed graph contains the fork/join as parallel branches). No device memory.
    static cudaStream_t s_side = 0;
    static cudaEvent_t  ev_fork = 0, ev_coll = 0, ev_join = 0;
    static int s_init = 0;
    if(!s_init){
        if(cudaStreamCreateWithFlags(&s_side, cudaStreamNonBlocking) != cudaSuccess) s_side = 0;
        if(s_side){
            if(cudaEventCreateWithFlags(&ev_fork, cudaEventDisableTiming) != cudaSuccess ||
               cudaEventCreateWithFlags(&ev_coll, cudaEventDisableTiming) != cudaSuccess ||
               cudaEventCreateWithFlags(&ev_join, cudaEventDisableTiming) != cudaSuccess){
                s_side = 0;
            }
        }
        s_init = 1;
    }

    k_twtab<<<2, 512>>>();
    if(s_side){
        // fork: side stream runs collapse + the verb FFT chain
        cudaEventRecord(ev_fork, 0);
        cudaStreamWaitEvent(s_side, ev_fork, 0);
        k_collapse<<<NVO*HID, 128, 0, s_side>>>(w_ih, w_in);
        cudaEventRecord(ev_coll, s_side);
        k_col_fwd<1><<<dim3(64, NVB), 512, 0, s_side>>>(verbs);
        k_row_verb<<<dim3(64, NVB), 512, 0, s_side>>>();
        cudaEventRecord(ev_join, s_side);
        // main stream
        k_prep<<<NEV, 256>>>(voice, cpc, amp, room, mix, times, cp_table);
        cudaStreamWaitEvent(0, ev_coll, 0);
        k_rnn<<<NEV, 256>>>(w_hh);
        k_wout<<<dim3(8, NEV), 256>>>(w_out);
        k_col_fwd<0><<<dim3(64, NPAIR), 512>>>(nullptr);
        cudaStreamWaitEvent(0, ev_join, 0);
        k_rowpair<<<dim3(129, NPAIR), 256>>>();
        k_col_inv<<<dim3(64, NPAIR), 512>>>(out);
    } else {
        // serial fallback (identical to R9)
        k_prep<<<NEV, 256>>>(voice, cpc, amp, room, mix, times, cp_table);
        k_collapse<<<NVO*HID, 128>>>(w_ih, w_in);
        k_rnn<<<NEV, 256>>>(w_hh);
        k_wout<<<dim3(8, NEV), 256>>>(w_out);
        k_col_fwd<1><<<dim3(64, NVB), 512>>>(verbs);
        k_row_verb<<<dim3(64, NVB), 512>>>();
        k_col_fwd<0><<<dim3(64, NPAIR), 512>>>(nullptr);
        k_rowpair<<<dim3(129, NPAIR), 256>>>();
        k_col_inv<<<dim3(64, NPAIR), 512>>>(out);
    }
}

// round 11
// speedup vs baseline: 1.4597x; 1.0989x over previous
#include <cuda_runtime.h>
#include <math.h>

#define NEV   128
#define NPAIR 64
#define NSAMP 131072
#define NFFT  262144
#define NFR   128
#define WINL  1024
#define CPD   16
#define NCP   512
#define NVO   8
#define NVB   16
#define HID   128
#define KSP   128
#define LSTR  578

__device__ float2 g_twtab[1024];                     // [0:512) W512^k ; [512:1024) W_N^k
__device__ float2 g_spec[(size_t)NPAIR * NFFT];      // 128 MB packed spectra
__device__ float2 g_vspec[(size_t)NVB * NFFT];       // 32 MB verb spectra
__device__ float  g_sig[(size_t)NEV * NSAMP];
__device__ float  g_hs[(size_t)NEV * NFR * HID];
__device__ float  g_ctrl[NEV * NFR * CPD];
__device__ float  g_M[NVO * HID * CPD];
__device__ int    g_vidx[NEV], g_ridx[NEV], g_shift[NEV];
__device__ float  g_m0[NEV], g_m1[NEV], g_amp[NEV];
__device__ int    g_pairA[257], g_pairB[257];

__device__ __forceinline__ int skew(int i){ return i + (i >> 3); }
__device__ __forceinline__ float2 cadd(float2 a, float2 b){ return make_float2(a.x+b.x, a.y+b.y); }
__device__ __forceinline__ float2 csub(float2 a, float2 b){ return make_float2(a.x-b.x, a.y-b.y); }
__device__ __forceinline__ float2 cmul(float2 a, float2 b){ return make_float2(a.x*b.x - a.y*b.y, a.x*b.y + a.y*b.x); }
__device__ __forceinline__ float2 cmulc(float2 a, float2 b){ return make_float2(a.x*b.x + a.y*b.y, a.y*b.x - a.x*b.y); }
__device__ __forceinline__ int rev9(int p){ return ((p & 7) << 6) | (p & 56) | (p >> 6); }

__device__ __forceinline__ float2 twN(int idx){
    int k = idx & (NFFT - 1);
    return cmul(g_twtab[k >> 9], g_twtab[512 + (k & 511)]);
}

template<bool INV>
__device__ __forceinline__ float2 mulmi(float2 a){
    return INV ? make_float2(-a.y, a.x) : make_float2(a.y, -a.x);
}

template<bool INV>
__device__ __forceinline__ void dft8(float2* v){
    float2 t0 = cadd(v[0], v[4]), t1 = csub(v[0], v[4]);
    float2 t2 = cadd(v[2], v[6]), t3 = mulmi<INV>(csub(v[2], v[6]));
    float2 t4 = cadd(v[1], v[5]), t5 = csub(v[1], v[5]);
    float2 t6 = cadd(v[3], v[7]), t7 = mulmi<INV>(csub(v[3], v[7]));
    float2 a0 = cadd(t0, t2), a2 = csub(t0, t2);
    float2 a1 = cadd(t1, t3), a3 = csub(t1, t3);
    float2 b0 = cadd(t4, t6), b2 = csub(t4, t6);
    float2 b1 = cadd(t5, t7), b3 = csub(t5, t7);
    const float r = 0.70710678118654752440f;
    float2 w1 = INV ? make_float2(r,  r) : make_float2(r, -r);
    float2 w3 = INV ? make_float2(-r, r) : make_float2(-r, -r);
    b1 = cmul(b1, w1); b2 = mulmi<INV>(b2); b3 = cmul(b3, w3);
    v[0] = cadd(a0, b0); v[4] = csub(a0, b0);
    v[1] = cadd(a1, b1); v[5] = csub(a1, b1);
    v[2] = cadd(a2, b2); v[6] = csub(a2, b2);
    v[3] = cadd(a3, b3); v[7] = csub(a3, b3);
}

// DIF 512 = radix-8^3, natural in -> octal-digit-reversed out.
// ZTOP: input rows [256,512) are structural zeros (not staged in smem).
template<bool ZTOP>
__device__ __forceinline__ void dif512t(float2* L, int t){
    float2 v[8];
    if(ZTOP){
        #pragma unroll
        for(int m = 0; m < 4; m++) v[m] = L[skew(t + 64*m)];
        #pragma unroll
        for(int m = 4; m < 8; m++) v[m] = make_float2(0.f, 0.f);
    } else {
        #pragma unroll
        for(int m = 0; m < 8; m++) v[m] = L[skew(t + 64*m)];
    }
    dft8<false>(v);
    #pragma unroll
    for(int m = 1; m < 8; m++) v[m] = cmul(v[m], g_twtab[(t*m) & 511]);
    #pragma unroll
    for(int m = 0; m < 8; m++) L[skew(t + 64*m)] = v[m];
    __syncthreads();
    int base = (t >> 3) << 6, j = t & 7;
    #pragma unroll
    for(int m = 0; m < 8; m++) v[m] = L[skew(base + j + 8*m)];
    dft8<false>(v);
    #pragma unroll
    for(int m = 1; m < 8; m++) v[m] = cmul(v[m], g_twtab[((j*m) << 3) & 511]);
    #pragma unroll
    for(int m = 0; m < 8; m++) L[skew(base + j + 8*m)] = v[m];
    __syncthreads();
    base = t << 3;
    #pragma unroll
    for(int m = 0; m < 8; m++) v[m] = L[skew(base + m)];
    dft8<false>(v);
    #pragma unroll
    for(int m = 0; m < 8; m++) L[skew(base + m)] = v[m];
}

// DIT 512: digit-reversed in -> natural out, conjugate twiddles (unscaled inverse).
__device__ __forceinline__ void dit512(float2* L, int t){
    float2 v[8];
    int base = t << 3;
    #pragma unroll
    for(int m = 0; m < 8; m++) v[m] = L[skew(base + m)];
    dft8<true>(v);
    #pragma unroll
    for(int m = 0; m < 8; m++) L[skew(base + m)] = v[m];
    __syncthreads();
    base = (t >> 3) << 6; int j = t & 7;
    #pragma unroll
    for(int m = 0; m < 8; m++) v[m] = L[skew(base + j + 8*m)];
    #pragma unroll
    for(int m = 1; m < 8; m++) v[m] = cmulc(v[m], g_twtab[((j*m) << 3) & 511]);
    dft8<true>(v);
    #pragma unroll
    for(int m = 0; m < 8; m++) L[skew(base + j + 8*m)] = v[m];
    __syncthreads();
    #pragma unroll
    for(int m = 0; m < 8; m++) v[m] = L[skew(t + 64*m)];
    #pragma unroll
    for(int m = 1; m < 8; m++) v[m] = cmulc(v[m], g_twtab[(t*m) & 511]);
    dft8<true>(v);
    #pragma unroll
    for(int m = 0; m < 8; m++) L[skew(t + 64*m)] = v[m];
}

__global__ void k_twtab(){
    int k = blockIdx.x * blockDim.x + threadIdx.x;
    if(k < 1024){
        double a;
        if(k < 512) a = -6.283185307179586476925286766559 * (double)k / 512.0;
        else        a = -6.283185307179586476925286766559 * (double)(k - 512) / (double)NFFT;
        double s, c; sincos(a, &s, &c);
        g_twtab[k] = make_float2((float)c, (float)s);
    }
    if(k == 0){
        int cnt = 0;
        for(int p = 0; p < 512; p++){
            int k1 = rev9(p);
            int pp = rev9((512 - k1) & 511);
            if(p <= pp){ g_pairA[cnt] = p; g_pairB[cnt] = pp; cnt++; }
        }
    }
}

__global__ __launch_bounds__(256) void k_prep(
    const float* __restrict__ voice, const float* __restrict__ cpc,
    const float* __restrict__ amp,   const float* __restrict__ room,
    const float* __restrict__ mix,   const float* __restrict__ times,
    const float* __restrict__ cp_table)
{
    int n = blockIdx.x, tid = threadIdx.x;
    __shared__ float sv[256];
    __shared__ int   si[256];
    __shared__ int   s_cidx, s_cnt;

    float best = -1e30f; int bi = 0;
    for(int j = tid; j < NCP; j += 256){
        float v = cpc[n*NCP + j];
        if(v > best){ best = v; bi = j; }
    }
    sv[tid] = best; si[tid] = bi; __syncthreads();
    for(int s = 128; s > 0; s >>= 1){
        if(tid < s){
            if(sv[tid+s] > sv[tid] || (sv[tid+s] == sv[tid] && si[tid+s] < si[tid])){
                sv[tid] = sv[tid+s]; si[tid] = si[tid+s];
            }
        }
        __syncthreads();
    }
    if(tid == 0){
        s_cidx = si[0];
        float b = -1e30f; int ii = 0;
        for(int j = 0; j < NFR; j++){ float v = times[n*NFR + j]; if(v > b){ b = v; ii = j; } }
        g_shift[n] = ii * (NSAMP / NFR);
        b = -1e30f; ii = 0;
        for(int j = 0; j < NVO; j++){ float v = voice[n*NVO + j]; if(v > b){ b = v; ii = j; } }
        g_vidx[n] = ii;
        b = -1e30f; ii = 0;
        for(int j = 0; j < NVB; j++){ float v = room[n*NVB + j]; if(v > b){ b = v; ii = j; } }
        g_ridx[n] = ii;
        float x0 = mix[n*2], x1 = mix[n*2 + 1];
        float mm = fmaxf(x0, x1);
        float e0 = expf(x0 - mm), e1 = expf(x1 - mm);
        g_m0[n] = e0 / (e0 + e1);
        g_m1[n] = e1 / (e0 + e1);
        g_amp[n] = fabsf(amp[n]);
    }
    __syncthreads();

    const float* row = cp_table + (size_t)s_cidx * (NFR*CPD);
    float rv[8];
    #pragma unroll
    for(int j = 0; j < 8; j++) rv[j] = row[tid + 256*j];
    unsigned lo = 0u, hi = 0x7F800000u;
    while(hi - lo > 1u){
        unsigned mid = lo + ((hi - lo) >> 1);
        int c = 0;
        #pragma unroll
        for(int j = 0; j < 8; j++) c += (__float_as_uint(rv[j]) >= mid) ? 1 : 0;
        si[tid] = c; __syncthreads();
        for(int s = 128; s > 0; s >>= 1){
            if(tid < s) si[tid] += si[tid+s];
            __syncthreads();
        }
        if(tid == 0) s_cnt = si[0];
        __syncthreads();
        if(s_cnt >= KSP) lo = mid; else hi = mid;
    }
    for(int idx = tid; idx < NFR*CPD; idx += 256){
        int f = idx >> 4, c = idx & 15;
        float v = row[c*NFR + f];
        float keep = (__float_as_uint(v) >= lo) ? v : 0.f;
        g_ctrl[n*NFR*CPD + idx] = fmaxf(keep, 0.f);
    }
}

// M[v] = W_ih[v] @ W_in[v] — parallel Kahan-fp32 split-K
__global__ __launch_bounds__(128) void k_collapse(
    const float* __restrict__ w_ih, const float* __restrict__ w_in)
{
    int blk = blockIdx.x;
    int v = blk >> 7, i = blk & 127;
    int t = threadIdx.x;
    const float* wr = w_ih + ((size_t)v*HID + i) * WINL;
    const float* wc = w_in + (size_t)v*WINL*CPD;
    float s[CPD], comp[CPD];
    #pragma unroll
    for(int c = 0; c < CPD; c++){ s[c] = 0.f; comp[c] = 0.f; }
    for(int k = t; k < WINL; k += 128){
        float a = wr[k];
        const float4* p = (const float4*)(wc + (size_t)k*CPD);
        float4 q[4] = {p[0], p[1], p[2], p[3]};
        const float* qs = (const float*)q;
        #pragma unroll
        for(int c = 0; c < CPD; c++){
            float y = fmaf(a, qs[c], -comp[c]);
            float tt = s[c] + y;
            comp[c] = (tt - s[c]) - y;
            s[c] = tt;
        }
    }
    __shared__ float red[128 * CPD];
    #pragma unroll
    for(int c = 0; c < CPD; c++) red[t*CPD + c] = s[c];
    __syncthreads();
    for(int st = 64; st > 0; st >>= 1){
        if(t < st){
            #pragma unroll
            for(int c = 0; c < CPD; c++) red[t*CPD + c] += red[(t+st)*CPD + c];
        }
        __syncthreads();
    }
    if(t < CPD) g_M[(v*HID + i)*CPD + t] = red[t];
}

// persistent RNN: one block per event
__global__ __launch_bounds__(256) void k_rnn(const float* __restrict__ w_hh){
    int n = blockIdx.x, t = threadIdx.x;
    int i = t & 127, half = t >> 7;
    int v = g_vidx[n];
    __shared__ float ctrl_s[NFR*CPD];
    __shared__ float h_s[HID];
    __shared__ float part_s[256];

    float W[64];
    const float* wh = w_hh + ((size_t)v*HID + i) * HID + half*64;
    #pragma unroll
    for(int k = 0; k < 64; k++) W[k] = wh[k];
    float M[CPD];
    const float* mp = g_M + (v*HID + i)*CPD;
    #pragma unroll
    for(int c = 0; c < CPD; c++) M[c] = mp[c];
    for(int idx = t; idx < NFR*CPD; idx += 256) ctrl_s[idx] = g_ctrl[n*NFR*CPD + idx];
    if(t < HID) h_s[t] = 0.f;
    __syncthreads();

    float* hsout = g_hs + (size_t)n*NFR*HID;
    for(int f = 0; f < NFR; f++){
        const float* hb = h_s + half*64;
        float p0 = 0.f, p1 = 0.f, p2 = 0.f, p3 = 0.f;
        #pragma unroll
        for(int k = 0; k < 64; k += 4){
            p0 = fmaf(W[k],   hb[k],   p0);
            p1 = fmaf(W[k+1], hb[k+1], p1);
            p2 = fmaf(W[k+2], hb[k+2], p2);
            p3 = fmaf(W[k+3], hb[k+3], p3);
        }
        float inp = 0.f;
        if(half == 0){
            const float* cf = ctrl_s + f*CPD;
            float i0 = 0.f, i1 = 0.f;
            #pragma unroll
            for(int c = 0; c < CPD; c += 2){
                i0 = fmaf(M[c],   cf[c],   i0);
                i1 = fmaf(M[c+1], cf[c+1], i1);
            }
            inp = i0 + i1;
        }
        part_s[t] = (p0 + p1) + (p2 + p3);
        __syncthreads();
        if(half == 0){
            float h = tanhf(part_s[t] + part_s[t + 128] + inp);
            h_s[i] = h;
            hsout[f*HID + i] = h;
        }
        __syncthreads();
    }
}

// sig[f,w] = sin( hs[f,:] . w_out[v,w,:] ) — fp32 register-tiled GEMM, fast-sin epilogue
__global__ __launch_bounds__(256) void k_wout(const float* __restrict__ w_out){
    int wt = blockIdx.x, n = blockIdx.y, t = threadIdx.x;
    int v = g_vidx[n];
    const float* A  = g_hs + (size_t)n*NFR*HID;
    const float* Bm = w_out + (size_t)v*WINL*HID + (size_t)wt*128*HID;
    __shared__ float As[32*132];
    __shared__ float Bs[32*132];
    int tx = t & 15, ty = t >> 4;
    int f0 = ty*8, w0 = tx*8;
    float acc[8][8];
    #pragma unroll
    for(int i = 0; i < 8; i++)
        #pragma unroll
        for(int j = 0; j < 8; j++) acc[i][j] = 0.f;

    for(int ks = 0; ks < 4; ks++){
        int k0 = ks*32;
        #pragma unroll
        for(int r = 0; r < 4; r++){
            int idx4 = t + 256*r;
            int rr = idx4 >> 3, kk4 = idx4 & 7;
            float4 va = *(const float4*)(A  + (size_t)rr*HID + k0 + kk4*4);
            float4 vb = *(const float4*)(Bm + (size_t)rr*HID + k0 + kk4*4);
            As[(kk4*4+0)*132 + rr] = va.x; As[(kk4*4+1)*132 + rr] = va.y;
            As[(kk4*4+2)*132 + rr] = va.z; As[(kk4*4+3)*132 + rr] = va.w;
            Bs[(kk4*4+0)*132 + rr] = vb.x; Bs[(kk4*4+1)*132 + rr] = vb.y;
            Bs[(kk4*4+2)*132 + rr] = vb.z; Bs[(kk4*4+3)*132 + rr] = vb.w;
        }
        __syncthreads();
        #pragma unroll
        for(int k = 0; k < 32; k++){
            float4 a0 = *(const float4*)&As[k*132 + f0];
            float4 a1 = *(const float4*)&As[k*132 + f0 + 4];
            float4 b0 = *(const float4*)&Bs[k*132 + w0];
            float4 b1 = *(const float4*)&Bs[k*132 + w0 + 4];
            float a[8] = {a0.x,a0.y,a0.z,a0.w,a1.x,a1.y,a1.z,a1.w};
            float b[8] = {b0.x,b0.y,b0.z,b0.w,b1.x,b1.y,b1.z,b1.w};
            #pragma unroll
            for(int i = 0; i < 8; i++)
                #pragma unroll
                for(int j = 0; j < 8; j++) acc[i][j] += a[i]*b[j];
        }
        __syncthreads();
    }
    float* out = g_sig + (size_t)n*NSAMP + wt*128;
    #pragma unroll
    for(int i = 0; i < 8; i++)
        #pragma unroll
        for(int j = 0; j < 8; j++)
            out[(size_t)(f0+i)*WINL + w0 + j] = __sinf(acc[i][j]);
}

// F1 column pass (forward). VERB=1: real verb -> g_vspec. VERB=0: packed pair of sigs -> g_spec.
// Upper 256 rows are structural zeros: not staged, pruned in dif512t<true>.
template<int VERB>
__global__ __launch_bounds__(512) void k_col_fwd(const float* __restrict__ rin_ext){
    __shared__ float2 s[8*LSTR];
    int y = blockIdx.y, col0 = blockIdx.x*8, tid = threadIdx.x;
    const float* sa; const float* sb = nullptr; float2* dst;
    if(VERB){ sa = rin_ext + (size_t)y*NSAMP;        dst = g_vspec + (size_t)y*NFFT; }
    else    { sa = g_sig + (size_t)(2*y)*NSAMP; sb = g_sig + (size_t)(2*y+1)*NSAMP;
              dst = g_spec + (size_t)y*NFFT; }
    for(int idx = tid; idx < 2048; idx += 512){
        int r = idx >> 3, c = idx & 7;
        int o = r*512 + col0 + c;
        float re = sa[o];
        float im = VERB ? 0.f : sb[o];
        s[c*LSTR + skew(r)] = make_float2(re, im);
    }
    __syncthreads();
    dif512t<true>(&s[(tid >> 6)*LSTR], tid & 63);
    __syncthreads();
    for(int idx = tid; idx < 4096; idx += 512){
        int r = idx >> 3, c = idx & 7;
        int n2 = col0 + c;
        dst[(size_t)r*512 + n2] = cmul(s[c*LSTR + skew(r)], twN(rev9(r)*n2));
    }
}

// F2 row pass for verb spectra — direct global in (stage 1) and out (stage 3).
__global__ __launch_bounds__(512) void k_row_verb(){
    __shared__ float2 s[8*LSTR];
    int n = blockIdx.y, row0 = blockIdx.x*8, tid = threadIdx.x;
    int line = tid >> 6, t = tid & 63;
    float2* base = g_vspec + (size_t)n*NFFT + (size_t)row0*512;
    float2* grow = base + (size_t)line*512;
    float2* L = s + line*LSTR;
    float2 v[8];
    #pragma unroll
    for(int m = 0; m < 8; m++) v[m] = grow[t + 64*m];
    dft8<false>(v);
    #pragma unroll
    for(int m = 1; m < 8; m++) v[m] = cmul(v[m], g_twtab[(t*m) & 511]);
    #pragma unroll
    for(int m = 0; m < 8; m++) L[skew(t + 64*m)] = v[m];
    __syncthreads();
    int b2 = (t >> 3) << 6, j = t & 7;
    #pragma unroll
    for(int m = 0; m < 8; m++) v[m] = L[skew(b2 + j + 8*m)];
    dft8<false>(v);
    #pragma unroll
    for(int m = 1; m < 8; m++) v[m] = cmul(v[m], g_twtab[((j*m) << 3) & 511]);
    #pragma unroll
    for(int m = 0; m < 8; m++) L[skew(b2 + j + 8*m)] = v[m];
    __syncthreads();
    int b3 = t << 3;
    #pragma unroll
    for(int m = 0; m < 8; m++) v[m] = L[skew(b3 + m)];
    dft8<false>(v);
    #pragma unroll
    for(int m = 0; m < 8; m++) grow[b3 + m] = v[m];
}

__device__ __forceinline__ int pzero(int e){   // partner col for the k1==0 row
    int k2 = rev9(e);
    return rev9((512 - k2) & 511);
}

// Fused: F2 + conj-unpack + spectral mul (verb+dry fold, 1/N) + repack + I1 + conj twiddle.
// Direct-global stage-1 in and stage-3 out; smem only for stage exchanges and the unpack.
// 256 threads = 2 pair-slots per block. Slot >256 clamps to 256 (same-block idempotent duplicate).
__global__ __launch_bounds__(256) void k_rowpair(){
    __shared__ float2 s[4*LSTR];
    int p = blockIdx.y;
    int grp = threadIdx.x >> 7;
    int lt  = threadIdx.x & 127;
    int slot = blockIdx.x*2 + grp; if(slot > 256) slot = 256;
    int rows0 = g_pairA[slot], rows1 = g_pairB[slot];
    int line = lt >> 6, t = lt & 63;
    int myrow = line ? rows1 : rows0;
    float2* base = g_spec + (size_t)p*NFFT;
    float2* sg = s + (2*grp)*LSTR;
    float2* L  = sg + line*LSTR;
    float2* grow = base + (size_t)myrow*512;
    float2 v[8];

    // F2 stage 1: direct global in
    #pragma unroll
    for(int m = 0; m < 8; m++) v[m] = grow[t + 64*m];
    dft8<false>(v);
    #pragma unroll
    for(int m = 1; m < 8; m++) v[m] = cmul(v[m], g_twtab[(t*m) & 511]);
    #pragma unroll
    for(int m = 0; m < 8; m++) L[skew(t + 64*m)] = v[m];
    __syncthreads();
    // F2 stage 2
    int b2 = (t >> 3) << 6, j = t & 7;
    #pragma unroll
    for(int m = 0; m < 8; m++) v[m] = L[skew(b2 + j + 8*m)];
    dft8<false>(v);
    #pragma unroll
    for(int m = 1; m < 8; m++) v[m] = cmul(v[m], g_twtab[((j*m) << 3) & 511]);
    #pragma unroll
    for(int m = 0; m < 8; m++) L[skew(b2 + j + 8*m)] = v[m];
    __syncthreads();
    // F2 stage 3 -> smem (unpack needs full lines)
    int b3 = t << 3;
    #pragma unroll
    for(int m = 0; m < 8; m++) v[m] = L[skew(b3 + m)];
    dft8<false>(v);
    #pragma unroll
    for(int m = 0; m < 8; m++) L[skew(b3 + m)] = v[m];
    __syncthreads();

    // conj-unpack + spectral multiply (verb + dry folded) + repack
    int na = 2*p, nb = 2*p + 1;
    const float2* va = g_vspec + (size_t)g_ridx[na]*NFFT;
    const float2* vb = g_vspec + (size_t)g_ridx[nb]*NFFT;
    float m0a = g_m0[na], m1a = g_m1[na], m0b = g_m0[nb], m1b = g_m1[nb];
    const float invN = 1.f / (float)NFFT;

    float2 Z[8], Zp[8];
    #pragma unroll
    for(int q = 0; q < 8; q++){
        int idx = lt + 128*q;
        int l = idx >> 9, e = idx & 511;
        int row = l ? rows1 : rows0;
        int k1 = rev9(row);
        int ep = (k1 == 0) ? pzero(e) : (511 - e);
        Z[q]  = sg[l*LSTR + skew(e)];
        Zp[q] = sg[(1 - l)*LSTR + skew(ep)];
    }
    __syncthreads();
    #pragma unroll
    for(int q = 0; q < 8; q++){
        int idx = lt + 128*q;
        int l = idx >> 9, e = idx & 511;
        int row = l ? rows1 : rows0;
        float2 S1 = make_float2(0.5f*(Z[q].x + Zp[q].x), 0.5f*(Z[q].y - Zp[q].y));
        float2 S2 = make_float2(0.5f*(Z[q].y + Zp[q].y), -0.5f*(Z[q].x - Zp[q].x));
        float2 V1 = va[(size_t)row*512 + e];
        float2 V2 = vb[(size_t)row*512 + e];
        float2 M1 = make_float2(m0a*V1.x + m1a, m0a*V1.y);
        float2 M2 = make_float2(m0b*V2.x + m1b, m0b*V2.y);
        float2 W1 = cmul(S1, M1), W2 = cmul(S2, M2);
        sg[l*LSTR + skew(e)] = make_float2((W1.x - W2.y)*invN, (W1.y + W2.x)*invN);
    }
    __syncthreads();

    // I1 (DIT) stage 1
    #pragma unroll
    for(int m = 0; m < 8; m++) v[m] = L[skew(b3 + m)];
    dft8<true>(v);
    #pragma unroll
    for(int m = 0; m < 8; m++) L[skew(b3 + m)] = v[m];
    __syncthreads();
    // I1 stage 2
    #pragma unroll
    for(int m = 0; m < 8; m++) v[m] = L[skew(b2 + j + 8*m)];
    #pragma unroll
    for(int m = 1; m < 8; m++) v[m] = cmulc(v[m], g_twtab[((j*m) << 3) & 511]);
    dft8<true>(v);
    #pragma unroll
    for(int m = 0; m < 8; m++) L[skew(b2 + j + 8*m)] = v[m];
    __syncthreads();
    // I1 stage 3 + conj inter-pass twiddle -> direct global out
    #pragma unroll
    for(int m = 0; m < 8; m++) v[m] = L[skew(t + 64*m)];
    #pragma unroll
    for(int m = 1; m < 8; m++) v[m] = cmulc(v[m], g_twtab[(t*m) & 511]);
    dft8<true>(v);
    int k1 = rev9(myrow);
    #pragma unroll
    for(int m = 0; m < 8; m++)
        grow[t + 64*m] = cmulc(v[m], twN(k1*(t + 64*m)));
}

// I2 column pass (inverse, packed) + epilogue: |amp| + dirac row-shift.
__global__ __launch_bounds__(512) void k_col_inv(float* __restrict__ out){
    __shared__ float2 s[8*LSTR];
    int p = blockIdx.y, col0 = blockIdx.x*8, tid = threadIdx.x;
    const float2* src = g_spec + (size_t)p*NFFT;
    for(int idx = tid; idx < 4096; idx += 512){
        int r = idx >> 3, c = idx & 7;
        s[c*LSTR + skew(r)] = src[(size_t)r*512 + col0 + c];
    }
    __syncthreads();
    dit512(&s[(tid >> 6)*LSTR], tid & 63);
    __syncthreads();
    int na = 2*p, nb = 2*p + 1;
    float aA = g_amp[na], aB = g_amp[nb];
    int dA = g_shift[na] >> 9, dB = g_shift[nb] >> 9;
    float* oA = out + (size_t)na*NSAMP;
    float* oB = out + (size_t)nb*NSAMP;
    for(int idx = tid; idx < 2048; idx += 512){
        int rp = idx >> 3, c = idx & 7;
        int col = col0 + c;
        int ra = rp - dA;
        oA[rp*512 + col] = (ra >= 0) ? s[c*LSTR + skew(ra)].x * aA : 0.f;
        int rb = rp - dB;
        oB[rp*512 + col] = (rb >= 0) ? s[c*LSTR + skew(rb)].y * aB : 0.f;
    }
}

extern "C" void kernel_launch(void* const* d_in, const int* in_sizes, int n_in,
                              void* d_out, int out_size) {
    const float* voice = (const float*)d_in[0];
    const float* cpc   = (const float*)d_in[1];
    const float* amp   = (const float*)d_in[2];
    const float* room  = (const float*)d_in[3];
    const float* mix   = (const float*)d_in[4];
    const float* times = (const float*)d_in[5];
    const float* cp_table = (const float*)d_in[6];
    const float* verbs = (const float*)d_in[7];
    const float* w_in  = (const float*)d_in[8];
    const float* w_ih  = (const float*)d_in[9];
    const float* w_hh  = (const float*)d_in[10];
    const float* w_out = (const float*)d_in[11];
    float* out = (float*)d_out;

    static cudaStream_t s_side = 0;
    static cudaEvent_t  ev_fork = 0, ev_coll = 0, ev_join = 0;
    static int s_init = 0;
    if(!s_init){
        if(cudaStreamCreateWithFlags(&s_side, cudaStreamNonBlocking) != cudaSuccess) s_side = 0;
        if(s_side){
            if(cudaEventCreateWithFlags(&ev_fork, cudaEventDisableTiming) != cudaSuccess ||
               cudaEventCreateWithFlags(&ev_coll, cudaEventDisableTiming) != cudaSuccess ||
               cudaEventCreateWithFlags(&ev_join, cudaEventDisableTiming) != cudaSuccess){
                s_side = 0;
            }
        }
        s_init = 1;
    }

    k_twtab<<<2, 512>>>();
    if(s_side){
        cudaEventRecord(ev_fork, 0);
        cudaStreamWaitEvent(s_side, ev_fork, 0);
        k_collapse<<<NVO*HID, 128, 0, s_side>>>(w_ih, w_in);
        cudaEventRecord(ev_coll, s_side);
        k_col_fwd<1><<<dim3(64, NVB), 512, 0, s_side>>>(verbs);
        k_row_verb<<<dim3(64, NVB), 512, 0, s_side>>>();
        cudaEventRecord(ev_join, s_side);
        k_prep<<<NEV, 256>>>(voice, cpc, amp, room, mix, times, cp_table);
        cudaStreamWaitEvent(0, ev_coll, 0);
        k_rnn<<<NEV, 256>>>(w_hh);
        k_wout<<<dim3(8, NEV), 256>>>(w_out);
        k_col_fwd<0><<<dim3(64, NPAIR), 512>>>(nullptr);
        cudaStreamWaitEvent(0, ev_join, 0);
        k_rowpair<<<dim3(129, NPAIR), 256>>>();
        k_col_inv<<<dim3(64, NPAIR), 512>>>(out);
    } else {
        k_prep<<<NEV, 256>>>(voice, cpc, amp, room, mix, times, cp_table);
        k_collapse<<<NVO*HID, 128>>>(w_ih, w_in);
        k_rnn<<<NEV, 256>>>(w_hh);
        k_wout<<<dim3(8, NEV), 256>>>(w_out);
        k_col_fwd<1><<<dim3(64, NVB), 512>>>(verbs);
        k_row_verb<<<dim3(64, NVB), 512>>>();
        k_col_fwd<0><<<dim3(64, NPAIR), 512>>>(nullptr);
        k_rowpair<<<dim3(129, NPAIR), 256>>>();
        k_col_inv<<<dim3(64, NPAIR), 512>>>(out);
    }
}

// round 12
// speedup vs baseline: 1.7068x; 1.1693x over previous
#include <cuda_runtime.h>
#include <math.h>

#define NEV   128
#define NPAIR 64
#define NSAMP 131072
#define NFFT  262144
#define NFR   128
#define WINL  1024
#define CPD   16
#define NCP   512
#define NVO   8
#define NVB   16
#define HID   128
#define KSP   128
#define LSTR  578

__device__ float2 g_twtab[1024];                     // [0:512) W512^k ; [512:1024) W_N^k
__device__ float2 g_spec[(size_t)NPAIR * NFFT];      // 128 MB packed spectra
__device__ float2 g_vspec[(size_t)NVB * NFFT];       // 32 MB verb spectra
__device__ float  g_sig[(size_t)NEV * NSAMP];
__device__ float  g_hs[(size_t)NEV * NFR * HID];
__device__ float  g_ctrl[NEV * NFR * CPD];
__device__ float  g_M[NVO * HID * CPD];
__device__ int    g_vidx[NEV], g_ridx[NEV], g_shift[NEV];
__device__ float  g_m0[NEV], g_m1[NEV], g_amp[NEV];
__device__ int    g_pairA[257], g_pairB[257];

__device__ __forceinline__ int skew(int i){ return i + (i >> 3); }
__device__ __forceinline__ float2 cadd(float2 a, float2 b){ return make_float2(a.x+b.x, a.y+b.y); }
__device__ __forceinline__ float2 csub(float2 a, float2 b){ return make_float2(a.x-b.x, a.y-b.y); }
__device__ __forceinline__ float2 cmul(float2 a, float2 b){ return make_float2(a.x*b.x - a.y*b.y, a.x*b.y + a.y*b.x); }
__device__ __forceinline__ float2 cmulc(float2 a, float2 b){ return make_float2(a.x*b.x + a.y*b.y, a.y*b.x - a.x*b.y); }
__device__ __forceinline__ int rev9(int p){ return ((p & 7) << 6) | (p & 56) | (p >> 6); }

__device__ __forceinline__ float2 twN(int idx){
    int k = idx & (NFFT - 1);
    return cmul(g_twtab[k >> 9], g_twtab[512 + (k & 511)]);
}

template<bool INV>
__device__ __forceinline__ float2 mulmi(float2 a){
    return INV ? make_float2(-a.y, a.x) : make_float2(a.y, -a.x);
}

template<bool INV>
__device__ __forceinline__ void dft8(float2* v){
    float2 t0 = cadd(v[0], v[4]), t1 = csub(v[0], v[4]);
    float2 t2 = cadd(v[2], v[6]), t3 = mulmi<INV>(csub(v[2], v[6]));
    float2 t4 = cadd(v[1], v[5]), t5 = csub(v[1], v[5]);
    float2 t6 = cadd(v[3], v[7]), t7 = mulmi<INV>(csub(v[3], v[7]));
    float2 a0 = cadd(t0, t2), a2 = csub(t0, t2);
    float2 a1 = cadd(t1, t3), a3 = csub(t1, t3);
    float2 b0 = cadd(t4, t6), b2 = csub(t4, t6);
    float2 b1 = cadd(t5, t7), b3 = csub(t5, t7);
    const float r = 0.70710678118654752440f;
    float2 w1 = INV ? make_float2(r,  r) : make_float2(r, -r);
    float2 w3 = INV ? make_float2(-r, r) : make_float2(-r, -r);
    b1 = cmul(b1, w1); b2 = mulmi<INV>(b2); b3 = cmul(b3, w3);
    v[0] = cadd(a0, b0); v[4] = csub(a0, b0);
    v[1] = cadd(a1, b1); v[5] = csub(a1, b1);
    v[2] = cadd(a2, b2); v[6] = csub(a2, b2);
    v[3] = cadd(a3, b3); v[7] = csub(a3, b3);
}

// apply twiddles w1^m to v[1..7] via recurrence (1 table value, 6 extra cmuls)
__device__ __forceinline__ void twid_fwd(float2* v, float2 w1){
    float2 wm = w1;
    v[1] = cmul(v[1], wm);
    #pragma unroll
    for(int m = 2; m < 8; m++){ wm = cmul(wm, w1); v[m] = cmul(v[m], wm); }
}
__device__ __forceinline__ void twid_inv(float2* v, float2 w1){
    float2 wm = w1;
    v[1] = cmulc(v[1], wm);
    #pragma unroll
    for(int m = 2; m < 8; m++){ wm = cmul(wm, w1); v[m] = cmulc(v[m], wm); }
}

// DIF 512 = radix-8^3, natural in -> octal-digit-reversed out.
// ZTOP: input rows [256,512) are structural zeros (not staged in smem).
template<bool ZTOP>
__device__ __forceinline__ void dif512t(float2* L, int t){
    float2 v[8];
    if(ZTOP){
        #pragma unroll
        for(int m = 0; m < 4; m++) v[m] = L[skew(t + 64*m)];
        #pragma unroll
        for(int m = 4; m < 8; m++) v[m] = make_float2(0.f, 0.f);
    } else {
        #pragma unroll
        for(int m = 0; m < 8; m++) v[m] = L[skew(t + 64*m)];
    }
    dft8<false>(v);
    twid_fwd(v, g_twtab[t]);
    #pragma unroll
    for(int m = 0; m < 8; m++) L[skew(t + 64*m)] = v[m];
    __syncthreads();
    int base = (t >> 3) << 6, j = t & 7;
    #pragma unroll
    for(int m = 0; m < 8; m++) v[m] = L[skew(base + j + 8*m)];
    dft8<false>(v);
    twid_fwd(v, g_twtab[j << 3]);
    #pragma unroll
    for(int m = 0; m < 8; m++) L[skew(base + j + 8*m)] = v[m];
    __syncthreads();
    base = t << 3;
    #pragma unroll
    for(int m = 0; m < 8; m++) v[m] = L[skew(base + m)];
    dft8<false>(v);
    #pragma unroll
    for(int m = 0; m < 8; m++) L[skew(base + m)] = v[m];
}

// DIT 512: digit-reversed in -> natural out, conjugate twiddles (unscaled inverse).
__device__ __forceinline__ void dit512(float2* L, int t){
    float2 v[8];
    int base = t << 3;
    #pragma unroll
    for(int m = 0; m < 8; m++) v[m] = L[skew(base + m)];
    dft8<true>(v);
    #pragma unroll
    for(int m = 0; m < 8; m++) L[skew(base + m)] = v[m];
    __syncthreads();
    base = (t >> 3) << 6; int j = t & 7;
    #pragma unroll
    for(int m = 0; m < 8; m++) v[m] = L[skew(base + j + 8*m)];
    twid_inv(v, g_twtab[j << 3]);
    dft8<true>(v);
    #pragma unroll
    for(int m = 0; m < 8; m++) L[skew(base + j + 8*m)] = v[m];
    __syncthreads();
    #pragma unroll
    for(int m = 0; m < 8; m++) v[m] = L[skew(t + 64*m)];
    twid_inv(v, g_twtab[t]);
    dft8<true>(v);
    #pragma unroll
    for(int m = 0; m < 8; m++) L[skew(t + 64*m)] = v[m];
}

__global__ void k_twtab(){
    int k = blockIdx.x * blockDim.x + threadIdx.x;
    if(k < 1024){
        double a;
        if(k < 512) a = -6.283185307179586476925286766559 * (double)k / 512.0;
        else        a = -6.283185307179586476925286766559 * (double)(k - 512) / (double)NFFT;
        double s, c; sincos(a, &s, &c);
        g_twtab[k] = make_float2((float)c, (float)s);
    }
    if(k == 0){
        int cnt = 0;
        for(int p = 0; p < 512; p++){
            int k1 = rev9(p);
            int pp = rev9((512 - k1) & 511);
            if(p <= pp){ g_pairA[cnt] = p; g_pairB[cnt] = pp; cnt++; }
        }
    }
}

__global__ __launch_bounds__(256) void k_prep(
    const float* __restrict__ voice, const float* __restrict__ cpc,
    const float* __restrict__ amp,   const float* __restrict__ room,
    const float* __restrict__ mix,   const float* __restrict__ times,
    const float* __restrict__ cp_table)
{
    int n = blockIdx.x, tid = threadIdx.x;
    __shared__ float sv[256];
    __shared__ int   si[256];
    __shared__ int   s_cidx, s_cnt;

    float best = -1e30f; int bi = 0;
    for(int j = tid; j < NCP; j += 256){
        float v = cpc[n*NCP + j];
        if(v > best){ best = v; bi = j; }
    }
    sv[tid] = best; si[tid] = bi; __syncthreads();
    for(int s = 128; s > 0; s >>= 1){
        if(tid < s){
            if(sv[tid+s] > sv[tid] || (sv[tid+s] == sv[tid] && si[tid+s] < si[tid])){
                sv[tid] = sv[tid+s]; si[tid] = si[tid+s];
            }
        }
        __syncthreads();
    }
    if(tid == 0){
        s_cidx = si[0];
        float b = -1e30f; int ii = 0;
        for(int j = 0; j < NFR; j++){ float v = times[n*NFR + j]; if(v > b){ b = v; ii = j; } }
        g_shift[n] = ii * (NSAMP / NFR);
        b = -1e30f; ii = 0;
        for(int j = 0; j < NVO; j++){ float v = voice[n*NVO + j]; if(v > b){ b = v; ii = j; } }
        g_vidx[n] = ii;
        b = -1e30f; ii = 0;
        for(int j = 0; j < NVB; j++){ float v = room[n*NVB + j]; if(v > b){ b = v; ii = j; } }
        g_ridx[n] = ii;
        float x0 = mix[n*2], x1 = mix[n*2 + 1];
        float mm = fmaxf(x0, x1);
        float e0 = expf(x0 - mm), e1 = expf(x1 - mm);
        g_m0[n] = e0 / (e0 + e1);
        g_m1[n] = e1 / (e0 + e1);
        g_amp[n] = fabsf(amp[n]);
    }
    __syncthreads();

    const float* row = cp_table + (size_t)s_cidx * (NFR*CPD);
    float rv[8];
    #pragma unroll
    for(int j = 0; j < 8; j++) rv[j] = row[tid + 256*j];
    unsigned lo = 0u, hi = 0x7F800000u;
    while(hi - lo > 1u){
        unsigned mid = lo + ((hi - lo) >> 1);
        int c = 0;
        #pragma unroll
        for(int j = 0; j < 8; j++) c += (__float_as_uint(rv[j]) >= mid) ? 1 : 0;
        si[tid] = c; __syncthreads();
        for(int s = 128; s > 0; s >>= 1){
            if(tid < s) si[tid] += si[tid+s];
            __syncthreads();
        }
        if(tid == 0) s_cnt = si[0];
        __syncthreads();
        if(s_cnt >= KSP) lo = mid; else hi = mid;
    }
    for(int idx = tid; idx < NFR*CPD; idx += 256){
        int f = idx >> 4, c = idx & 15;
        float v = row[c*NFR + f];
        float keep = (__float_as_uint(v) >= lo) ? v : 0.f;
        g_ctrl[n*NFR*CPD + idx] = fmaxf(keep, 0.f);
    }
}

// M[v] = W_ih[v] @ W_in[v] — parallel Kahan-fp32 split-K
__global__ __launch_bounds__(128) void k_collapse(
    const float* __restrict__ w_ih, const float* __restrict__ w_in)
{
    int blk = blockIdx.x;
    int v = blk >> 7, i = blk & 127;
    int t = threadIdx.x;
    const float* wr = w_ih + ((size_t)v*HID + i) * WINL;
    const float* wc = w_in + (size_t)v*WINL*CPD;
    float s[CPD], comp[CPD];
    #pragma unroll
    for(int c = 0; c < CPD; c++){ s[c] = 0.f; comp[c] = 0.f; }
    for(int k = t; k < WINL; k += 128){
        float a = wr[k];
        const float4* p = (const float4*)(wc + (size_t)k*CPD);
        float4 q[4] = {p[0], p[1], p[2], p[3]};
        const float* qs = (const float*)q;
        #pragma unroll
        for(int c = 0; c < CPD; c++){
            float y = fmaf(a, qs[c], -comp[c]);
            float tt = s[c] + y;
            comp[c] = (tt - s[c]) - y;
            s[c] = tt;
        }
    }
    __shared__ float red[128 * CPD];
    #pragma unroll
    for(int c = 0; c < CPD; c++) red[t*CPD + c] = s[c];
    __syncthreads();
    for(int st = 64; st > 0; st >>= 1){
        if(t < st){
            #pragma unroll
            for(int c = 0; c < CPD; c++) red[t*CPD + c] += red[(t+st)*CPD + c];
        }
        __syncthreads();
    }
    if(t < CPD) g_M[(v*HID + i)*CPD + t] = red[t];
}

// overflow-safe fast tanh: 1 - 2e/(1+e), e = exp(-2|x|); e<=1 so no overflow
__device__ __forceinline__ float ftanh(float x){
    float ax = fabsf(x);
    float e = __expf(-2.f*ax);
    float th = 1.f - 2.f*e/(1.f + e);
    return copysignf(th, x);
}

// persistent RNN: one block per event
__global__ __launch_bounds__(256) void k_rnn(const float* __restrict__ w_hh){
    int n = blockIdx.x, t = threadIdx.x;
    int i = t & 127, half = t >> 7;
    int v = g_vidx[n];
    __shared__ float ctrl_s[NFR*CPD];
    __shared__ float h_s[HID];
    __shared__ float part_s[256];

    float W[64];
    const float* wh = w_hh + ((size_t)v*HID + i) * HID + half*64;
    #pragma unroll
    for(int k = 0; k < 64; k++) W[k] = wh[k];
    float M[CPD];
    const float* mp = g_M + (v*HID + i)*CPD;
    #pragma unroll
    for(int c = 0; c < CPD; c++) M[c] = mp[c];
    for(int idx = t; idx < NFR*CPD; idx += 256) ctrl_s[idx] = g_ctrl[n*NFR*CPD + idx];
    if(t < HID) h_s[t] = 0.f;
    __syncthreads();

    float* hsout = g_hs + (size_t)n*NFR*HID;
    for(int f = 0; f < NFR; f++){
        const float* hb = h_s + half*64;
        float p0 = 0.f, p1 = 0.f, p2 = 0.f, p3 = 0.f;
        #pragma unroll
        for(int k = 0; k < 64; k += 4){
            p0 = fmaf(W[k],   hb[k],   p0);
            p1 = fmaf(W[k+1], hb[k+1], p1);
            p2 = fmaf(W[k+2], hb[k+2], p2);
            p3 = fmaf(W[k+3], hb[k+3], p3);
        }
        float inp = 0.f;
        if(half == 0){
            const float* cf = ctrl_s + f*CPD;
            float i0 = 0.f, i1 = 0.f;
            #pragma unroll
            for(int c = 0; c < CPD; c += 2){
                i0 = fmaf(M[c],   cf[c],   i0);
                i1 = fmaf(M[c+1], cf[c+1], i1);
            }
            inp = i0 + i1;
        }
        part_s[t] = (p0 + p1) + (p2 + p3);
        __syncthreads();
        if(half == 0){
            float h = ftanh(part_s[t] + part_s[t + 128] + inp);
            h_s[i] = h;
            hsout[f*HID + i] = h;
        }
        __syncthreads();
    }
}

// sig[f,w] = sin( hs[f,:] . w_out[v,w,:] ) — fp32 register-tiled GEMM, fast-sin epilogue
__global__ __launch_bounds__(256) void k_wout(const float* __restrict__ w_out){
    int wt = blockIdx.x, n = blockIdx.y, t = threadIdx.x;
    int v = g_vidx[n];
    const float* A  = g_hs + (size_t)n*NFR*HID;
    const float* Bm = w_out + (size_t)v*WINL*HID + (size_t)wt*128*HID;
    __shared__ float As[32*132];
    __shared__ float Bs[32*132];
    int tx = t & 15, ty = t >> 4;
    int f0 = ty*8, w0 = tx*8;
    float acc[8][8];
    #pragma unroll
    for(int i = 0; i < 8; i++)
        #pragma unroll
        for(int j = 0; j < 8; j++) acc[i][j] = 0.f;

    for(int ks = 0; ks < 4; ks++){
        int k0 = ks*32;
        #pragma unroll
        for(int r = 0; r < 4; r++){
            int idx4 = t + 256*r;
            int rr = idx4 >> 3, kk4 = idx4 & 7;
            float4 va = *(const float4*)(A  + (size_t)rr*HID + k0 + kk4*4);
            float4 vb = *(const float4*)(Bm + (size_t)rr*HID + k0 + kk4*4);
            As[(kk4*4+0)*132 + rr] = va.x; As[(kk4*4+1)*132 + rr] = va.y;
            As[(kk4*4+2)*132 + rr] = va.z; As[(kk4*4+3)*132 + rr] = va.w;
            Bs[(kk4*4+0)*132 + rr] = vb.x; Bs[(kk4*4+1)*132 + rr] = vb.y;
            Bs[(kk4*4+2)*132 + rr] = vb.z; Bs[(kk4*4+3)*132 + rr] = vb.w;
        }
        __syncthreads();
        #pragma unroll
        for(int k = 0; k < 32; k++){
            float4 a0 = *(const float4*)&As[k*132 + f0];
            float4 a1 = *(const float4*)&As[k*132 + f0 + 4];
            float4 b0 = *(const float4*)&Bs[k*132 + w0];
            float4 b1 = *(const float4*)&Bs[k*132 + w0 + 4];
            float a[8] = {a0.x,a0.y,a0.z,a0.w,a1.x,a1.y,a1.z,a1.w};
            float b[8] = {b0.x,b0.y,b0.z,b0.w,b1.x,b1.y,b1.z,b1.w};
            #pragma unroll
            for(int i = 0; i < 8; i++)
                #pragma unroll
                for(int j = 0; j < 8; j++) acc[i][j] += a[i]*b[j];
        }
        __syncthreads();
    }
    float* out = g_sig + (size_t)n*NSAMP + wt*128;
    #pragma unroll
    for(int i = 0; i < 8; i++)
        #pragma unroll
        for(int j = 0; j < 8; j++)
            out[(size_t)(f0+i)*WINL + w0 + j] = __sinf(acc[i][j]);
}

// F1 column pass (forward). VERB=1: real verb -> g_vspec. VERB=0: packed pair of sigs -> g_spec.
// Epilogue twiddle via linear recurrence: rev9(r0+64q) = rev9(r0)+q.
template<int VERB>
__global__ __launch_bounds__(512) void k_col_fwd(const float* __restrict__ rin_ext){
    __shared__ float2 s[8*LSTR];
    int y = blockIdx.y, col0 = blockIdx.x*8, tid = threadIdx.x;
    const float* sa; const float* sb = nullptr; float2* dst;
    if(VERB){ sa = rin_ext + (size_t)y*NSAMP;        dst = g_vspec + (size_t)y*NFFT; }
    else    { sa = g_sig + (size_t)(2*y)*NSAMP; sb = g_sig + (size_t)(2*y+1)*NSAMP;
              dst = g_spec + (size_t)y*NFFT; }
    for(int idx = tid; idx < 2048; idx += 512){
        int r = idx >> 3, c = idx & 7;
        int o = r*512 + col0 + c;
        float re = sa[o];
        float im = VERB ? 0.f : sb[o];
        s[c*LSTR + skew(r)] = make_float2(re, im);
    }
    __syncthreads();
    dif512t<true>(&s[(tid >> 6)*LSTR], tid & 63);
    __syncthreads();
    {
        int r0 = tid >> 3, c = tid & 7;
        int n2 = col0 + c;
        float2 w = twN(rev9(r0) * n2);
        float2 wstep = twN(n2);
        #pragma unroll
        for(int q = 0; q < 8; q++){
            int r = r0 + 64*q;
            dst[(size_t)r*512 + n2] = cmul(s[c*LSTR + skew(r)], w);
            w = cmul(w, wstep);
        }
    }
}

// F2 row pass for verb spectra — direct global in (stage 1) and out (stage 3).
__global__ __launch_bounds__(512) void k_row_verb(){
    __shared__ float2 s[8*LSTR];
    int n = blockIdx.y, row0 = blockIdx.x*8, tid = threadIdx.x;
    int line = tid >> 6, t = tid & 63;
    float2* base = g_vspec + (size_t)n*NFFT + (size_t)row0*512;
    float2* grow = base + (size_t)line*512;
    float2* L = s + line*LSTR;
    float2 v[8];
    #pragma unroll
    for(int m = 0; m < 8; m++) v[m] = grow[t + 64*m];
    dft8<false>(v);
    twid_fwd(v, g_twtab[t]);
    #pragma unroll
    for(int m = 0; m < 8; m++) L[skew(t + 64*m)] = v[m];
    __syncthreads();
    int b2 = (t >> 3) << 6, j = t & 7;
    #pragma unroll
    for(int m = 0; m < 8; m++) v[m] = L[skew(b2 + j + 8*m)];
    dft8<false>(v);
    twid_fwd(v, g_twtab[j << 3]);
    #pragma unroll
    for(int m = 0; m < 8; m++) L[skew(b2 + j + 8*m)] = v[m];
    __syncthreads();
    int b3 = t << 3;
    #pragma unroll
    for(int m = 0; m < 8; m++) v[m] = L[skew(b3 + m)];
    dft8<false>(v);
    #pragma unroll
    for(int m = 0; m < 8; m++) grow[b3 + m] = v[m];
}

__device__ __forceinline__ int pzero(int e){   // partner col for the k1==0 row
    int k2 = rev9(e);
    return rev9((512 - k2) & 511);
}

// Fused: F2 + conj-unpack + spectral mul (verb+dry fold, 1/N) + repack + I1 + conj twiddle.
// Direct-global stage-1 in and stage-3 out; tail twN via linear recurrence (step W_N^{64 k1}).
__global__ __launch_bounds__(256) void k_rowpair(){
    __shared__ float2 s[4*LSTR];
    int p = blockIdx.y;
    int grp = threadIdx.x >> 7;
    int lt  = threadIdx.x & 127;
    int slot = blockIdx.x*2 + grp; if(slot > 256) slot = 256;
    int rows0 = g_pairA[slot], rows1 = g_pairB[slot];
    int line = lt >> 6, t = lt & 63;
    int myrow = line ? rows1 : rows0;
    float2* base = g_spec + (size_t)p*NFFT;
    float2* sg = s + (2*grp)*LSTR;
    float2* L  = sg + line*LSTR;
    float2* grow = base + (size_t)myrow*512;
    float2 v[8];

    // F2 stage 1: direct global in
    #pragma unroll
    for(int m = 0; m < 8; m++) v[m] = grow[t + 64*m];
    dft8<false>(v);
    twid_fwd(v, g_twtab[t]);
    #pragma unroll
    for(int m = 0; m < 8; m++) L[skew(t + 64*m)] = v[m];
    __syncthreads();
    // F2 stage 2
    int b2 = (t >> 3) << 6, j = t & 7;
    #pragma unroll
    for(int m = 0; m < 8; m++) v[m] = L[skew(b2 + j + 8*m)];
    dft8<false>(v);
    twid_fwd(v, g_twtab[j << 3]);
    #pragma unroll
    for(int m = 0; m < 8; m++) L[skew(b2 + j + 8*m)] = v[m];
    __syncthreads();
    // F2 stage 3 -> smem (unpack needs full lines)
    int b3 = t << 3;
    #pragma unroll
    for(int m = 0; m < 8; m++) v[m] = L[skew(b3 + m)];
    dft8<false>(v);
    #pragma unroll
    for(int m = 0; m < 8; m++) L[skew(b3 + m)] = v[m];
    __syncthreads();

    // conj-unpack + spectral multiply (verb + dry folded) + repack
    int na = 2*p, nb = 2*p + 1;
    const float2* va = g_vspec + (size_t)g_ridx[na]*NFFT;
    const float2* vb = g_vspec + (size_t)g_ridx[nb]*NFFT;
    float m0a = g_m0[na], m1a = g_m1[na], m0b = g_m0[nb], m1b = g_m1[nb];
    const float invN = 1.f / (float)NFFT;

    float2 Z[8], Zp[8];
    #pragma unroll
    for(int q = 0; q < 8; q++){
        int idx = lt + 128*q;
        int l = idx >> 9, e = idx & 511;
        int row = l ? rows1 : rows0;
        int k1 = rev9(row);
        int ep = (k1 == 0) ? pzero(e) : (511 - e);
        Z[q]  = sg[l*LSTR + skew(e)];
        Zp[q] = sg[(1 - l)*LSTR + skew(ep)];
    }
    __syncthreads();
    #pragma unroll
    for(int q = 0; q < 8; q++){
        int idx = lt + 128*q;
        int l = idx >> 9, e = idx & 511;
        int row = l ? rows1 : rows0;
        float2 S1 = make_float2(0.5f*(Z[q].x + Zp[q].x), 0.5f*(Z[q].y - Zp[q].y));
        float2 S2 = make_float2(0.5f*(Z[q].y + Zp[q].y), -0.5f*(Z[q].x - Zp[q].x));
        float2 V1 = va[(size_t)row*512 + e];
        float2 V2 = vb[(size_t)row*512 + e];
        float2 M1 = make_float2(m0a*V1.x + m1a, m0a*V1.y);
        float2 M2 = make_float2(m0b*V2.x + m1b, m0b*V2.y);
        float2 W1 = cmul(S1, M1), W2 = cmul(S2, M2);
        sg[l*LSTR + skew(e)] = make_float2((W1.x - W2.y)*invN, (W1.y + W2.x)*invN);
    }
    __syncthreads();

    // I1 (DIT) stage 1
    #pragma unroll
    for(int m = 0; m < 8; m++) v[m] = L[skew(b3 + m)];
    dft8<true>(v);
    #pragma unroll
    for(int m = 0; m < 8; m++) L[skew(b3 + m)] = v[m];
    __syncthreads();
    // I1 stage 2
    #pragma unroll
    for(int m = 0; m < 8; m++) v[m] = L[skew(b2 + j + 8*m)];
    twid_inv(v, g_twtab[j << 3]);
    dft8<true>(v);
    #pragma unroll
    for(int m = 0; m < 8; m++) L[skew(b2 + j + 8*m)] = v[m];
    __syncthreads();
    // I1 stage 3 + conj inter-pass twiddle -> direct global out (recurrence)
    #pragma unroll
    for(int m = 0; m < 8; m++) v[m] = L[skew(t + 64*m)];
    twid_inv(v, g_twtab[t]);
    dft8<true>(v);
    {
        int k1 = rev9(myrow);
        float2 w = twN(k1 * t);
        float2 wstep = twN(k1 << 6);
        #pragma unroll
        for(int m = 0; m < 8; m++){
            grow[t + 64*m] = cmulc(v[m], w);
            w = cmul(w, wstep);
        }
    }
}

// I2 column pass (inverse, packed) + epilogue: |amp| + dirac row-shift.
__global__ __launch_bounds__(512) void k_col_inv(float* __restrict__ out){
    __shared__ float2 s[8*LSTR];
    int p = blockIdx.y, col0 = blockIdx.x*8, tid = threadIdx.x;
    const float2* src = g_spec + (size_t)p*NFFT;
    for(int idx = tid; idx < 4096; idx += 512){
        int r = idx >> 3, c = idx & 7;
        s[c*LSTR + skew(r)] = src[(size_t)r*512 + col0 + c];
    }
    __syncthreads();
    dit512(&s[(tid >> 6)*LSTR], tid & 63);
    __syncthreads();
    int na = 2*p, nb = 2*p + 1;
    float aA = g_amp[na], aB = g_amp[nb];
    int dA = g_shift[na] >> 9, dB = g_shift[nb] >> 9;
    float* oA = out + (size_t)na*NSAMP;
    float* oB = out + (size_t)nb*NSAMP;
    for(int idx = tid; idx < 2048; idx += 512){
        int rp = idx >> 3, c = idx & 7;
        int col = col0 + c;
        int ra = rp - dA;
        oA[rp*512 + col] = (ra >= 0) ? s[c*LSTR + skew(ra)].x * aA : 0.f;
        int rb = rp - dB;
        oB[rp*512 + col] = (rb >= 0) ? s[c*LSTR + skew(rb)].y * aB : 0.f;
    }
}

extern "C" void kernel_launch(void* const* d_in, const int* in_sizes, int n_in,
                              void* d_out, int out_size) {
    const float* voice = (const float*)d_in[0];
    const float* cpc   = (const float*)d_in[1];
    const float* amp   = (const float*)d_in[2];
    const float* room  = (const float*)d_in[3];
    const float* mix   = (const float*)d_in[4];
    const float* times = (const float*)d_in[5];
    const float* cp_table = (const float*)d_in[6];
    const float* verbs = (const float*)d_in[7];
    const float* w_in  = (const float*)d_in[8];
    const float* w_ih  = (const float*)d_in[9];
    const float* w_hh  = (const float*)d_in[10];
    const float* w_out = (const float*)d_in[11];
    float* out = (float*)d_out;

    static cudaStream_t s_side = 0;
    static cudaEvent_t  ev_fork = 0, ev_coll = 0, ev_join = 0;
    static int s_init = 0;
    if(!s_init){
        if(cudaStreamCreateWithFlags(&s_side, cudaStreamNonBlocking) != cudaSuccess) s_side = 0;
        if(s_side){
            if(cudaEventCreateWithFlags(&ev_fork, cudaEventDisableTiming) != cudaSuccess ||
               cudaEventCreateWithFlags(&ev_coll, cudaEventDisableTiming) != cudaSuccess ||
               cudaEventCreateWithFlags(&ev_join, cudaEventDisableTiming) != cudaSuccess){
                s_side = 0;
            }
        }
        s_init = 1;
    }

    k_twtab<<<2, 512>>>();
    if(s_side){
        cudaEventRecord(ev_fork, 0);
        cudaStreamWaitEvent(s_side, ev_fork, 0);
        k_collapse<<<NVO*HID, 128, 0, s_side>>>(w_ih, w_in);
        cudaEventRecord(ev_coll, s_side);
        k_col_fwd<1><<<dim3(64, NVB), 512, 0, s_side>>>(verbs);
        k_row_verb<<<dim3(64, NVB), 512, 0, s_side>>>();
        cudaEventRecord(ev_join, s_side);
        k_prep<<<NEV, 256>>>(voice, cpc, amp, room, mix, times, cp_table);
        cudaStreamWaitEvent(0, ev_coll, 0);
        k_rnn<<<NEV, 256>>>(w_hh);
        k_wout<<<dim3(8, NEV), 256>>>(w_out);
        k_col_fwd<0><<<dim3(64, NPAIR), 512>>>(nullptr);
        cudaStreamWaitEvent(0, ev_join, 0);
        k_rowpair<<<dim3(129, NPAIR), 256>>>();
        k_col_inv<<<dim3(64, NPAIR), 512>>>(out);
    } else {
        k_prep<<<NEV, 256>>>(voice, cpc, amp, room, mix, times, cp_table);
        k_collapse<<<NVO*HID, 128>>>(w_ih, w_in);
        k_rnn<<<NEV, 256>>>(w_hh);
        k_wout<<<dim3(8, NEV), 256>>>(w_out);
        k_col_fwd<1><<<dim3(64, NVB), 512>>>(verbs);
        k_row_verb<<<dim3(64, NVB), 512>>>();
        k_col_fwd<0><<<dim3(64, NPAIR), 512>>>(nullptr);
        k_rowpair<<<dim3(129, NPAIR), 256>>>();
        k_col_inv<<<dim3(64, NPAIR), 512>>>(out);
    }
}

// round 13
// speedup vs baseline: 1.7715x; 1.0379x over previous
#include <cuda_runtime.h>
#include <math.h>

#define NEV   128
#define NPAIR 64
#define NSAMP 131072
#define NFFT  262144
#define NFR   128
#define WINL  1024
#define CPD   16
#define NCP   512
#define NVO   8
#define NVB   16
#define HID   128
#define KSP   128
#define LSTR  578

__device__ float2 g_twtab[1024];                     // [0:512) W512^k ; [512:1024) W_N^k
__device__ float2 g_spec[(size_t)NPAIR * NFFT];      // 128 MB packed spectra
__device__ float2 g_vspec[(size_t)NVB * NFFT];       // 32 MB verb spectra
__device__ float  g_sig[(size_t)NEV * NSAMP];
__device__ float  g_hs[(size_t)NEV * NFR * HID];
__device__ float  g_ctrl[NEV * NFR * CPD];
__device__ float  g_M[NVO * HID * CPD];
__device__ int    g_vidx[NEV], g_ridx[NEV], g_shift[NEV];
__device__ float  g_m0[NEV], g_m1[NEV], g_amp[NEV];
__device__ int    g_pairA[257], g_pairB[257];

__device__ __forceinline__ int skew(int i){ return i + (i >> 3); }
__device__ __forceinline__ float2 cadd(float2 a, float2 b){ return make_float2(a.x+b.x, a.y+b.y); }
__device__ __forceinline__ float2 csub(float2 a, float2 b){ return make_float2(a.x-b.x, a.y-b.y); }
__device__ __forceinline__ float2 cmul(float2 a, float2 b){ return make_float2(a.x*b.x - a.y*b.y, a.x*b.y + a.y*b.x); }
__device__ __forceinline__ float2 cmulc(float2 a, float2 b){ return make_float2(a.x*b.x + a.y*b.y, a.y*b.x - a.x*b.y); }
__device__ __forceinline__ int rev9(int p){ return ((p & 7) << 6) | (p & 56) | (p >> 6); }

__device__ __forceinline__ float2 twN(int idx){
    int k = idx & (NFFT - 1);
    return cmul(g_twtab[k >> 9], g_twtab[512 + (k & 511)]);
}

template<bool INV>
__device__ __forceinline__ float2 mulmi(float2 a){
    return INV ? make_float2(-a.y, a.x) : make_float2(a.y, -a.x);
}

template<bool INV>
__device__ __forceinline__ void dft8(float2* v){
    float2 t0 = cadd(v[0], v[4]), t1 = csub(v[0], v[4]);
    float2 t2 = cadd(v[2], v[6]), t3 = mulmi<INV>(csub(v[2], v[6]));
    float2 t4 = cadd(v[1], v[5]), t5 = csub(v[1], v[5]);
    float2 t6 = cadd(v[3], v[7]), t7 = mulmi<INV>(csub(v[3], v[7]));
    float2 a0 = cadd(t0, t2), a2 = csub(t0, t2);
    float2 a1 = cadd(t1, t3), a3 = csub(t1, t3);
    float2 b0 = cadd(t4, t6), b2 = csub(t4, t6);
    float2 b1 = cadd(t5, t7), b3 = csub(t5, t7);
    const float r = 0.70710678118654752440f;
    float2 w1 = INV ? make_float2(r,  r) : make_float2(r, -r);
    float2 w3 = INV ? make_float2(-r, r) : make_float2(-r, -r);
    b1 = cmul(b1, w1); b2 = mulmi<INV>(b2); b3 = cmul(b3, w3);
    v[0] = cadd(a0, b0); v[4] = csub(a0, b0);
    v[1] = cadd(a1, b1); v[5] = csub(a1, b1);
    v[2] = cadd(a2, b2); v[6] = csub(a2, b2);
    v[3] = cadd(a3, b3); v[7] = csub(a3, b3);
}

// apply twiddles w1^m to v[1..7] via recurrence (1 table value, 6 extra cmuls)
__device__ __forceinline__ void twid_fwd(float2* v, float2 w1){
    float2 wm = w1;
    v[1] = cmul(v[1], wm);
    #pragma unroll
    for(int m = 2; m < 8; m++){ wm = cmul(wm, w1); v[m] = cmul(v[m], wm); }
}
__device__ __forceinline__ void twid_inv(float2* v, float2 w1){
    float2 wm = w1;
    v[1] = cmulc(v[1], wm);
    #pragma unroll
    for(int m = 2; m < 8; m++){ wm = cmul(wm, w1); v[m] = cmulc(v[m], wm); }
}

// DIF 512 = radix-8^3, natural in -> octal-digit-reversed out.
// ZTOP: input rows [256,512) are structural zeros (not staged in smem).
template<bool ZTOP>
__device__ __forceinline__ void dif512t(float2* L, int t){
    float2 v[8];
    if(ZTOP){
        #pragma unroll
        for(int m = 0; m < 4; m++) v[m] = L[skew(t + 64*m)];
        #pragma unroll
        for(int m = 4; m < 8; m++) v[m] = make_float2(0.f, 0.f);
    } else {
        #pragma unroll
        for(int m = 0; m < 8; m++) v[m] = L[skew(t + 64*m)];
    }
    dft8<false>(v);
    twid_fwd(v, g_twtab[t]);
    #pragma unroll
    for(int m = 0; m < 8; m++) L[skew(t + 64*m)] = v[m];
    __syncthreads();
    int base = (t >> 3) << 6, j = t & 7;
    #pragma unroll
    for(int m = 0; m < 8; m++) v[m] = L[skew(base + j + 8*m)];
    dft8<false>(v);
    twid_fwd(v, g_twtab[j << 3]);
    #pragma unroll
    for(int m = 0; m < 8; m++) L[skew(base + j + 8*m)] = v[m];
    __syncthreads();
    base = t << 3;
    #pragma unroll
    for(int m = 0; m < 8; m++) v[m] = L[skew(base + m)];
    dft8<false>(v);
    #pragma unroll
    for(int m = 0; m < 8; m++) L[skew(base + m)] = v[m];
}

// DIT 512: digit-reversed in -> natural out, conjugate twiddles (unscaled inverse).
// HALF: store only natural outputs < 256 (last stage m<4); rows >=256 stale.
template<bool HALF>
__device__ __forceinline__ void dit512t(float2* L, int t){
    float2 v[8];
    int base = t << 3;
    #pragma unroll
    for(int m = 0; m < 8; m++) v[m] = L[skew(base + m)];
    dft8<true>(v);
    #pragma unroll
    for(int m = 0; m < 8; m++) L[skew(base + m)] = v[m];
    __syncthreads();
    base = (t >> 3) << 6; int j = t & 7;
    #pragma unroll
    for(int m = 0; m < 8; m++) v[m] = L[skew(base + j + 8*m)];
    twid_inv(v, g_twtab[j << 3]);
    dft8<true>(v);
    #pragma unroll
    for(int m = 0; m < 8; m++) L[skew(base + j + 8*m)] = v[m];
    __syncthreads();
    #pragma unroll
    for(int m = 0; m < 8; m++) v[m] = L[skew(t + 64*m)];
    twid_inv(v, g_twtab[t]);
    dft8<true>(v);
    #pragma unroll
    for(int m = 0; m < (HALF ? 4 : 8); m++) L[skew(t + 64*m)] = v[m];
}

__global__ void k_twtab(){
    int k = blockIdx.x * blockDim.x + threadIdx.x;
    if(k < 1024){
        double a;
        if(k < 512) a = -6.283185307179586476925286766559 * (double)k / 512.0;
        else        a = -6.283185307179586476925286766559 * (double)(k - 512) / (double)NFFT;
        double s, c; sincos(a, &s, &c);
        g_twtab[k] = make_float2((float)c, (float)s);
    }
    if(k == 0){
        int cnt = 0;
        for(int p = 0; p < 512; p++){
            int k1 = rev9(p);
            int pp = rev9((512 - k1) & 511);
            if(p <= pp){ g_pairA[cnt] = p; g_pairB[cnt] = pp; cnt++; }
        }
    }
}

__global__ __launch_bounds__(256) void k_prep(
    const float* __restrict__ voice, const float* __restrict__ cpc,
    const float* __restrict__ amp,   const float* __restrict__ room,
    const float* __restrict__ mix,   const float* __restrict__ times,
    const float* __restrict__ cp_table)
{
    int n = blockIdx.x, tid = threadIdx.x;
    __shared__ float sv[256];
    __shared__ int   si[256];
    __shared__ int   s_cidx, s_cnt;

    float best = -1e30f; int bi = 0;
    for(int j = tid; j < NCP; j += 256){
        float v = cpc[n*NCP + j];
        if(v > best){ best = v; bi = j; }
    }
    sv[tid] = best; si[tid] = bi; __syncthreads();
    for(int s = 128; s > 0; s >>= 1){
        if(tid < s){
            if(sv[tid+s] > sv[tid] || (sv[tid+s] == sv[tid] && si[tid+s] < si[tid])){
                sv[tid] = sv[tid+s]; si[tid] = si[tid+s];
            }
        }
        __syncthreads();
    }
    if(tid == 0){
        s_cidx = si[0];
        float b = -1e30f; int ii = 0;
        for(int j = 0; j < NFR; j++){ float v = times[n*NFR + j]; if(v > b){ b = v; ii = j; } }
        g_shift[n] = ii * (NSAMP / NFR);
        b = -1e30f; ii = 0;
        for(int j = 0; j < NVO; j++){ float v = voice[n*NVO + j]; if(v > b){ b = v; ii = j; } }
        g_vidx[n] = ii;
        b = -1e30f; ii = 0;
        for(int j = 0; j < NVB; j++){ float v = room[n*NVB + j]; if(v > b){ b = v; ii = j; } }
        g_ridx[n] = ii;
        float x0 = mix[n*2], x1 = mix[n*2 + 1];
        float mm = fmaxf(x0, x1);
        float e0 = expf(x0 - mm), e1 = expf(x1 - mm);
        g_m0[n] = e0 / (e0 + e1);
        g_m1[n] = e1 / (e0 + e1);
        g_amp[n] = fabsf(amp[n]);
    }
    __syncthreads();

    const float* row = cp_table + (size_t)s_cidx * (NFR*CPD);
    float rv[8];
    #pragma unroll
    for(int j = 0; j < 8; j++) rv[j] = row[tid + 256*j];
    unsigned lo = 0u, hi = 0x7F800000u;
    while(hi - lo > 1u){
        unsigned mid = lo + ((hi - lo) >> 1);
        int c = 0;
        #pragma unroll
        for(int j = 0; j < 8; j++) c += (__float_as_uint(rv[j]) >= mid) ? 1 : 0;
        si[tid] = c; __syncthreads();
        for(int s = 128; s > 0; s >>= 1){
            if(tid < s) si[tid] += si[tid+s];
            __syncthreads();
        }
        if(tid == 0) s_cnt = si[0];
        __syncthreads();
        if(s_cnt >= KSP) lo = mid; else hi = mid;
    }
    for(int idx = tid; idx < NFR*CPD; idx += 256){
        int f = idx >> 4, c = idx & 15;
        float v = row[c*NFR + f];
        float keep = (__float_as_uint(v) >= lo) ? v : 0.f;
        g_ctrl[n*NFR*CPD + idx] = fmaxf(keep, 0.f);
    }
}

// M[v] = W_ih[v] @ W_in[v] — parallel Kahan-fp32 split-K
__global__ __launch_bounds__(128) void k_collapse(
    const float* __restrict__ w_ih, const float* __restrict__ w_in)
{
    int blk = blockIdx.x;
    int v = blk >> 7, i = blk & 127;
    int t = threadIdx.x;
    const float* wr = w_ih + ((size_t)v*HID + i) * WINL;
    const float* wc = w_in + (size_t)v*WINL*CPD;
    float s[CPD], comp[CPD];
    #pragma unroll
    for(int c = 0; c < CPD; c++){ s[c] = 0.f; comp[c] = 0.f; }
    for(int k = t; k < WINL; k += 128){
        float a = wr[k];
        const float4* p = (const float4*)(wc + (size_t)k*CPD);
        float4 q[4] = {p[0], p[1], p[2], p[3]};
        const float* qs = (const float*)q;
        #pragma unroll
        for(int c = 0; c < CPD; c++){
            float y = fmaf(a, qs[c], -comp[c]);
            float tt = s[c] + y;
            comp[c] = (tt - s[c]) - y;
            s[c] = tt;
        }
    }
    __shared__ float red[128 * CPD];
    #pragma unroll
    for(int c = 0; c < CPD; c++) red[t*CPD + c] = s[c];
    __syncthreads();
    for(int st = 64; st > 0; st >>= 1){
        if(t < st){
            #pragma unroll
            for(int c = 0; c < CPD; c++) red[t*CPD + c] += red[(t+st)*CPD + c];
        }
        __syncthreads();
    }
    if(t < CPD) g_M[(v*HID + i)*CPD + t] = red[t];
}

// overflow-safe fast tanh: 1 - 2e/(1+e), e = exp(-2|x|); e<=1 so no overflow
__device__ __forceinline__ float ftanh(float x){
    float ax = fabsf(x);
    float e = __expf(-2.f*ax);
    float th = 1.f - 2.f*e/(1.f + e);
    return copysignf(th, x);
}

// persistent RNN: one block per event
__global__ __launch_bounds__(256) void k_rnn(const float* __restrict__ w_hh){
    int n = blockIdx.x, t = threadIdx.x;
    int i = t & 127, half = t >> 7;
    int v = g_vidx[n];
    __shared__ float ctrl_s[NFR*CPD];
    __shared__ float h_s[HID];
    __shared__ float part_s[256];

    float W[64];
    const float* wh = w_hh + ((size_t)v*HID + i) * HID + half*64;
    #pragma unroll
    for(int k = 0; k < 64; k++) W[k] = wh[k];
    float M[CPD];
    const float* mp = g_M + (v*HID + i)*CPD;
    #pragma unroll
    for(int c = 0; c < CPD; c++) M[c] = mp[c];
    for(int idx = t; idx < NFR*CPD; idx += 256) ctrl_s[idx] = g_ctrl[n*NFR*CPD + idx];
    if(t < HID) h_s[t] = 0.f;
    __syncthreads();

    float* hsout = g_hs + (size_t)n*NFR*HID;
    for(int f = 0; f < NFR; f++){
        const float* hb = h_s + half*64;
        float p0 = 0.f, p1 = 0.f, p2 = 0.f, p3 = 0.f;
        #pragma unroll
        for(int k = 0; k < 64; k += 4){
            p0 = fmaf(W[k],   hb[k],   p0);
            p1 = fmaf(W[k+1], hb[k+1], p1);
            p2 = fmaf(W[k+2], hb[k+2], p2);
            p3 = fmaf(W[k+3], hb[k+3], p3);
        }
        float inp = 0.f;
        if(half == 0){
            const float* cf = ctrl_s + f*CPD;
            float i0 = 0.f, i1 = 0.f;
            #pragma unroll
            for(int c = 0; c < CPD; c += 2){
                i0 = fmaf(M[c],   cf[c],   i0);
                i1 = fmaf(M[c+1], cf[c+1], i1);
            }
            inp = i0 + i1;
        }
        part_s[t] = (p0 + p1) + (p2 + p3);
        __syncthreads();
        if(half == 0){
            float h = ftanh(part_s[t] + part_s[t + 128] + inp);
            h_s[i] = h;
            hsout[f*HID + i] = h;
        }
        __syncthreads();
    }
}

// sig[f,w] = sin( hs[f,:] . w_out[v,w,:] ) — fp32 register-tiled GEMM, fast-sin epilogue
__global__ __launch_bounds__(256) void k_wout(const float* __restrict__ w_out, int n0){
    int wt = blockIdx.x, n = blockIdx.y + n0, t = threadIdx.x;
    int v = g_vidx[n];
    const float* A  = g_hs + (size_t)n*NFR*HID;
    const float* Bm = w_out + (size_t)v*WINL*HID + (size_t)wt*128*HID;
    __shared__ float As[32*132];
    __shared__ float Bs[32*132];
    int tx = t & 15, ty = t >> 4;
    int f0 = ty*8, w0 = tx*8;
    float acc[8][8];
    #pragma unroll
    for(int i = 0; i < 8; i++)
        #pragma unroll
        for(int j = 0; j < 8; j++) acc[i][j] = 0.f;

    for(int ks = 0; ks < 4; ks++){
        int k0 = ks*32;
        #pragma unroll
        for(int r = 0; r < 4; r++){
            int idx4 = t + 256*r;
            int rr = idx4 >> 3, kk4 = idx4 & 7;
            float4 va = *(const float4*)(A  + (size_t)rr*HID + k0 + kk4*4);
            float4 vb = *(const float4*)(Bm + (size_t)rr*HID + k0 + kk4*4);
            As[(kk4*4+0)*132 + rr] = va.x; As[(kk4*4+1)*132 + rr] = va.y;
            As[(kk4*4+2)*132 + rr] = va.z; As[(kk4*4+3)*132 + rr] = va.w;
            Bs[(kk4*4+0)*132 + rr] = vb.x; Bs[(kk4*4+1)*132 + rr] = vb.y;
            Bs[(kk4*4+2)*132 + rr] = vb.z; Bs[(kk4*4+3)*132 + rr] = vb.w;
        }
        __syncthreads();
        #pragma unroll
        for(int k = 0; k < 32; k++){
            float4 a0 = *(const float4*)&As[k*132 + f0];
            float4 a1 = *(const float4*)&As[k*132 + f0 + 4];
            float4 b0 = *(const float4*)&Bs[k*132 + w0];
            float4 b1 = *(const float4*)&Bs[k*132 + w0 + 4];
            float a[8] = {a0.x,a0.y,a0.z,a0.w,a1.x,a1.y,a1.z,a1.w};
            float b[8] = {b0.x,b0.y,b0.z,b0.w,b1.x,b1.y,b1.z,b1.w};
            #pragma unroll
            for(int i = 0; i < 8; i++)
                #pragma unroll
                for(int j = 0; j < 8; j++) acc[i][j] += a[i]*b[j];
        }
        __syncthreads();
    }
    float* out = g_sig + (size_t)n*NSAMP + wt*128;
    #pragma unroll
    for(int i = 0; i < 8; i++)
        #pragma unroll
        for(int j = 0; j < 8; j++)
            out[(size_t)(f0+i)*WINL + w0 + j] = __sinf(acc[i][j]);
}

// F1 column pass (forward). VERB=1: real verb -> g_vspec. VERB=0: packed pair of sigs -> g_spec.
// float4 staging loads; upper 256 rows structural zeros (pruned in dif512t<true>).
template<int VERB>
__global__ __launch_bounds__(512) void k_col_fwd(const float* __restrict__ rin_ext, int y0){
    __shared__ float2 s[8*LSTR];
    int y = blockIdx.y + y0, col0 = blockIdx.x*8, tid = threadIdx.x;
    const float* sa; const float* sb = nullptr; float2* dst;
    if(VERB){ sa = rin_ext + (size_t)y*NSAMP;        dst = g_vspec + (size_t)y*NFFT; }
    else    { sa = g_sig + (size_t)(2*y)*NSAMP; sb = g_sig + (size_t)(2*y+1)*NSAMP;
              dst = g_spec + (size_t)y*NFFT; }
    {
        int r = tid >> 1, c4 = (tid & 1) * 4;
        int o = r*512 + col0 + c4;
        float4 va = *(const float4*)(sa + o);
        float4 vb4 = make_float4(0.f, 0.f, 0.f, 0.f);
        if(!VERB) vb4 = *(const float4*)(sb + o);
        s[(c4+0)*LSTR + skew(r)] = make_float2(va.x, vb4.x);
        s[(c4+1)*LSTR + skew(r)] = make_float2(va.y, vb4.y);
        s[(c4+2)*LSTR + skew(r)] = make_float2(va.z, vb4.z);
        s[(c4+3)*LSTR + skew(r)] = make_float2(va.w, vb4.w);
    }
    __syncthreads();
    dif512t<true>(&s[(tid >> 6)*LSTR], tid & 63);
    __syncthreads();
    {
        int r0 = tid >> 3, c = tid & 7;
        int n2 = col0 + c;
        float2 w = twN(rev9(r0) * n2);
        float2 wstep = twN(n2);
        #pragma unroll
        for(int q = 0; q < 8; q++){
            int r = r0 + 64*q;
            dst[(size_t)r*512 + n2] = cmul(s[c*LSTR + skew(r)], w);
            w = cmul(w, wstep);
        }
    }
}

// F2 row pass for verb spectra — direct global in (stage 1) and out (stage 3).
__global__ __launch_bounds__(512) void k_row_verb(){
    __shared__ float2 s[8*LSTR];
    int n = blockIdx.y, row0 = blockIdx.x*8, tid = threadIdx.x;
    int line = tid >> 6, t = tid & 63;
    float2* base = g_vspec + (size_t)n*NFFT + (size_t)row0*512;
    float2* grow = base + (size_t)line*512;
    float2* L = s + line*LSTR;
    float2 v[8];
    #pragma unroll
    for(int m = 0; m < 8; m++) v[m] = grow[t + 64*m];
    dft8<false>(v);
    twid_fwd(v, g_twtab[t]);
    #pragma unroll
    for(int m = 0; m < 8; m++) L[skew(t + 64*m)] = v[m];
    __syncthreads();
    int b2 = (t >> 3) << 6, j = t & 7;
    #pragma unroll
    for(int m = 0; m < 8; m++) v[m] = L[skew(b2 + j + 8*m)];
    dft8<false>(v);
    twid_fwd(v, g_twtab[j << 3]);
    #pragma unroll
    for(int m = 0; m < 8; m++) L[skew(b2 + j + 8*m)] = v[m];
    __syncthreads();
    int b3 = t << 3;
    #pragma unroll
    for(int m = 0; m < 8; m++) v[m] = L[skew(b3 + m)];
    dft8<false>(v);
    #pragma unroll
    for(int m = 0; m < 8; m++) grow[b3 + m] = v[m];
}

__device__ __forceinline__ int pzero(int e){   // partner col for the k1==0 row
    int k2 = rev9(e);
    return rev9((512 - k2) & 511);
}

// Fused: F2 + conj-unpack + spectral mul (verb+dry fold, 1/N) + repack + I1 + conj twiddle.
__global__ __launch_bounds__(256) void k_rowpair(int p0){
    __shared__ float2 s[4*LSTR];
    int p = blockIdx.y + p0;
    int grp = threadIdx.x >> 7;
    int lt  = threadIdx.x & 127;
    int slot = blockIdx.x*2 + grp; if(slot > 256) slot = 256;
    int rows0 = g_pairA[slot], rows1 = g_pairB[slot];
    int line = lt >> 6, t = lt & 63;
    int myrow = line ? rows1 : rows0;
    float2* base = g_spec + (size_t)p*NFFT;
    float2* sg = s + (2*grp)*LSTR;
    float2* L  = sg + line*LSTR;
    float2* grow = base + (size_t)myrow*512;
    float2 v[8];

    // F2 stage 1: direct global in
    #pragma unroll
    for(int m = 0; m < 8; m++) v[m] = grow[t + 64*m];
    dft8<false>(v);
    twid_fwd(v, g_twtab[t]);
    #pragma unroll
    for(int m = 0; m < 8; m++) L[skew(t + 64*m)] = v[m];
    __syncthreads();
    // F2 stage 2
    int b2 = (t >> 3) << 6, j = t & 7;
    #pragma unroll
    for(int m = 0; m < 8; m++) v[m] = L[skew(b2 + j + 8*m)];
    dft8<false>(v);
    twid_fwd(v, g_twtab[j << 3]);
    #pragma unroll
    for(int m = 0; m < 8; m++) L[skew(b2 + j + 8*m)] = v[m];
    __syncthreads();
    // F2 stage 3 -> smem (unpack needs full lines)
    int b3 = t << 3;
    #pragma unroll
    for(int m = 0; m < 8; m++) v[m] = L[skew(b3 + m)];
    dft8<false>(v);
    #pragma unroll
    for(int m = 0; m < 8; m++) L[skew(b3 + m)] = v[m];
    __syncthreads();

    // conj-unpack + spectral multiply (verb + dry folded) + repack
    int na = 2*p, nb = 2*p + 1;
    const float2* va = g_vspec + (size_t)g_ridx[na]*NFFT;
    const float2* vb = g_vspec + (size_t)g_ridx[nb]*NFFT;
    float m0a = g_m0[na], m1a = g_m1[na], m0b = g_m0[nb], m1b = g_m1[nb];
    const float invN = 1.f / (float)NFFT;

    float2 Z[8], Zp[8];
    #pragma unroll
    for(int q = 0; q < 8; q++){
        int idx = lt + 128*q;
        int l = idx >> 9, e = idx & 511;
        int row = l ? rows1 : rows0;
        int k1 = rev9(row);
        int ep = (k1 == 0) ? pzero(e) : (511 - e);
        Z[q]  = sg[l*LSTR + skew(e)];
        Zp[q] = sg[(1 - l)*LSTR + skew(ep)];
    }
    __syncthreads();
    #pragma unroll
    for(int q = 0; q < 8; q++){
        int idx = lt + 128*q;
        int l = idx >> 9, e = idx & 511;
        int row = l ? rows1 : rows0;
        float2 S1 = make_float2(0.5f*(Z[q].x + Zp[q].x), 0.5f*(Z[q].y - Zp[q].y));
        float2 S2 = make_float2(0.5f*(Z[q].y + Zp[q].y), -0.5f*(Z[q].x - Zp[q].x));
        float2 V1 = va[(size_t)row*512 + e];
        float2 V2 = vb[(size_t)row*512 + e];
        float2 M1 = make_float2(m0a*V1.x + m1a, m0a*V1.y);
        float2 M2 = make_float2(m0b*V2.x + m1b, m0b*V2.y);
        float2 W1 = cmul(S1, M1), W2 = cmul(S2, M2);
        sg[l*LSTR + skew(e)] = make_float2((W1.x - W2.y)*invN, (W1.y + W2.x)*invN);
    }
    __syncthreads();

    // I1 (DIT) stage 1
    #pragma unroll
    for(int m = 0; m < 8; m++) v[m] = L[skew(b3 + m)];
    dft8<true>(v);
    #pragma unroll
    for(int m = 0; m < 8; m++) L[skew(b3 + m)] = v[m];
    __syncthreads();
    // I1 stage 2
    #pragma unroll
    for(int m = 0; m < 8; m++) v[m] = L[skew(b2 + j + 8*m)];
    twid_inv(v, g_twtab[j << 3]);
    dft8<true>(v);
    #pragma unroll
    for(int m = 0; m < 8; m++) L[skew(b2 + j + 8*m)] = v[m];
    __syncthreads();
    // I1 stage 3 + conj inter-pass twiddle -> direct global out (recurrence)
    #pragma unroll
    for(int m = 0; m < 8; m++) v[m] = L[skew(t + 64*m)];
    twid_inv(v, g_twtab[t]);
    dft8<true>(v);
    {
        int k1 = rev9(myrow);
        float2 w = twN(k1 * t);
        float2 wstep = twN(k1 << 6);
        #pragma unroll
        for(int m = 0; m < 8; m++){
            grow[t + 64*m] = cmulc(v[m], w);
            w = cmul(w, wstep);
        }
    }
}

// I2 column pass (inverse, packed, half-output) + epilogue: |amp| + dirac row-shift.
__global__ __launch_bounds__(512) void k_col_inv(float* __restrict__ out, int p0){
    __shared__ float2 s[8*LSTR];
    int p = blockIdx.y + p0, col0 = blockIdx.x*8, tid = threadIdx.x;
    const float2* src = g_spec + (size_t)p*NFFT;
    #pragma unroll
    for(int it = 0; it < 4; it++){
        int idx2 = tid + 512*it;
        int r = idx2 >> 2, cp = idx2 & 3;
        float4 v4 = *(const float4*)(src + (size_t)r*512 + col0 + cp*2);
        s[(2*cp)*LSTR + skew(r)]   = make_float2(v4.x, v4.y);
        s[(2*cp+1)*LSTR + skew(r)] = make_float2(v4.z, v4.w);
    }
    __syncthreads();
    dit512t<true>(&s[(tid >> 6)*LSTR], tid & 63);
    __syncthreads();
    int na = 2*p, nb = 2*p + 1;
    float aA = g_amp[na], aB = g_amp[nb];
    int dA = g_shift[na] >> 9, dB = g_shift[nb] >> 9;
    float* oA = out + (size_t)na*NSAMP;
    float* oB = out + (size_t)nb*NSAMP;
    for(int idx = tid; idx < 2048; idx += 512){
        int rp = idx >> 3, c = idx & 7;
        int col = col0 + c;
        int ra = rp - dA;
        oA[rp*512 + col] = (ra >= 0) ? s[c*LSTR + skew(ra)].x * aA : 0.f;
        int rb = rp - dB;
        oB[rp*512 + col] = (rb >= 0) ? s[c*LSTR + skew(rb)].y * aB : 0.f;
    }
}

extern "C" void kernel_launch(void* const* d_in, const int* in_sizes, int n_in,
                              void* d_out, int out_size) {
    const float* voice = (const float*)d_in[0];
    const float* cpc   = (const float*)d_in[1];
    const float* amp   = (const float*)d_in[2];
    const float* room  = (const float*)d_in[3];
    const float* mix   = (const float*)d_in[4];
    const float* times = (const float*)d_in[5];
    const float* cp_table = (const float*)d_in[6];
    const float* verbs = (const float*)d_in[7];
    const float* w_in  = (const float*)d_in[8];
    const float* w_ih  = (const float*)d_in[9];
    const float* w_hh  = (const float*)d_in[10];
    const float* w_out = (const float*)d_in[11];
    float* out = (float*)d_out;

    static cudaStream_t s_side = 0;
    static cudaEvent_t ev_fork = 0, ev_coll = 0, ev_w0 = 0, ev_c0 = 0, ev_p0 = 0, ev_d0 = 0;
    static int s_init = 0;
    if(!s_init){
        if(cudaStreamCreateWithFlags(&s_side, cudaStreamNonBlocking) != cudaSuccess) s_side = 0;
        if(s_side){
            bool ok = cudaEventCreateWithFlags(&ev_fork, cudaEventDisableTiming) == cudaSuccess &&
                      cudaEventCreateWithFlags(&ev_coll, cudaEventDisableTiming) == cudaSuccess &&
                      cudaEventCreateWithFlags(&ev_w0,   cudaEventDisableTiming) == cudaSuccess &&
                      cudaEventCreateWithFlags(&ev_c0,   cudaEventDisableTiming) == cudaSuccess &&
                      cudaEventCreateWithFlags(&ev_p0,   cudaEventDisableTiming) == cudaSuccess &&
                      cudaEventCreateWithFlags(&ev_d0,   cudaEventDisableTiming) == cudaSuccess;
            if(!ok) s_side = 0;
        }
        s_init = 1;
    }

    k_twtab<<<2, 512>>>();
    if(s_side){
        cudaEventRecord(ev_fork, 0);
        cudaStreamWaitEvent(s_side, ev_fork, 0);
        // side: collapse + verb FFT chain
        k_collapse<<<NVO*HID, 128, 0, s_side>>>(w_ih, w_in);
        cudaEventRecord(ev_coll, s_side);
        k_col_fwd<1><<<dim3(64, NVB), 512, 0, s_side>>>(verbs, 0);
        k_row_verb<<<dim3(64, NVB), 512, 0, s_side>>>();
        // main: prep -> rnn -> wout halves
        k_prep<<<NEV, 256>>>(voice, cpc, amp, room, mix, times, cp_table);
        cudaStreamWaitEvent(0, ev_coll, 0);
        k_rnn<<<NEV, 256>>>(w_hh);
        k_wout<<<dim3(8, 64), 256>>>(w_out, 0);
        cudaEventRecord(ev_w0, 0);
        k_wout<<<dim3(8, 64), 256>>>(w_out, 64);
        // side: colfwd for first half (overlaps wout_h1); after verb chain in side order
        cudaStreamWaitEvent(s_side, ev_w0, 0);
        k_col_fwd<0><<<dim3(64, 32), 512, 0, s_side>>>(nullptr, 0);
        cudaEventRecord(ev_c0, s_side);
        // main: colfwd second half
        k_col_fwd<0><<<dim3(64, 32), 512>>>(nullptr, 32);
        cudaStreamWaitEvent(0, ev_c0, 0);
        // main: rowpair halves; side: colinv first half overlaps rowpair_h1
        k_rowpair<<<dim3(129, 32), 256>>>(0);
        cudaEventRecord(ev_p0, 0);
        k_rowpair<<<dim3(129, 32), 256>>>(32);
        cudaStreamWaitEvent(s_side, ev_p0, 0);
        k_col_inv<<<dim3(64, 32), 512, 0, s_side>>>(out, 0);
        cudaEventRecord(ev_d0, s_side);
        k_col_inv<<<dim3(64, 32), 512>>>(out, 32);
        cudaStreamWaitEvent(0, ev_d0, 0);
    } else {
        k_prep<<<NEV, 256>>>(voice, cpc, amp, room, mix, times, cp_table);
        k_collapse<<<NVO*HID, 128>>>(w_ih, w_in);
        k_rnn<<<NEV, 256>>>(w_hh);
        k_wout<<<dim3(8, NEV), 256>>>(w_out, 0);
        k_col_fwd<1><<<dim3(64, NVB), 512>>>(verbs, 0);
        k_row_verb<<<dim3(64, NVB), 512>>>();
        k_col_fwd<0><<<dim3(64, NPAIR), 512>>>(nullptr, 0);
        k_rowpair<<<dim3(129, NPAIR), 256>>>(0);
        k_col_inv<<<dim3(64, NPAIR), 512>>>(out, 0);
    }
}

// round 14
// speedup vs baseline: 1.7768x; 1.0030x over previous
#include <cuda_runtime.h>
#include <math.h>

#define NEV   128
#define NPAIR 64
#define NSAMP 131072
#define NFFT  262144
#define NFR   128
#define WINL  1024
#define CPD   16
#define NCP   512
#define NVO   8
#define NVB   16
#define HID   128
#define KSP   128
#define LSTR  578

__device__ float2 g_twtab[1024];                     // [0:512) W512^k ; [512:1024) W_N^k
__device__ float2 g_spec[(size_t)NPAIR * NFFT];      // 128 MB packed spectra
__device__ float2 g_vspec[(size_t)NVB * NFFT];       // 32 MB verb spectra
__device__ float  g_sig[(size_t)NEV * NSAMP];
__device__ float  g_hs[(size_t)NEV * NFR * HID];
__device__ float  g_ctrl[NEV * NFR * CPD];
__device__ float  g_M[NVO * HID * CPD];
__device__ int    g_vidx[NEV], g_ridx[NEV], g_shift[NEV];
__device__ float  g_m0[NEV], g_m1[NEV], g_amp[NEV];
__device__ int    g_pairA[257], g_pairB[257];

__device__ __forceinline__ int skew(int i){ return i + (i >> 3); }
__device__ __forceinline__ float2 cadd(float2 a, float2 b){ return make_float2(a.x+b.x, a.y+b.y); }
__device__ __forceinline__ float2 csub(float2 a, float2 b){ return make_float2(a.x-b.x, a.y-b.y); }
__device__ __forceinline__ float2 cmul(float2 a, float2 b){ return make_float2(a.x*b.x - a.y*b.y, a.x*b.y + a.y*b.x); }
__device__ __forceinline__ float2 cmulc(float2 a, float2 b){ return make_float2(a.x*b.x + a.y*b.y, a.y*b.x - a.x*b.y); }
__device__ __forceinline__ int rev9(int p){ return ((p & 7) << 6) | (p & 56) | (p >> 6); }

__device__ __forceinline__ float2 twN(int idx){
    int k = idx & (NFFT - 1);
    return cmul(g_twtab[k >> 9], g_twtab[512 + (k & 511)]);
}

template<bool INV>
__device__ __forceinline__ float2 mulmi(float2 a){
    return INV ? make_float2(-a.y, a.x) : make_float2(a.y, -a.x);
}

template<bool INV>
__device__ __forceinline__ void dft8(float2* v){
    float2 t0 = cadd(v[0], v[4]), t1 = csub(v[0], v[4]);
    float2 t2 = cadd(v[2], v[6]), t3 = mulmi<INV>(csub(v[2], v[6]));
    float2 t4 = cadd(v[1], v[5]), t5 = csub(v[1], v[5]);
    float2 t6 = cadd(v[3], v[7]), t7 = mulmi<INV>(csub(v[3], v[7]));
    float2 a0 = cadd(t0, t2), a2 = csub(t0, t2);
    float2 a1 = cadd(t1, t3), a3 = csub(t1, t3);
    float2 b0 = cadd(t4, t6), b2 = csub(t4, t6);
    float2 b1 = cadd(t5, t7), b3 = csub(t5, t7);
    const float r = 0.70710678118654752440f;
    float2 w1 = INV ? make_float2(r,  r) : make_float2(r, -r);
    float2 w3 = INV ? make_float2(-r, r) : make_float2(-r, -r);
    b1 = cmul(b1, w1); b2 = mulmi<INV>(b2); b3 = cmul(b3, w3);
    v[0] = cadd(a0, b0); v[4] = csub(a0, b0);
    v[1] = cadd(a1, b1); v[5] = csub(a1, b1);
    v[2] = cadd(a2, b2); v[6] = csub(a2, b2);
    v[3] = cadd(a3, b3); v[7] = csub(a3, b3);
}

// apply twiddles w1^m to v[1..7] via recurrence (1 table value, 6 extra cmuls)
__device__ __forceinline__ void twid_fwd(float2* v, float2 w1){
    float2 wm = w1;
    v[1] = cmul(v[1], wm);
    #pragma unroll
    for(int m = 2; m < 8; m++){ wm = cmul(wm, w1); v[m] = cmul(v[m], wm); }
}
__device__ __forceinline__ void twid_inv(float2* v, float2 w1){
    float2 wm = w1;
    v[1] = cmulc(v[1], wm);
    #pragma unroll
    for(int m = 2; m < 8; m++){ wm = cmul(wm, w1); v[m] = cmulc(v[m], wm); }
}

// DIF 512 = radix-8^3, natural in -> octal-digit-reversed out.
// ZTOP: input rows [256,512) are structural zeros (not staged in smem).
template<bool ZTOP>
__device__ __forceinline__ void dif512t(float2* L, int t){
    float2 v[8];
    if(ZTOP){
        #pragma unroll
        for(int m = 0; m < 4; m++) v[m] = L[skew(t + 64*m)];
        #pragma unroll
        for(int m = 4; m < 8; m++) v[m] = make_float2(0.f, 0.f);
    } else {
        #pragma unroll
        for(int m = 0; m < 8; m++) v[m] = L[skew(t + 64*m)];
    }
    dft8<false>(v);
    twid_fwd(v, g_twtab[t]);
    #pragma unroll
    for(int m = 0; m < 8; m++) L[skew(t + 64*m)] = v[m];
    __syncthreads();
    int base = (t >> 3) << 6, j = t & 7;
    #pragma unroll
    for(int m = 0; m < 8; m++) v[m] = L[skew(base + j + 8*m)];
    dft8<false>(v);
    twid_fwd(v, g_twtab[j << 3]);
    #pragma unroll
    for(int m = 0; m < 8; m++) L[skew(base + j + 8*m)] = v[m];
    __syncthreads();
    base = t << 3;
    #pragma unroll
    for(int m = 0; m < 8; m++) v[m] = L[skew(base + m)];
    dft8<false>(v);
    #pragma unroll
    for(int m = 0; m < 8; m++) L[skew(base + m)] = v[m];
}

// DIT 512: digit-reversed in -> natural out, conjugate twiddles (unscaled inverse).
// HALF: store only natural outputs < 256 (last stage m<4); rows >=256 stale.
template<bool HALF>
__device__ __forceinline__ void dit512t(float2* L, int t){
    float2 v[8];
    int base = t << 3;
    #pragma unroll
    for(int m = 0; m < 8; m++) v[m] = L[skew(base + m)];
    dft8<true>(v);
    #pragma unroll
    for(int m = 0; m < 8; m++) L[skew(base + m)] = v[m];
    __syncthreads();
    base = (t >> 3) << 6; int j = t & 7;
    #pragma unroll
    for(int m = 0; m < 8; m++) v[m] = L[skew(base + j + 8*m)];
    twid_inv(v, g_twtab[j << 3]);
    dft8<true>(v);
    #pragma unroll
    for(int m = 0; m < 8; m++) L[skew(base + j + 8*m)] = v[m];
    __syncthreads();
    #pragma unroll
    for(int m = 0; m < 8; m++) v[m] = L[skew(t + 64*m)];
    twid_inv(v, g_twtab[t]);
    dft8<true>(v);
    #pragma unroll
    for(int m = 0; m < (HALF ? 4 : 8); m++) L[skew(t + 64*m)] = v[m];
}

__global__ void k_twtab(){
    int k = blockIdx.x * blockDim.x + threadIdx.x;
    if(k < 1024){
        double a;
        if(k < 512) a = -6.283185307179586476925286766559 * (double)k / 512.0;
        else        a = -6.283185307179586476925286766559 * (double)(k - 512) / (double)NFFT;
        double s, c; sincos(a, &s, &c);
        g_twtab[k] = make_float2((float)c, (float)s);
    }
    if(k == 0){
        int cnt = 0;
        for(int p = 0; p < 512; p++){
            int k1 = rev9(p);
            int pp = rev9((512 - k1) & 511);
            if(p <= pp){ g_pairA[cnt] = p; g_pairB[cnt] = pp; cnt++; }
        }
    }
}

__global__ __launch_bounds__(256) void k_prep(
    const float* __restrict__ voice, const float* __restrict__ cpc,
    const float* __restrict__ amp,   const float* __restrict__ room,
    const float* __restrict__ mix,   const float* __restrict__ times,
    const float* __restrict__ cp_table)
{
    int n = blockIdx.x, tid = threadIdx.x;
    __shared__ float sv[256];
    __shared__ int   si[256];
    __shared__ int   s_cidx, s_cnt;

    float best = -1e30f; int bi = 0;
    for(int j = tid; j < NCP; j += 256){
        float v = cpc[n*NCP + j];
        if(v > best){ best = v; bi = j; }
    }
    sv[tid] = best; si[tid] = bi; __syncthreads();
    for(int s = 128; s > 0; s >>= 1){
        if(tid < s){
            if(sv[tid+s] > sv[tid] || (sv[tid+s] == sv[tid] && si[tid+s] < si[tid])){
                sv[tid] = sv[tid+s]; si[tid] = si[tid+s];
            }
        }
        __syncthreads();
    }
    if(tid == 0){
        s_cidx = si[0];
        float b = -1e30f; int ii = 0;
        for(int j = 0; j < NFR; j++){ float v = times[n*NFR + j]; if(v > b){ b = v; ii = j; } }
        g_shift[n] = ii * (NSAMP / NFR);
        b = -1e30f; ii = 0;
        for(int j = 0; j < NVO; j++){ float v = voice[n*NVO + j]; if(v > b){ b = v; ii = j; } }
        g_vidx[n] = ii;
        b = -1e30f; ii = 0;
        for(int j = 0; j < NVB; j++){ float v = room[n*NVB + j]; if(v > b){ b = v; ii = j; } }
        g_ridx[n] = ii;
        float x0 = mix[n*2], x1 = mix[n*2 + 1];
        float mm = fmaxf(x0, x1);
        float e0 = expf(x0 - mm), e1 = expf(x1 - mm);
        g_m0[n] = e0 / (e0 + e1);
        g_m1[n] = e1 / (e0 + e1);
        g_amp[n] = fabsf(amp[n]);
    }
    __syncthreads();

    const float* row = cp_table + (size_t)s_cidx * (NFR*CPD);
    float rv[8];
    #pragma unroll
    for(int j = 0; j < 8; j++) rv[j] = row[tid + 256*j];
    unsigned lo = 0u, hi = 0x7F800000u;
    while(hi - lo > 1u){
        unsigned mid = lo + ((hi - lo) >> 1);
        int c = 0;
        #pragma unroll
        for(int j = 0; j < 8; j++) c += (__float_as_uint(rv[j]) >= mid) ? 1 : 0;
        si[tid] = c; __syncthreads();
        for(int s = 128; s > 0; s >>= 1){
            if(tid < s) si[tid] += si[tid+s];
            __syncthreads();
        }
        if(tid == 0) s_cnt = si[0];
        __syncthreads();
        if(s_cnt >= KSP) lo = mid; else hi = mid;
    }
    for(int idx = tid; idx < NFR*CPD; idx += 256){
        int f = idx >> 4, c = idx & 15;
        float v = row[c*NFR + f];
        float keep = (__float_as_uint(v) >= lo) ? v : 0.f;
        g_ctrl[n*NFR*CPD + idx] = fmaxf(keep, 0.f);
    }
}

// M[v] = W_ih[v] @ W_in[v] — parallel Kahan-fp32 split-K
__global__ __launch_bounds__(128) void k_collapse(
    const float* __restrict__ w_ih, const float* __restrict__ w_in)
{
    int blk = blockIdx.x;
    int v = blk >> 7, i = blk & 127;
    int t = threadIdx.x;
    const float* wr = w_ih + ((size_t)v*HID + i) * WINL;
    const float* wc = w_in + (size_t)v*WINL*CPD;
    float s[CPD], comp[CPD];
    #pragma unroll
    for(int c = 0; c < CPD; c++){ s[c] = 0.f; comp[c] = 0.f; }
    for(int k = t; k < WINL; k += 128){
        float a = wr[k];
        const float4* p = (const float4*)(wc + (size_t)k*CPD);
        float4 q[4] = {p[0], p[1], p[2], p[3]};
        const float* qs = (const float*)q;
        #pragma unroll
        for(int c = 0; c < CPD; c++){
            float y = fmaf(a, qs[c], -comp[c]);
            float tt = s[c] + y;
            comp[c] = (tt - s[c]) - y;
            s[c] = tt;
        }
    }
    __shared__ float red[128 * CPD];
    #pragma unroll
    for(int c = 0; c < CPD; c++) red[t*CPD + c] = s[c];
    __syncthreads();
    for(int st = 64; st > 0; st >>= 1){
        if(t < st){
            #pragma unroll
            for(int c = 0; c < CPD; c++) red[t*CPD + c] += red[(t+st)*CPD + c];
        }
        __syncthreads();
    }
    if(t < CPD) g_M[(v*HID + i)*CPD + t] = red[t];
}

// overflow-safe fast tanh: 1 - 2e/(1+e), e = exp(-2|x|); e<=1 so no overflow
__device__ __forceinline__ float ftanh(float x){
    float ax = fabsf(x);
    float e = __expf(-2.f*ax);
    float th = 1.f - 2.f*e/(1.f + e);
    return copysignf(th, x);
}

// persistent RNN: one block per event
__global__ __launch_bounds__(256) void k_rnn(const float* __restrict__ w_hh){
    int n = blockIdx.x, t = threadIdx.x;
    int i = t & 127, half = t >> 7;
    int v = g_vidx[n];
    __shared__ float ctrl_s[NFR*CPD];
    __shared__ float h_s[HID];
    __shared__ float part_s[256];

    float W[64];
    const float* wh = w_hh + ((size_t)v*HID + i) * HID + half*64;
    #pragma unroll
    for(int k = 0; k < 64; k++) W[k] = wh[k];
    float M[CPD];
    const float* mp = g_M + (v*HID + i)*CPD;
    #pragma unroll
    for(int c = 0; c < CPD; c++) M[c] = mp[c];
    for(int idx = t; idx < NFR*CPD; idx += 256) ctrl_s[idx] = g_ctrl[n*NFR*CPD + idx];
    if(t < HID) h_s[t] = 0.f;
    __syncthreads();

    float* hsout = g_hs + (size_t)n*NFR*HID;
    for(int f = 0; f < NFR; f++){
        const float* hb = h_s + half*64;
        float p0 = 0.f, p1 = 0.f, p2 = 0.f, p3 = 0.f;
        #pragma unroll
        for(int k = 0; k < 64; k += 4){
            p0 = fmaf(W[k],   hb[k],   p0);
            p1 = fmaf(W[k+1], hb[k+1], p1);
            p2 = fmaf(W[k+2], hb[k+2], p2);
            p3 = fmaf(W[k+3], hb[k+3], p3);
        }
        float inp = 0.f;
        if(half == 0){
            const float* cf = ctrl_s + f*CPD;
            float i0 = 0.f, i1 = 0.f;
            #pragma unroll
            for(int c = 0; c < CPD; c += 2){
                i0 = fmaf(M[c],   cf[c],   i0);
                i1 = fmaf(M[c+1], cf[c+1], i1);
            }
            inp = i0 + i1;
        }
        part_s[t] = (p0 + p1) + (p2 + p3);
        __syncthreads();
        if(half == 0){
            float h = ftanh(part_s[t] + part_s[t + 128] + inp);
            h_s[i] = h;
            hsout[f*HID + i] = h;
        }
        __syncthreads();
    }
}

// sig[f,w] = sin( hs[f,:] . w_out[v,w,:] ) — fp32 register-tiled GEMM, fast-sin epilogue
__global__ __launch_bounds__(256) void k_wout(const float* __restrict__ w_out, int n0){
    int wt = blockIdx.x, n = blockIdx.y + n0, t = threadIdx.x;
    int v = g_vidx[n];
    const float* A  = g_hs + (size_t)n*NFR*HID;
    const float* Bm = w_out + (size_t)v*WINL*HID + (size_t)wt*128*HID;
    __shared__ float As[32*132];
    __shared__ float Bs[32*132];
    int tx = t & 15, ty = t >> 4;
    int f0 = ty*8, w0 = tx*8;
    float acc[8][8];
    #pragma unroll
    for(int i = 0; i < 8; i++)
        #pragma unroll
        for(int j = 0; j < 8; j++) acc[i][j] = 0.f;

    for(int ks = 0; ks < 4; ks++){
        int k0 = ks*32;
        #pragma unroll
        for(int r = 0; r < 4; r++){
            int idx4 = t + 256*r;
            int rr = idx4 >> 3, kk4 = idx4 & 7;
            float4 va = *(const float4*)(A  + (size_t)rr*HID + k0 + kk4*4);
            float4 vb = *(const float4*)(Bm + (size_t)rr*HID + k0 + kk4*4);
            As[(kk4*4+0)*132 + rr] = va.x; As[(kk4*4+1)*132 + rr] = va.y;
            As[(kk4*4+2)*132 + rr] = va.z; As[(kk4*4+3)*132 + rr] = va.w;
            Bs[(kk4*4+0)*132 + rr] = vb.x; Bs[(kk4*4+1)*132 + rr] = vb.y;
            Bs[(kk4*4+2)*132 + rr] = vb.z; Bs[(kk4*4+3)*132 + rr] = vb.w;
        }
        __syncthreads();
        #pragma unroll
        for(int k = 0; k < 32; k++){
            float4 a0 = *(const float4*)&As[k*132 + f0];
            float4 a1 = *(const float4*)&As[k*132 + f0 + 4];
            float4 b0 = *(const float4*)&Bs[k*132 + w0];
            float4 b1 = *(const float4*)&Bs[k*132 + w0 + 4];
            float a[8] = {a0.x,a0.y,a0.z,a0.w,a1.x,a1.y,a1.z,a1.w};
            float b[8] = {b0.x,b0.y,b0.z,b0.w,b1.x,b1.y,b1.z,b1.w};
            #pragma unroll
            for(int i = 0; i < 8; i++)
                #pragma unroll
                for(int j = 0; j < 8; j++) acc[i][j] += a[i]*b[j];
        }
        __syncthreads();
    }
    float* out = g_sig + (size_t)n*NSAMP + wt*128;
    #pragma unroll
    for(int i = 0; i < 8; i++)
        #pragma unroll
        for(int j = 0; j < 8; j++)
            out[(size_t)(f0+i)*WINL + w0 + j] = __sinf(acc[i][j]);
}

// F1 column pass (forward). VERB=1: real verb -> g_vspec. VERB=0: packed pair of sigs -> g_spec.
template<int VERB>
__global__ __launch_bounds__(512) void k_col_fwd(const float* __restrict__ rin_ext, int y0){
    __shared__ float2 s[8*LSTR];
    int y = blockIdx.y + y0, col0 = blockIdx.x*8, tid = threadIdx.x;
    const float* sa; const float* sb = nullptr; float2* dst;
    if(VERB){ sa = rin_ext + (size_t)y*NSAMP;        dst = g_vspec + (size_t)y*NFFT; }
    else    { sa = g_sig + (size_t)(2*y)*NSAMP; sb = g_sig + (size_t)(2*y+1)*NSAMP;
              dst = g_spec + (size_t)y*NFFT; }
    {
        int r = tid >> 1, c4 = (tid & 1) * 4;
        int o = r*512 + col0 + c4;
        float4 va = *(const float4*)(sa + o);
        float4 vb4 = make_float4(0.f, 0.f, 0.f, 0.f);
        if(!VERB) vb4 = *(const float4*)(sb + o);
        s[(c4+0)*LSTR + skew(r)] = make_float2(va.x, vb4.x);
        s[(c4+1)*LSTR + skew(r)] = make_float2(va.y, vb4.y);
        s[(c4+2)*LSTR + skew(r)] = make_float2(va.z, vb4.z);
        s[(c4+3)*LSTR + skew(r)] = make_float2(va.w, vb4.w);
    }
    __syncthreads();
    dif512t<true>(&s[(tid >> 6)*LSTR], tid & 63);
    __syncthreads();
    {
        int r0 = tid >> 3, c = tid & 7;
        int n2 = col0 + c;
        float2 w = twN(rev9(r0) * n2);
        float2 wstep = twN(n2);
        #pragma unroll
        for(int q = 0; q < 8; q++){
            int r = r0 + 64*q;
            dst[(size_t)r*512 + n2] = cmul(s[c*LSTR + skew(r)], w);
            w = cmul(w, wstep);
        }
    }
}

// F2 row pass for verb spectra — direct global in (stage 1) and out (stage 3).
__global__ __launch_bounds__(512) void k_row_verb(){
    __shared__ float2 s[8*LSTR];
    int n = blockIdx.y, row0 = blockIdx.x*8, tid = threadIdx.x;
    int line = tid >> 6, t = tid & 63;
    float2* base = g_vspec + (size_t)n*NFFT + (size_t)row0*512;
    float2* grow = base + (size_t)line*512;
    float2* L = s + line*LSTR;
    float2 v[8];
    #pragma unroll
    for(int m = 0; m < 8; m++) v[m] = grow[t + 64*m];
    dft8<false>(v);
    twid_fwd(v, g_twtab[t]);
    #pragma unroll
    for(int m = 0; m < 8; m++) L[skew(t + 64*m)] = v[m];
    __syncthreads();
    int b2 = (t >> 3) << 6, j = t & 7;
    #pragma unroll
    for(int m = 0; m < 8; m++) v[m] = L[skew(b2 + j + 8*m)];
    dft8<false>(v);
    twid_fwd(v, g_twtab[j << 3]);
    #pragma unroll
    for(int m = 0; m < 8; m++) L[skew(b2 + j + 8*m)] = v[m];
    __syncthreads();
    int b3 = t << 3;
    #pragma unroll
    for(int m = 0; m < 8; m++) v[m] = L[skew(b3 + m)];
    dft8<false>(v);
    #pragma unroll
    for(int m = 0; m < 8; m++) grow[b3 + m] = v[m];
}

__device__ __forceinline__ int pzero(int e){   // partner col for the k1==0 row
    int k2 = rev9(e);
    return rev9((512 - k2) & 511);
}

// Fused: F2 + conj-unpack + spectral mul (verb+dry fold, 1/N) + repack + I1 + conj twiddle.
// Register-carried through stage3 -> multiply -> DIT stage1 (same contiguous 8-run).
__global__ __launch_bounds__(256) void k_rowpair(int p0){
    __shared__ float2 s[4*LSTR];
    int p = blockIdx.y + p0;
    int grp = threadIdx.x >> 7;
    int lt  = threadIdx.x & 127;
    int slot = blockIdx.x*2 + grp; if(slot > 256) slot = 256;
    int rows0 = g_pairA[slot], rows1 = g_pairB[slot];
    int line = lt >> 6, t = lt & 63;
    int myrow = line ? rows1 : rows0;
    float2* base = g_spec + (size_t)p*NFFT;
    float2* sg = s + (2*grp)*LSTR;
    float2* L  = sg + line*LSTR;
    float2* grow = base + (size_t)myrow*512;
    float2 v[8];

    // F2 stage 1: direct global in
    #pragma unroll
    for(int m = 0; m < 8; m++) v[m] = grow[t + 64*m];
    dft8<false>(v);
    twid_fwd(v, g_twtab[t]);
    #pragma unroll
    for(int m = 0; m < 8; m++) L[skew(t + 64*m)] = v[m];
    __syncthreads();
    // F2 stage 2
    int b2 = (t >> 3) << 6, j = t & 7;
    #pragma unroll
    for(int m = 0; m < 8; m++) v[m] = L[skew(b2 + j + 8*m)];
    dft8<false>(v);
    twid_fwd(v, g_twtab[j << 3]);
    #pragma unroll
    for(int m = 0; m < 8; m++) L[skew(b2 + j + 8*m)] = v[m];
    __syncthreads();
    // F2 stage 3: dft8 on own contiguous run; v stays in registers, smem copy for partner
    int b3 = t << 3;
    #pragma unroll
    for(int m = 0; m < 8; m++) v[m] = L[skew(b3 + m)];
    dft8<false>(v);
    #pragma unroll
    for(int m = 0; m < 8; m++) L[skew(b3 + m)] = v[m];
    __syncthreads();

    // read partner values (reversed run of the other line) into registers
    int k1r = rev9(myrow);
    float2 Zp[8];
    #pragma unroll
    for(int m = 0; m < 8; m++){
        int e = b3 + m;
        int ep = (k1r == 0) ? pzero(e) : (511 - e);
        Zp[m] = sg[(1 - line)*LSTR + skew(ep)];
    }
    __syncthreads();   // all partner reads done before dit1 stores overwrite

    // unpack + spectral multiply (verb + dry folded) + repack, in registers
    {
        int na = 2*p, nb = 2*p + 1;
        const float2* va = g_vspec + (size_t)g_ridx[na]*NFFT + (size_t)myrow*512 + b3;
        const float2* vb = g_vspec + (size_t)g_ridx[nb]*NFFT + (size_t)myrow*512 + b3;
        float m0a = g_m0[na], m1a = g_m1[na], m0b = g_m0[nb], m1b = g_m1[nb];
        const float invN = 1.f / (float)NFFT;
        float4 va4[4], vb4[4];
        #pragma unroll
        for(int q = 0; q < 4; q++){
            va4[q] = ((const float4*)va)[q];
            vb4[q] = ((const float4*)vb)[q];
        }
        const float2* V1s = (const float2*)va4;
        const float2* V2s = (const float2*)vb4;
        #pragma unroll
        for(int m = 0; m < 8; m++){
            float2 Z = v[m];
            float2 S1 = make_float2(0.5f*(Z.x + Zp[m].x), 0.5f*(Z.y - Zp[m].y));
            float2 S2 = make_float2(0.5f*(Z.y + Zp[m].y), -0.5f*(Z.x - Zp[m].x));
            float2 M1 = make_float2(m0a*V1s[m].x + m1a, m0a*V1s[m].y);
            float2 M2 = make_float2(m0b*V2s[m].x + m1b, m0b*V2s[m].y);
            float2 W1 = cmul(S1, M1), W2 = cmul(S2, M2);
            v[m] = make_float2((W1.x - W2.y)*invN, (W1.y + W2.x)*invN);
        }
    }
    // I1 (DIT) stage 1 directly on the register run
    dft8<true>(v);
    #pragma unroll
    for(int m = 0; m < 8; m++) L[skew(b3 + m)] = v[m];
    __syncthreads();
    // I1 stage 2
    #pragma unroll
    for(int m = 0; m < 8; m++) v[m] = L[skew(b2 + j + 8*m)];
    twid_inv(v, g_twtab[j << 3]);
    dft8<true>(v);
    #pragma unroll
    for(int m = 0; m < 8; m++) L[skew(b2 + j + 8*m)] = v[m];
    __syncthreads();
    // I1 stage 3 + conj inter-pass twiddle -> direct global out (recurrence)
    #pragma unroll
    for(int m = 0; m < 8; m++) v[m] = L[skew(t + 64*m)];
    twid_inv(v, g_twtab[t]);
    dft8<true>(v);
    {
        float2 w = twN(k1r * t);
        float2 wstep = twN(k1r << 6);
        #pragma unroll
        for(int m = 0; m < 8; m++){
            grow[t + 64*m] = cmulc(v[m], w);
            w = cmul(w, wstep);
        }
    }
}

// I2 column pass (inverse, packed, half-output) + epilogue: |amp| + dirac row-shift.
__global__ __launch_bounds__(512) void k_col_inv(float* __restrict__ out, int p0){
    __shared__ float2 s[8*LSTR];
    int p = blockIdx.y + p0, col0 = blockIdx.x*8, tid = threadIdx.x;
    const float2* src = g_spec + (size_t)p*NFFT;
    #pragma unroll
    for(int it = 0; it < 4; it++){
        int idx2 = tid + 512*it;
        int r = idx2 >> 2, cp = idx2 & 3;
        float4 v4 = *(const float4*)(src + (size_t)r*512 + col0 + cp*2);
        s[(2*cp)*LSTR + skew(r)]   = make_float2(v4.x, v4.y);
        s[(2*cp+1)*LSTR + skew(r)] = make_float2(v4.z, v4.w);
    }
    __syncthreads();
    dit512t<true>(&s[(tid >> 6)*LSTR], tid & 63);
    __syncthreads();
    int na = 2*p, nb = 2*p + 1;
    float aA = g_amp[na], aB = g_amp[nb];
    int dA = g_shift[na] >> 9, dB = g_shift[nb] >> 9;
    float* oA = out + (size_t)na*NSAMP;
    float* oB = out + (size_t)nb*NSAMP;
    for(int idx = tid; idx < 2048; idx += 512){
        int rp = idx >> 3, c = idx & 7;
        int col = col0 + c;
        int ra = rp - dA;
        oA[rp*512 + col] = (ra >= 0) ? s[c*LSTR + skew(ra)].x * aA : 0.f;
        int rb = rp - dB;
        oB[rp*512 + col] = (rb >= 0) ? s[c*LSTR + skew(rb)].y * aB : 0.f;
    }
}

extern "C" void kernel_launch(void* const* d_in, const int* in_sizes, int n_in,
                              void* d_out, int out_size) {
    const float* voice = (const float*)d_in[0];
    const float* cpc   = (const float*)d_in[1];
    const float* amp   = (const float*)d_in[2];
    const float* room  = (const float*)d_in[3];
    const float* mix   = (const float*)d_in[4];
    const float* times = (const float*)d_in[5];
    const float* cp_table = (const float*)d_in[6];
    const float* verbs = (const float*)d_in[7];
    const float* w_in  = (const float*)d_in[8];
    const float* w_ih  = (const float*)d_in[9];
    const float* w_hh  = (const float*)d_in[10];
    const float* w_out = (const float*)d_in[11];
    float* out = (float*)d_out;

    static cudaStream_t s_side = 0;
    static cudaEvent_t ev_fork = 0, ev_coll = 0, ev_w0 = 0, ev_c0 = 0, ev_p0 = 0, ev_d0 = 0;
    static int s_init = 0;
    if(!s_init){
        if(cudaStreamCreateWithFlags(&s_side, cudaStreamNonBlocking) != cudaSuccess) s_side = 0;
        if(s_side){
            bool ok = cudaEventCreateWithFlags(&ev_fork, cudaEventDisableTiming) == cudaSuccess &&
                      cudaEventCreateWithFlags(&ev_coll, cudaEventDisableTiming) == cudaSuccess &&
                      cudaEventCreateWithFlags(&ev_w0,   cudaEventDisableTiming) == cudaSuccess &&
                      cudaEventCreateWithFlags(&ev_c0,   cudaEventDisableTiming) == cudaSuccess &&
                      cudaEventCreateWithFlags(&ev_p0,   cudaEventDisableTiming) == cudaSuccess &&
                      cudaEventCreateWithFlags(&ev_d0,   cudaEventDisableTiming) == cudaSuccess;
            if(!ok) s_side = 0;
        }
        s_init = 1;
    }

    k_twtab<<<2, 512>>>();
    if(s_side){
        cudaEventRecord(ev_fork, 0);
        cudaStreamWaitEvent(s_side, ev_fork, 0);
        k_collapse<<<NVO*HID, 128, 0, s_side>>>(w_ih, w_in);
        cudaEventRecord(ev_coll, s_side);
        k_col_fwd<1><<<dim3(64, NVB), 512, 0, s_side>>>(verbs, 0);
        k_row_verb<<<dim3(64, NVB), 512, 0, s_side>>>();
        k_prep<<<NEV, 256>>>(voice, cpc, amp, room, mix, times, cp_table);
        cudaStreamWaitEvent(0, ev_coll, 0);
        k_rnn<<<NEV, 256>>>(w_hh);
        k_wout<<<dim3(8, 64), 256>>>(w_out, 0);
        cudaEventRecord(ev_w0, 0);
        k_wout<<<dim3(8, 64), 256>>>(w_out, 64);
        cudaStreamWaitEvent(s_side, ev_w0, 0);
        k_col_fwd<0><<<dim3(64, 32), 512, 0, s_side>>>(nullptr, 0);
        cudaEventRecord(ev_c0, s_side);
        k_col_fwd<0><<<dim3(64, 32), 512>>>(nullptr, 32);
        cudaStreamWaitEvent(0, ev_c0, 0);
        k_rowpair<<<dim3(129, 32), 256>>>(0);
        cudaEventRecord(ev_p0, 0);
        k_rowpair<<<dim3(129, 32), 256>>>(32);
        cudaStreamWaitEvent(s_side, ev_p0, 0);
        k_col_inv<<<dim3(64, 32), 512, 0, s_side>>>(out, 0);
        cudaEventRecord(ev_d0, s_side);
        k_col_inv<<<dim3(64, 32), 512>>>(out, 32);
        cudaStreamWaitEvent(0, ev_d0, 0);
    } else {
        k_prep<<<NEV, 256>>>(voice, cpc, amp, room, mix, times, cp_table);
        k_collapse<<<NVO*HID, 128>>>(w_ih, w_in);
        k_rnn<<<NEV, 256>>>(w_hh);
        k_wout<<<dim3(8, NEV), 256>>>(w_out, 0);
        k_col_fwd<1><<<dim3(64, NVB), 512>>>(verbs, 0);
        k_row_verb<<<dim3(64, NVB), 512>>>();
        k_col_fwd<0><<<dim3(64, NPAIR), 512>>>(nullptr, 0);
        k_rowpair<<<dim3(129, NPAIR), 256>>>(0);
        k_col_inv<<<dim3(64, NPAIR), 512>>>(out, 0);
    }
}